// round 2
// baseline (speedup 1.0000x reference)
#include <cuda_runtime.h>
#include <math.h>

#define BATCH 4
#define SEQ   1024
#define DMODEL 1024
#define NHEAD 16
#define NLAYER 4
#define VOCAB 32000
#define DHEAD 64
#define NTOK (BATCH*SEQ)   // 4096

// ---------------- scratch (device globals; no allocations allowed) ----------
__device__ float g_x [NTOK*DMODEL];
__device__ float g_hn[NTOK*DMODEL];
__device__ float g_q [NTOK*DMODEL];
__device__ float g_k [NTOK*DMODEL];
__device__ float g_v [NTOK*DMODEL];
__device__ float g_y [NTOK*DMODEL];
__device__ float g_mlp[NTOK*4*DMODEL];

// ---------------- state encoder + positional embedding ----------------------
__global__ __launch_bounds__(256)
void embed_kernel(const float* __restrict__ states,
                  const int*   __restrict__ timesteps,
                  const float* __restrict__ w1, const float* __restrict__ b1,
                  const float* __restrict__ w2, const float* __restrict__ b2,
                  const float* __restrict__ w3, const float* __restrict__ b3,
                  const float* __restrict__ pos_emb,
                  const float* __restrict__ gpe,
                  float* __restrict__ x)
{
    int token = blockIdx.x;            // 0..4095
    int b = token / SEQ, s = token % SEQ;
    __shared__ float st[4], h1[16], h2[16];
    int tid = threadIdx.x;
    if (tid < 4) st[tid] = states[token*4 + tid];
    __syncthreads();
    if (tid < 16) {
        float a = b1[tid];
        #pragma unroll
        for (int i = 0; i < 4; i++) a += st[i] * w1[i*16 + tid];
        h1[tid] = fmaxf(a, 0.0f);
    }
    __syncthreads();
    if (tid < 16) {
        float a = b2[tid];
        #pragma unroll
        for (int i = 0; i < 16; i++) a += h1[i] * w2[i*16 + tid];
        h2[tid] = fmaxf(a, 0.0f);
    }
    __syncthreads();
    int t = timesteps[b];              // [B,1]
    for (int d = tid; d < DMODEL; d += blockDim.x) {
        float a = b3[d];
        #pragma unroll
        for (int i = 0; i < 16; i++) a += h2[i] * w3[i*DMODEL + d];
        float tok = tanhf(a);
        x[(size_t)token*DMODEL + d] = tok + gpe[(size_t)t*DMODEL + d]
                                          + pos_emb[(size_t)s*DMODEL + d];
    }
}

// ---------------- layernorm (row-wise, 1024 cols) ----------------------------
__global__ __launch_bounds__(256)
void ln_kernel(const float* __restrict__ X,
               const float* __restrict__ g, const float* __restrict__ b,
               float* __restrict__ out)
{
    int row = blockIdx.x;
    const float* xr = X + (size_t)row*DMODEL;
    int tid = threadIdx.x;
    float v[4]; float s = 0.f, sq = 0.f;
    #pragma unroll
    for (int i = 0; i < 4; i++) {
        v[i] = xr[tid + i*256];
        s += v[i]; sq += v[i]*v[i];
    }
    __shared__ float rs[8], rq[8];
    #pragma unroll
    for (int off = 16; off; off >>= 1) {
        s  += __shfl_xor_sync(0xffffffffu, s,  off);
        sq += __shfl_xor_sync(0xffffffffu, sq, off);
    }
    if ((tid & 31) == 0) { rs[tid>>5] = s; rq[tid>>5] = sq; }
    __syncthreads();
    if (tid < 32) {
        s  = (tid < 8) ? rs[tid] : 0.f;
        sq = (tid < 8) ? rq[tid] : 0.f;
        #pragma unroll
        for (int off = 4; off; off >>= 1) {
            s  += __shfl_xor_sync(0xffffffffu, s,  off);
            sq += __shfl_xor_sync(0xffffffffu, sq, off);
        }
        if (tid == 0) { rs[0] = s; rq[0] = sq; }
    }
    __syncthreads();
    float mu  = rs[0] * (1.0f/DMODEL);
    float var = rq[0] * (1.0f/DMODEL) - mu*mu;
    float r   = rsqrtf(var + 1e-5f);
    float* orow = out + (size_t)row*DMODEL;
    #pragma unroll
    for (int i = 0; i < 4; i++) {
        int c = tid + i*256;
        orow[c] = (v[i] - mu) * r * g[c] + b[c];
    }
}

// ---------------- generic SGEMM: C = A[MxK] * B[KxN] (+ epilogue) ------------
// mode: 0 = none, 1 = +bias, 2 = +bias +resid, 3 = +bias then exact GELU
__global__ __launch_bounds__(256)
void gemm_kernel(const float* __restrict__ A, const float* __restrict__ B,
                 const float* __restrict__ bias, const float* __restrict__ resid,
                 float* __restrict__ C, int M, int N, int K, int mode)
{
    __shared__ float As[8][128];
    __shared__ float Bs[8][128];
    int tid = threadIdx.x;
    int bm = blockIdx.y * 128;
    int bn = blockIdx.x * 128;
    int tx = tid & 15, ty = tid >> 4;
    int aRow = tid >> 1, aCol = (tid & 1) * 4;
    int bRow = tid >> 5, bCol = (tid & 31) * 4;
    const float* Ag = A + (size_t)(bm + aRow) * K + aCol;
    const float* Bg = B + (size_t)bRow * N + bn + bCol;

    float acc[8][8];
    #pragma unroll
    for (int i = 0; i < 8; i++)
        #pragma unroll
        for (int j = 0; j < 8; j++) acc[i][j] = 0.f;

    for (int k0 = 0; k0 < K; k0 += 8) {
        float4 a4 = *(const float4*)(Ag + k0);
        As[aCol+0][aRow] = a4.x; As[aCol+1][aRow] = a4.y;
        As[aCol+2][aRow] = a4.z; As[aCol+3][aRow] = a4.w;
        float4 b4 = *(const float4*)(Bg + (size_t)k0 * N);
        *(float4*)&Bs[bRow][bCol] = b4;
        __syncthreads();
        #pragma unroll
        for (int kk = 0; kk < 8; kk++) {
            float4 a0 = *(const float4*)&As[kk][ty*4];
            float4 a1 = *(const float4*)&As[kk][64 + ty*4];
            float4 b0 = *(const float4*)&Bs[kk][tx*4];
            float4 b1 = *(const float4*)&Bs[kk][64 + tx*4];
            float a[8] = {a0.x,a0.y,a0.z,a0.w,a1.x,a1.y,a1.z,a1.w};
            float bb[8] = {b0.x,b0.y,b0.z,b0.w,b1.x,b1.y,b1.z,b1.w};
            #pragma unroll
            for (int i = 0; i < 8; i++)
                #pragma unroll
                for (int j = 0; j < 8; j++)
                    acc[i][j] += a[i] * bb[j];
        }
        __syncthreads();
    }

    #pragma unroll
    for (int i = 0; i < 8; i++) {
        int row = bm + ((i < 4) ? (ty*4 + i) : (64 + ty*4 + i - 4));
        #pragma unroll
        for (int jc = 0; jc < 2; jc++) {
            int col = bn + jc*64 + tx*4;
            float4 v; float* vp = &v.x;
            #pragma unroll
            for (int j = 0; j < 4; j++) {
                float val = acc[i][jc*4 + j];
                int c = col + j;
                if (mode >= 1) val += bias[c];
                if (mode == 2) val += resid[(size_t)row*N + c];
                if (mode == 3) val = 0.5f * val * (1.0f + erff(val * 0.70710678118654752f));
                vp[j] = val;
            }
            *(float4*)(C + (size_t)row*N + col) = v;
        }
    }
}

// ---------------- causal flash attention (fp32), 64 q-rows per block --------
// grid: (S/64, H, B), 256 threads (8 warps x 8 rows)
__global__ __launch_bounds__(256)
void attn_kernel(const float* __restrict__ Q, const float* __restrict__ K,
                 const float* __restrict__ V, float* __restrict__ Y)
{
    __shared__ float qs[64][64];   // q[r][d]
    __shared__ float ks[64][64];   // kT[d][j], reused as p[r][j]
    __shared__ float vs[64][64];   // v[j][d]
    int qt = blockIdx.x, h = blockIdx.y, b = blockIdx.z;
    int tid = threadIdx.x, warp = tid >> 5, lane = tid & 31;
    size_t base = ((size_t)b * SEQ) * DMODEL + h * DHEAD;

    { // load q tile
        int r = tid >> 2, c0 = (tid & 3) * 16;
        const float* src = Q + base + (size_t)(qt*64 + r) * DMODEL + c0;
        float4* dst = (float4*)&qs[r][c0];
        #pragma unroll
        for (int i = 0; i < 4; i++) dst[i] = ((const float4*)src)[i];
    }

    float m[8], l[8], o0[8], o1[8];
    #pragma unroll
    for (int rr = 0; rr < 8; rr++) { m[rr] = -1e30f; l[rr] = 0.f; o0[rr] = 0.f; o1[rr] = 0.f; }
    __syncthreads();

    for (int kt = 0; kt <= qt; kt++) {
        { // load kT and v tiles
            int j = tid >> 2, c0 = (tid & 3) * 16;
            const float* ksrc = K + base + (size_t)(kt*64 + j) * DMODEL + c0;
            const float* vsrc = V + base + (size_t)(kt*64 + j) * DMODEL + c0;
            #pragma unroll
            for (int i = 0; i < 4; i++) {
                float4 kv = ((const float4*)ksrc)[i];
                ks[c0 + i*4 + 0][j] = kv.x; ks[c0 + i*4 + 1][j] = kv.y;
                ks[c0 + i*4 + 2][j] = kv.z; ks[c0 + i*4 + 3][j] = kv.w;
                ((float4*)&vs[j][c0])[i] = ((const float4*)vsrc)[i];
            }
        }
        __syncthreads();

        bool diag = (kt == qt);
        float p0[8], p1[8];
        #pragma unroll
        for (int rr = 0; rr < 8; rr++) {
            int r = warp*8 + rr;
            float s0 = 0.f, s1 = 0.f;
            #pragma unroll 16
            for (int d = 0; d < 64; d++) {
                float qv = qs[r][d];
                s0 += qv * ks[d][lane];
                s1 += qv * ks[d][lane + 32];
            }
            s0 *= 0.125f; s1 *= 0.125f;
            if (diag) {
                if (lane > r)      s0 = -1e30f;
                if (lane + 32 > r) s1 = -1e30f;
            }
            float smax = fmaxf(s0, s1);
            #pragma unroll
            for (int off = 16; off; off >>= 1)
                smax = fmaxf(smax, __shfl_xor_sync(0xffffffffu, smax, off));
            float mnew  = fmaxf(m[rr], smax);
            float alpha = __expf(m[rr] - mnew);
            float e0 = __expf(s0 - mnew), e1 = __expf(s1 - mnew);
            float psum = e0 + e1;
            #pragma unroll
            for (int off = 16; off; off >>= 1)
                psum += __shfl_xor_sync(0xffffffffu, psum, off);
            l[rr] = l[rr]*alpha + psum;
            m[rr] = mnew;
            o0[rr] *= alpha; o1[rr] *= alpha;
            p0[rr] = e0; p1[rr] = e1;
        }
        __syncthreads();   // all warps done reading ks -> safe to overwrite with p

        #pragma unroll
        for (int rr = 0; rr < 8; rr++) {
            int r = warp*8 + rr;
            ks[r][lane] = p0[rr]; ks[r][lane + 32] = p1[rr];
        }
        __syncwarp();      // each warp only reads rows it wrote (r = warp*8+rr)

        #pragma unroll
        for (int rr = 0; rr < 8; rr++) {
            int r = warp*8 + rr;
            float a0 = 0.f, a1 = 0.f;
            #pragma unroll 16
            for (int j = 0; j < 64; j++) {
                float p = ks[r][j];
                a0 += p * vs[j][lane];
                a1 += p * vs[j][lane + 32];
            }
            o0[rr] += a0; o1[rr] += a1;
        }
        __syncthreads();   // before next tile overwrites ks/vs
    }

    #pragma unroll
    for (int rr = 0; rr < 8; rr++) {
        int r = warp*8 + rr;
        float inv = 1.0f / l[rr];
        size_t off = base + (size_t)(qt*64 + r) * DMODEL;
        Y[off + lane]      = o0[rr] * inv;
        Y[off + lane + 32] = o1[rr] * inv;
    }
}

// ---------------- launch --------------------------------------------------
extern "C" void kernel_launch(void* const* d_in, const int* in_sizes, int n_in,
                              void* d_out, int out_size)
{
    const float* states     = (const float*)d_in[0];
    const int*   timesteps  = (const int*)  d_in[1];
    const float* se_w1      = (const float*)d_in[2];
    const float* se_b1      = (const float*)d_in[3];
    const float* se_w2      = (const float*)d_in[4];
    const float* se_b2      = (const float*)d_in[5];
    const float* se_w3      = (const float*)d_in[6];
    const float* se_b3      = (const float*)d_in[7];
    const float* pos_emb    = (const float*)d_in[8];
    const float* gpe        = (const float*)d_in[9];
    const float* ln1_g      = (const float*)d_in[10];
    const float* ln1_b      = (const float*)d_in[11];
    const float* Wq         = (const float*)d_in[12];
    const float* Wk         = (const float*)d_in[13];
    const float* Wv         = (const float*)d_in[14];
    const float* Wp         = (const float*)d_in[15];
    const float* bp         = (const float*)d_in[16];
    const float* ln2_g      = (const float*)d_in[17];
    const float* ln2_b      = (const float*)d_in[18];
    const float* W1         = (const float*)d_in[19];
    const float* b1         = (const float*)d_in[20];
    const float* W2         = (const float*)d_in[21];
    const float* b2         = (const float*)d_in[22];
    const float* lnf_g      = (const float*)d_in[23];
    const float* lnf_b      = (const float*)d_in[24];
    const float* head_w     = (const float*)d_in[25];

    float *x, *hn, *q, *k, *v, *y, *mlp;
    cudaGetSymbolAddress((void**)&x,   g_x);
    cudaGetSymbolAddress((void**)&hn,  g_hn);
    cudaGetSymbolAddress((void**)&q,   g_q);
    cudaGetSymbolAddress((void**)&k,   g_k);
    cudaGetSymbolAddress((void**)&v,   g_v);
    cudaGetSymbolAddress((void**)&y,   g_y);
    cudaGetSymbolAddress((void**)&mlp, g_mlp);

    embed_kernel<<<NTOK, 256>>>(states, timesteps, se_w1, se_b1, se_w2, se_b2,
                                se_w3, se_b3, pos_emb, gpe, x);

    dim3 gDD(DMODEL/128, NTOK/128);           // 4096 x 1024 GEMM grid
    dim3 gD4(4*DMODEL/128, NTOK/128);         // 4096 x 4096 GEMM grid
    dim3 gHead(VOCAB/128, NTOK/128);          // 4096 x 32000 GEMM grid
    dim3 gAttn(SEQ/64, NHEAD, BATCH);

    for (int l = 0; l < NLAYER; l++) {
        size_t wOff  = (size_t)l * DMODEL * DMODEL;
        size_t w1Off = (size_t)l * DMODEL * 4 * DMODEL;
        ln_kernel<<<NTOK, 256>>>(x, ln1_g + l*DMODEL, ln1_b + l*DMODEL, hn);
        gemm_kernel<<<gDD, 256>>>(hn, Wq + wOff, nullptr, nullptr, q, NTOK, DMODEL, DMODEL, 0);
        gemm_kernel<<<gDD, 256>>>(hn, Wk + wOff, nullptr, nullptr, k, NTOK, DMODEL, DMODEL, 0);
        gemm_kernel<<<gDD, 256>>>(hn, Wv + wOff, nullptr, nullptr, v, NTOK, DMODEL, DMODEL, 0);
        attn_kernel<<<gAttn, 256>>>(q, k, v, y);
        gemm_kernel<<<gDD, 256>>>(y, Wp + wOff, bp + l*DMODEL, x, x, NTOK, DMODEL, DMODEL, 2);
        ln_kernel<<<NTOK, 256>>>(x, ln2_g + l*DMODEL, ln2_b + l*DMODEL, hn);
        gemm_kernel<<<gD4, 256>>>(hn, W1 + w1Off, b1 + (size_t)l*4*DMODEL, nullptr,
                                  mlp, NTOK, 4*DMODEL, DMODEL, 3);
        gemm_kernel<<<gDD, 256>>>(mlp, W2 + w1Off, b2 + l*DMODEL, x, x,
                                  NTOK, DMODEL, 4*DMODEL, 2);
    }

    ln_kernel<<<NTOK, 256>>>(x, lnf_g, lnf_b, hn);
    gemm_kernel<<<gHead, 256>>>(hn, head_w, nullptr, nullptr, (float*)d_out,
                                NTOK, VOCAB, DMODEL, 0);
}

// round 8
// speedup vs baseline: 1.3252x; 1.3252x over previous
#include <cuda_runtime.h>
#include <cuda_bf16.h>
#include <math.h>
#include <stdint.h>

#define BATCH 4
#define SEQ   1024
#define DMODEL 1024
#define NHEAD 16
#define NLAYER 4
#define VOCAB 32000
#define DHEAD 64
#define NTOK (BATCH*SEQ)   // 4096

// SW128 swizzle (Swizzle<3,4,3>)
#define SWZ(b) ((b) ^ ((((unsigned)(b)) >> 3) & 0x70u))

// ---------------------------------------------------------------------------
// PTX helpers (portable: sm_80+ PTX, runs on sm_103a as HMMA)
// ---------------------------------------------------------------------------
__device__ __forceinline__ uint32_t smem_u32(const void* p) {
    uint32_t a;
    asm("{ .reg .u64 t; cvta.to.shared.u64 t, %1; cvt.u32.u64 %0, t; }" : "=r"(a) : "l"(p));
    return a;
}
__device__ __forceinline__ void cp16(uint32_t dst, const void* src) {
    asm volatile("cp.async.cg.shared.global [%0], [%1], 16;" :: "r"(dst), "l"(src));
}
#define CP_COMMIT() asm volatile("cp.async.commit_group;" ::: "memory")
#define CP_WAIT(n)  asm volatile("cp.async.wait_group %0;" :: "n"(n) : "memory")

#define LDSM4(r, addr) \
    asm volatile("ldmatrix.sync.aligned.m8n8.x4.shared.b16 {%0,%1,%2,%3}, [%4];" \
        : "=r"((r)[0]), "=r"((r)[1]), "=r"((r)[2]), "=r"((r)[3]) : "r"(addr))

#define MMA16816(d, a, b0, b1) \
    asm volatile("mma.sync.aligned.m16n8k16.row.col.f32.bf16.bf16.f32 " \
        "{%0,%1,%2,%3}, {%4,%5,%6,%7}, {%8,%9}, {%0,%1,%2,%3};" \
        : "+f"((d)[0]), "+f"((d)[1]), "+f"((d)[2]), "+f"((d)[3]) \
        : "r"((a)[0]), "r"((a)[1]), "r"((a)[2]), "r"((a)[3]), "r"(b0), "r"(b1))

// ---------------------------------------------------------------------------
// scratch (device globals)
// ---------------------------------------------------------------------------
__device__ float g_x [NTOK*DMODEL];
__device__ float g_q [NTOK*DMODEL];
__device__ float g_k [NTOK*DMODEL];
__device__ float g_v [NTOK*DMODEL];
__device__ __nv_bfloat16 g_hn_hi[NTOK*DMODEL];
__device__ __nv_bfloat16 g_hn_lo[NTOK*DMODEL];
__device__ __nv_bfloat16 g_y_hi [NTOK*DMODEL];
__device__ __nv_bfloat16 g_y_lo [NTOK*DMODEL];
__device__ __nv_bfloat16 g_mlp_hi[NTOK*4*DMODEL];
__device__ __nv_bfloat16 g_mlp_lo[NTOK*4*DMODEL];
// weights, transposed [N,K] + swizzled tile format, hi/lo split
#define WTOTAL 83099648ull   // 4*(4*1M + 2*4M) + 1024*32000
__device__ __nv_bfloat16 g_w_hi[WTOTAL];
__device__ __nv_bfloat16 g_w_lo[WTOTAL];

// ---------------------------------------------------------------------------
// weight convert: W[K,N] fp32 -> hi/lo bf16, [N,K] K-major swizzled tiles
// grid: (K/64, N/128), 256 thr. out block = (nt*(K/64)+kc)*8192 elems
// ---------------------------------------------------------------------------
__global__ __launch_bounds__(256)
void convert_w(const float* __restrict__ W,
               __nv_bfloat16* __restrict__ ohi, __nv_bfloat16* __restrict__ olo,
               int K, int N)
{
    int kc = blockIdx.x, nt = blockIdx.y;
    int t = threadIdx.x;
    int n_loc = t & 127, grp = t >> 7;
    size_t blk = ((size_t)nt * gridDim.x + kc) * 8192;
    uint4* hi4 = (uint4*)(ohi + blk);
    uint4* lo4 = (uint4*)(olo + blk);
    #pragma unroll
    for (int g = 0; g < 4; g++) {
        int kg = grp + g*2;                 // 0..7 : 8-elem k group
        int k0 = kc*64 + kg*8;
        unsigned hs[8], ls[8];
        #pragma unroll
        for (int i = 0; i < 8; i++) {
            float v = W[(size_t)(k0 + i) * N + nt*128 + n_loc];
            __nv_bfloat16 h = __float2bfloat16(v);
            __nv_bfloat16 l = __float2bfloat16(v - __bfloat162float(h));
            hs[i] = __bfloat16_as_ushort(h);
            ls[i] = __bfloat16_as_ushort(l);
        }
        uint4 uh, ul;
        uh.x = hs[0] | (hs[1] << 16); uh.y = hs[2] | (hs[3] << 16);
        uh.z = hs[4] | (hs[5] << 16); uh.w = hs[6] | (hs[7] << 16);
        ul.x = ls[0] | (ls[1] << 16); ul.y = ls[2] | (ls[3] << 16);
        ul.z = ls[4] | (ls[5] << 16); ul.w = ls[6] | (ls[7] << 16);
        uint32_t bo = SWZ((uint32_t)n_loc*128 + (uint32_t)kg*16);
        hi4[bo >> 4] = uh;
        lo4[bo >> 4] = ul;
    }
}

// ---------------------------------------------------------------------------
// embed (fp32 residual stream)
// ---------------------------------------------------------------------------
__global__ __launch_bounds__(256)
void embed_kernel(const float* __restrict__ states, const int* __restrict__ timesteps,
                  const float* __restrict__ w1, const float* __restrict__ b1,
                  const float* __restrict__ w2, const float* __restrict__ b2,
                  const float* __restrict__ w3, const float* __restrict__ b3,
                  const float* __restrict__ pos_emb, const float* __restrict__ gpe,
                  float* __restrict__ x)
{
    int token = blockIdx.x;
    int b = token / SEQ, s = token % SEQ;
    __shared__ float st[4], h1[16], h2[16];
    int tid = threadIdx.x;
    if (tid < 4) st[tid] = states[token*4 + tid];
    __syncthreads();
    if (tid < 16) {
        float a = b1[tid];
        #pragma unroll
        for (int i = 0; i < 4; i++) a += st[i] * w1[i*16 + tid];
        h1[tid] = fmaxf(a, 0.0f);
    }
    __syncthreads();
    if (tid < 16) {
        float a = b2[tid];
        #pragma unroll
        for (int i = 0; i < 16; i++) a += h1[i] * w2[i*16 + tid];
        h2[tid] = fmaxf(a, 0.0f);
    }
    __syncthreads();
    int t = timesteps[b];
    for (int d = tid; d < DMODEL; d += blockDim.x) {
        float a = b3[d];
        #pragma unroll
        for (int i = 0; i < 16; i++) a += h2[i] * w3[i*DMODEL + d];
        x[(size_t)token*DMODEL + d] = tanhf(a) + gpe[(size_t)t*DMODEL + d]
                                      + pos_emb[(size_t)s*DMODEL + d];
    }
}

// ---------------------------------------------------------------------------
// layernorm: fp32 in -> bf16 hi/lo swizzled A-tiles (K=1024)
// ---------------------------------------------------------------------------
__global__ __launch_bounds__(256)
void ln_hilo_kernel(const float* __restrict__ X,
                    const float* __restrict__ g, const float* __restrict__ b,
                    __nv_bfloat16* __restrict__ ohi, __nv_bfloat16* __restrict__ olo)
{
    int row = blockIdx.x;
    const float* xr = X + (size_t)row*DMODEL;
    int tid = threadIdx.x;
    float4 v = *(const float4*)(xr + tid*4);
    float s = v.x+v.y+v.z+v.w;
    float sq = v.x*v.x + v.y*v.y + v.z*v.z + v.w*v.w;
    __shared__ float rs[8], rq[8];
    #pragma unroll
    for (int off = 16; off; off >>= 1) {
        s  += __shfl_xor_sync(0xffffffffu, s,  off);
        sq += __shfl_xor_sync(0xffffffffu, sq, off);
    }
    if ((tid & 31) == 0) { rs[tid>>5] = s; rq[tid>>5] = sq; }
    __syncthreads();
    if (tid < 32) {
        s  = (tid < 8) ? rs[tid] : 0.f;
        sq = (tid < 8) ? rq[tid] : 0.f;
        #pragma unroll
        for (int off = 4; off; off >>= 1) {
            s  += __shfl_xor_sync(0xffffffffu, s,  off);
            sq += __shfl_xor_sync(0xffffffffu, sq, off);
        }
        if (tid == 0) { rs[0] = s; rq[0] = sq; }
    }
    __syncthreads();
    float mu  = rs[0] * (1.0f/DMODEL);
    float var = rq[0] * (1.0f/DMODEL) - mu*mu;
    float r   = rsqrtf(var + 1e-5f);
    int k0 = tid*4;
    float o[4] = {v.x, v.y, v.z, v.w};
    unsigned hs[4], ls[4];
    #pragma unroll
    for (int i = 0; i < 4; i++) {
        int c = k0 + i;
        float val = (o[i] - mu) * r * g[c] + b[c];
        __nv_bfloat16 h = __float2bfloat16(val);
        __nv_bfloat16 l = __float2bfloat16(val - __bfloat162float(h));
        hs[i] = __bfloat16_as_ushort(h);
        ls[i] = __bfloat16_as_ushort(l);
    }
    int kc = k0 >> 6, c = k0 & 63;
    size_t tb = ((size_t)(row >> 7) * 16 + kc) * 8192;   // elems
    uint32_t bo = SWZ((uint32_t)(row & 127)*128 + (uint32_t)c*2);
    uint2 uh = { hs[0] | (hs[1] << 16), hs[2] | (hs[3] << 16) };
    uint2 ul = { ls[0] | (ls[1] << 16), ls[2] | (ls[3] << 16) };
    *(uint2*)((char*)(ohi + tb) + bo) = uh;
    *(uint2*)((char*)(olo + tb) + bo) = ul;
}

// ---------------------------------------------------------------------------
// mma.sync GEMM: C[M,N] = A[M,K] x W[K,N]  (A,B bf16 hi/lo swizzled tiles)
// 3-term compensated split. grid (N/128, M/128), 256 thr (8 warps, 4x2).
// mode 0: C fp32      2: C fp32 = +bias +resid      3: gelu(+bias) -> Ohi/Olo
// ---------------------------------------------------------------------------
#define GEMM_SMEM 131072

__global__ __launch_bounds__(256, 1)
void gemm_mma(const uint4* __restrict__ Ahi, const uint4* __restrict__ Alo,
              const uint4* __restrict__ Bhi, const uint4* __restrict__ Blo,
              const float* __restrict__ bias, const float* __restrict__ resid,
              float* __restrict__ Cf,
              __nv_bfloat16* __restrict__ Ohi, __nv_bfloat16* __restrict__ Olo,
              int N, int K, int mode)
{
    extern __shared__ char sb[];
    uint32_t sbase = smem_u32(sb);
    int tid = threadIdx.x, wid = tid >> 5, lane = tid & 31;
    int nt = blockIdx.x, mt = blockIdx.y;
    int NC = K >> 6;
    int wm = wid & 3, wn = wid >> 2;

    const uint4* gA0h = Ahi + (size_t)mt * NC * 1024;
    const uint4* gA0l = Alo + (size_t)mt * NC * 1024;
    const uint4* gB0h = Bhi + (size_t)nt * NC * 1024;
    const uint4* gB0l = Blo + (size_t)nt * NC * 1024;

    float acc[2][8][4];
    #pragma unroll
    for (int i = 0; i < 2; i++)
        #pragma unroll
        for (int j = 0; j < 8; j++)
            #pragma unroll
            for (int q = 0; q < 4; q++) acc[i][j][q] = 0.f;

    // ---- chunk loader: 64KB (4 x 16KB tiles) into stage s via cp.async ----
    auto load_chunk = [&](int c, int s) {
        uint32_t sA = sbase + s*65536;
        const uint4* ah = gA0h + (size_t)c*1024;
        const uint4* al = gA0l + (size_t)c*1024;
        const uint4* bh = gB0h + (size_t)c*1024;
        const uint4* bl = gB0l + (size_t)c*1024;
        #pragma unroll
        for (int i = 0; i < 4; i++) {
            int idx = tid + i*256;
            cp16(sA +         idx*16, ah + idx);
            cp16(sA + 16384 + idx*16, al + idx);
            cp16(sA + 32768 + idx*16, bh + idx);
            cp16(sA + 49152 + idx*16, bl + idx);
        }
    };

    load_chunk(0, 0);
    CP_COMMIT();

    // ldmatrix lane geometry (constant per thread)
    int lrow = lane & 15;          // row within 16-row tile
    int lkc8 = (lane >> 4) * 8;    // k offset of the 8x8 sub-matrix

    for (int c = 0; c < NC; c++) {
        int s = c & 1;
        if (c + 1 < NC) {
            load_chunk(c + 1, s ^ 1);
            CP_COMMIT();
            CP_WAIT(1);
        } else {
            CP_WAIT(0);
        }
        __syncthreads();

        uint32_t sAh = sbase + s*65536;
        uint32_t sAl = sAh + 16384;
        uint32_t sBh = sAh + 32768;
        uint32_t sBl = sAh + 49152;

        #pragma unroll
        for (int ks = 0; ks < 4; ks++) {
            int k0 = ks*16;
            uint32_t ah[2][4], al[2][4];
            #pragma unroll
            for (int tm = 0; tm < 2; tm++) {
                uint32_t off = SWZ((uint32_t)(wm*32 + tm*16 + lrow)*128
                                   + (uint32_t)(k0 + lkc8)*2);
                LDSM4(ah[tm], sAh + off);
                LDSM4(al[tm], sAl + off);
            }
            uint32_t bh[4][4], bl[4][4];
            #pragma unroll
            for (int g = 0; g < 4; g++) {
                uint32_t off = SWZ((uint32_t)(wn*64 + g*16 + lrow)*128
                                   + (uint32_t)(k0 + lkc8)*2);
                LDSM4(bh[g], sBh + off);
                LDSM4(bl[g], sBl + off);
            }
            #pragma unroll
            for (int tm = 0; tm < 2; tm++)
                #pragma unroll
                for (int g = 0; g < 4; g++) {
                    MMA16816(acc[tm][2*g  ], ah[tm], bh[g][0], bh[g][2]);
                    MMA16816(acc[tm][2*g+1], ah[tm], bh[g][1], bh[g][3]);
                    MMA16816(acc[tm][2*g  ], ah[tm], bl[g][0], bl[g][2]);
                    MMA16816(acc[tm][2*g+1], ah[tm], bl[g][1], bl[g][3]);
                    MMA16816(acc[tm][2*g  ], al[tm], bh[g][0], bh[g][2]);
                    MMA16816(acc[tm][2*g+1], al[tm], bh[g][1], bh[g][3]);
                }
        }
        __syncthreads();
    }

    // ---- epilogue ----
    int gr = lane >> 2, gc = lane & 3;
    #pragma unroll
    for (int tm = 0; tm < 2; tm++) {
        #pragma unroll
        for (int tn = 0; tn < 8; tn++) {
            float* a = acc[tm][tn];
            int rIn0 = wm*32 + tm*16 + gr;          // in-tile row (pair at +8)
            int col  = nt*128 + wn*64 + tn*8 + gc*2;
            if (mode == 3) {
                int kc = col >> 6, cc = col & 63;
                size_t tb = ((size_t)mt * (N >> 6) + kc) * 8192;
                #pragma unroll
                for (int hhalf = 0; hhalf < 2; hhalf++) {
                    int rIn = rIn0 + hhalf*8;
                    float v0 = a[hhalf*2]     + bias[col];
                    float v1 = a[hhalf*2 + 1] + bias[col + 1];
                    v0 = 0.5f * v0 * (1.0f + erff(v0 * 0.70710678118654752f));
                    v1 = 0.5f * v1 * (1.0f + erff(v1 * 0.70710678118654752f));
                    __nv_bfloat16 h0 = __float2bfloat16(v0);
                    __nv_bfloat16 l0 = __float2bfloat16(v0 - __bfloat162float(h0));
                    __nv_bfloat16 h1 = __float2bfloat16(v1);
                    __nv_bfloat16 l1 = __float2bfloat16(v1 - __bfloat162float(h1));
                    uint32_t uh = (uint32_t)__bfloat16_as_ushort(h0)
                                | ((uint32_t)__bfloat16_as_ushort(h1) << 16);
                    uint32_t ul = (uint32_t)__bfloat16_as_ushort(l0)
                                | ((uint32_t)__bfloat16_as_ushort(l1) << 16);
                    uint32_t bo = SWZ((uint32_t)rIn*128 + (uint32_t)cc*2);
                    *(uint32_t*)((char*)(Ohi + tb) + bo) = uh;
                    *(uint32_t*)((char*)(Olo + tb) + bo) = ul;
                }
            } else {
                #pragma unroll
                for (int hhalf = 0; hhalf < 2; hhalf++) {
                    int row = mt*128 + rIn0 + hhalf*8;
                    float v0 = a[hhalf*2], v1 = a[hhalf*2 + 1];
                    if (mode == 2) {
                        v0 += bias[col]     + resid[(size_t)row*N + col];
                        v1 += bias[col + 1] + resid[(size_t)row*N + col + 1];
                    }
                    float2 o = {v0, v1};
                    *(float2*)(Cf + (size_t)row*N + col) = o;
                }
            }
        }
    }
}

// ---------------------------------------------------------------------------
// causal flash attention fp32; outputs bf16 hi/lo swizzled A-tiles (K=1024)
// ---------------------------------------------------------------------------
__global__ __launch_bounds__(256)
void attn_kernel(const float* __restrict__ Q, const float* __restrict__ K,
                 const float* __restrict__ V,
                 __nv_bfloat16* __restrict__ yhi, __nv_bfloat16* __restrict__ ylo)
{
    __shared__ float qs[64][64];
    __shared__ float ks[64][64];
    __shared__ float vs[64][64];
    int qt = blockIdx.x, h = blockIdx.y, b = blockIdx.z;
    int tid = threadIdx.x, warp = tid >> 5, lane = tid & 31;
    size_t base = ((size_t)b * SEQ) * DMODEL + h * DHEAD;

    {
        int r = tid >> 2, c0 = (tid & 3) * 16;
        const float* src = Q + base + (size_t)(qt*64 + r) * DMODEL + c0;
        float4* dst = (float4*)&qs[r][c0];
        #pragma unroll
        for (int i = 0; i < 4; i++) dst[i] = ((const float4*)src)[i];
    }
    float m[8], l[8], o0[8], o1[8];
    #pragma unroll
    for (int rr = 0; rr < 8; rr++) { m[rr] = -1e30f; l[rr] = 0.f; o0[rr] = 0.f; o1[rr] = 0.f; }
    __syncthreads();

    for (int kt = 0; kt <= qt; kt++) {
        {
            int j = tid >> 2, c0 = (tid & 3) * 16;
            const float* ksrc = K + base + (size_t)(kt*64 + j) * DMODEL + c0;
            const float* vsrc = V + base + (size_t)(kt*64 + j) * DMODEL + c0;
            #pragma unroll
            for (int i = 0; i < 4; i++) {
                float4 kv = ((const float4*)ksrc)[i];
                ks[c0 + i*4 + 0][j] = kv.x; ks[c0 + i*4 + 1][j] = kv.y;
                ks[c0 + i*4 + 2][j] = kv.z; ks[c0 + i*4 + 3][j] = kv.w;
                ((float4*)&vs[j][c0])[i] = ((const float4*)vsrc)[i];
            }
        }
        __syncthreads();
        bool diag = (kt == qt);
        float p0[8], p1[8];
        #pragma unroll
        for (int rr = 0; rr < 8; rr++) {
            int r = warp*8 + rr;
            float s0 = 0.f, s1 = 0.f;
            #pragma unroll 16
            for (int d = 0; d < 64; d++) {
                float qv = qs[r][d];
                s0 += qv * ks[d][lane];
                s1 += qv * ks[d][lane + 32];
            }
            s0 *= 0.125f; s1 *= 0.125f;
            if (diag) {
                if (lane > r)      s0 = -1e30f;
                if (lane + 32 > r) s1 = -1e30f;
            }
            float smax = fmaxf(s0, s1);
            #pragma unroll
            for (int off = 16; off; off >>= 1)
                smax = fmaxf(smax, __shfl_xor_sync(0xffffffffu, smax, off));
            float mnew  = fmaxf(m[rr], smax);
            float alpha = __expf(m[rr] - mnew);
            float e0 = __expf(s0 - mnew), e1 = __expf(s1 - mnew);
            float psum = e0 + e1;
            #pragma unroll
            for (int off = 16; off; off >>= 1)
                psum += __shfl_xor_sync(0xffffffffu, psum, off);
            l[rr] = l[rr]*alpha + psum;
            m[rr] = mnew;
            o0[rr] *= alpha; o1[rr] *= alpha;
            p0[rr] = e0; p1[rr] = e1;
        }
        __syncthreads();
        #pragma unroll
        for (int rr = 0; rr < 8; rr++) {
            int r = warp*8 + rr;
            ks[r][lane] = p0[rr]; ks[r][lane + 32] = p1[rr];
        }
        __syncwarp();
        #pragma unroll
        for (int rr = 0; rr < 8; rr++) {
            int r = warp*8 + rr;
            float a0 = 0.f, a1 = 0.f;
            #pragma unroll 16
            for (int j = 0; j < 64; j++) {
                float p = ks[r][j];
                a0 += p * vs[j][lane];
                a1 += p * vs[j][lane + 32];
            }
            o0[rr] += a0; o1[rr] += a1;
        }
        __syncthreads();
    }

    #pragma unroll
    for (int rr = 0; rr < 8; rr++) {
        int r = warp*8 + rr;
        float inv = 1.0f / l[rr];
        float v0 = o0[rr] * inv, v1 = o1[rr] * inv;
        int mtok = b*SEQ + qt*64 + r;
        size_t tb = ((size_t)(mtok >> 7) * 16 + h) * 8192;   // kc == h
        uint32_t bo0 = SWZ((uint32_t)(mtok & 127)*128 + (uint32_t)lane*2);
        uint32_t bo1 = SWZ((uint32_t)(mtok & 127)*128 + (uint32_t)(lane + 32)*2);
        __nv_bfloat16 h0 = __float2bfloat16(v0);
        __nv_bfloat16 l0 = __float2bfloat16(v0 - __bfloat162float(h0));
        __nv_bfloat16 h1 = __float2bfloat16(v1);
        __nv_bfloat16 l1 = __float2bfloat16(v1 - __bfloat162float(h1));
        *(__nv_bfloat16*)((char*)(yhi + tb) + bo0) = h0;
        *(__nv_bfloat16*)((char*)(ylo + tb) + bo0) = l0;
        *(__nv_bfloat16*)((char*)(yhi + tb) + bo1) = h1;
        *(__nv_bfloat16*)((char*)(ylo + tb) + bo1) = l1;
    }
}

// ---------------------------------------------------------------------------
// launch
// ---------------------------------------------------------------------------
extern "C" void kernel_launch(void* const* d_in, const int* in_sizes, int n_in,
                              void* d_out, int out_size)
{
    const float* states     = (const float*)d_in[0];
    const int*   timesteps  = (const int*)  d_in[1];
    const float* se_w1 = (const float*)d_in[2];
    const float* se_b1 = (const float*)d_in[3];
    const float* se_w2 = (const float*)d_in[4];
    const float* se_b2 = (const float*)d_in[5];
    const float* se_w3 = (const float*)d_in[6];
    const float* se_b3 = (const float*)d_in[7];
    const float* pos_emb = (const float*)d_in[8];
    const float* gpe     = (const float*)d_in[9];
    const float* ln1_g = (const float*)d_in[10];
    const float* ln1_b = (const float*)d_in[11];
    const float* Wq = (const float*)d_in[12];
    const float* Wk = (const float*)d_in[13];
    const float* Wv = (const float*)d_in[14];
    const float* Wp = (const float*)d_in[15];
    const float* bp = (const float*)d_in[16];
    const float* ln2_g = (const float*)d_in[17];
    const float* ln2_b = (const float*)d_in[18];
    const float* W1 = (const float*)d_in[19];
    const float* b1 = (const float*)d_in[20];
    const float* W2 = (const float*)d_in[21];
    const float* b2 = (const float*)d_in[22];
    const float* lnf_g = (const float*)d_in[23];
    const float* lnf_b = (const float*)d_in[24];
    const float* head_w = (const float*)d_in[25];

    float *x, *q, *k, *v;
    __nv_bfloat16 *hnh, *hnl, *yh, *yl, *mh, *ml, *wh, *wl;
    cudaGetSymbolAddress((void**)&x,  g_x);
    cudaGetSymbolAddress((void**)&q,  g_q);
    cudaGetSymbolAddress((void**)&k,  g_k);
    cudaGetSymbolAddress((void**)&v,  g_v);
    cudaGetSymbolAddress((void**)&hnh, g_hn_hi);
    cudaGetSymbolAddress((void**)&hnl, g_hn_lo);
    cudaGetSymbolAddress((void**)&yh, g_y_hi);
    cudaGetSymbolAddress((void**)&yl, g_y_lo);
    cudaGetSymbolAddress((void**)&mh, g_mlp_hi);
    cudaGetSymbolAddress((void**)&ml, g_mlp_lo);
    cudaGetSymbolAddress((void**)&wh, g_w_hi);
    cudaGetSymbolAddress((void**)&wl, g_w_lo);

    cudaFuncSetAttribute(gemm_mma, cudaFuncAttributeMaxDynamicSharedMemorySize, GEMM_SMEM);

    // weight conversion (per replay)
    const size_t LW = 12582912ull, MDD = 1048576ull, MD4 = 4194304ull;
    for (int l = 0; l < NLAYER; l++) {
        size_t wb = (size_t)l * LW;
        size_t so = (size_t)l * DMODEL * DMODEL;
        size_t so4 = (size_t)l * DMODEL * 4 * DMODEL;
        convert_w<<<dim3(16, 8),  256>>>(Wq + so, wh + wb,          wl + wb,          1024, 1024);
        convert_w<<<dim3(16, 8),  256>>>(Wk + so, wh + wb + MDD,    wl + wb + MDD,    1024, 1024);
        convert_w<<<dim3(16, 8),  256>>>(Wv + so, wh + wb + 2*MDD,  wl + wb + 2*MDD,  1024, 1024);
        convert_w<<<dim3(16, 8),  256>>>(Wp + so, wh + wb + 3*MDD,  wl + wb + 3*MDD,  1024, 1024);
        convert_w<<<dim3(16, 32), 256>>>(W1 + so4, wh + wb + 4*MDD, wl + wb + 4*MDD,  1024, 4096);
        convert_w<<<dim3(64, 8),  256>>>(W2 + so4, wh + wb + 4*MDD + MD4,
                                                   wl + wb + 4*MDD + MD4, 4096, 1024);
    }
    const size_t HOFF = 4*LW;
    convert_w<<<dim3(16, 250), 256>>>(head_w, wh + HOFF, wl + HOFF, 1024, 32000);

    embed_kernel<<<NTOK, 256>>>(states, timesteps, se_w1, se_b1, se_w2, se_b2,
                                se_w3, se_b3, pos_emb, gpe, x);

    dim3 gDD(8, 32), gD4(32, 32), gHead(250, 32), gAttn(SEQ/64, NHEAD, BATCH);

    for (int l = 0; l < NLAYER; l++) {
        size_t wb = (size_t)l * LW;
        ln_hilo_kernel<<<NTOK, 256>>>(x, ln1_g + l*DMODEL, ln1_b + l*DMODEL, hnh, hnl);
        gemm_mma<<<gDD, 256, GEMM_SMEM>>>((uint4*)hnh, (uint4*)hnl,
            (uint4*)(wh + wb), (uint4*)(wl + wb),
            nullptr, nullptr, q, nullptr, nullptr, 1024, 1024, 0);
        gemm_mma<<<gDD, 256, GEMM_SMEM>>>((uint4*)hnh, (uint4*)hnl,
            (uint4*)(wh + wb + MDD), (uint4*)(wl + wb + MDD),
            nullptr, nullptr, k, nullptr, nullptr, 1024, 1024, 0);
        gemm_mma<<<gDD, 256, GEMM_SMEM>>>((uint4*)hnh, (uint4*)hnl,
            (uint4*)(wh + wb + 2*MDD), (uint4*)(wl + wb + 2*MDD),
            nullptr, nullptr, v, nullptr, nullptr, 1024, 1024, 0);
        attn_kernel<<<gAttn, 256>>>(q, k, v, yh, yl);
        gemm_mma<<<gDD, 256, GEMM_SMEM>>>((uint4*)yh, (uint4*)yl,
            (uint4*)(wh + wb + 3*MDD), (uint4*)(wl + wb + 3*MDD),
            bp + l*DMODEL, x, x, nullptr, nullptr, 1024, 1024, 2);
        ln_hilo_kernel<<<NTOK, 256>>>(x, ln2_g + l*DMODEL, ln2_b + l*DMODEL, hnh, hnl);
        gemm_mma<<<gD4, 256, GEMM_SMEM>>>((uint4*)hnh, (uint4*)hnl,
            (uint4*)(wh + wb + 4*MDD), (uint4*)(wl + wb + 4*MDD),
            b1 + (size_t)l*4*DMODEL, nullptr, nullptr, mh, ml, 4096, 1024, 3);
        gemm_mma<<<gDD, 256, GEMM_SMEM>>>((uint4*)mh, (uint4*)ml,
            (uint4*)(wh + wb + 4*MDD + MD4), (uint4*)(wl + wb + 4*MDD + MD4),
            b2 + l*DMODEL, x, x, nullptr, nullptr, 1024, 4096, 2);
    }

    ln_hilo_kernel<<<NTOK, 256>>>(x, lnf_g, lnf_b, hnh, hnl);
    gemm_mma<<<gHead, 256, GEMM_SMEM>>>((uint4*)hnh, (uint4*)hnl,
        (uint4*)(wh + HOFF), (uint4*)(wl + HOFF),
        nullptr, nullptr, (float*)d_out, nullptr, nullptr, 32000, 1024, 0);
}

// round 12
// speedup vs baseline: 2.1639x; 1.6329x over previous
#include <cuda_runtime.h>
#include <cuda_bf16.h>
#include <math.h>
#include <stdint.h>

#define BATCH 4
#define SEQ   1024
#define DMODEL 1024
#define NHEAD 16
#define NLAYER 4
#define VOCAB 32000
#define DHEAD 64
#define NTOK (BATCH*SEQ)   // 4096

// SW128 swizzle (Swizzle<3,4,3>)
#define SWZ(b) ((b) ^ ((((unsigned)(b)) >> 3) & 0x70u))

// ---------------------------------------------------------------------------
// PTX helpers (portable: sm_80+ PTX, runs on sm_103a)
// ---------------------------------------------------------------------------
__device__ __forceinline__ uint32_t smem_u32(const void* p) {
    uint32_t a;
    asm("{ .reg .u64 t; cvta.to.shared.u64 t, %1; cvt.u32.u64 %0, t; }" : "=r"(a) : "l"(p));
    return a;
}
__device__ __forceinline__ void cp16(uint32_t dst, const void* src) {
    asm volatile("cp.async.cg.shared.global [%0], [%1], 16;" :: "r"(dst), "l"(src));
}
#define CP_COMMIT() asm volatile("cp.async.commit_group;" ::: "memory")
#define CP_WAIT(n)  asm volatile("cp.async.wait_group %0;" :: "n"(n) : "memory")

#define LDSM4(r, addr) \
    asm volatile("ldmatrix.sync.aligned.m8n8.x4.shared.b16 {%0,%1,%2,%3}, [%4];" \
        : "=r"((r)[0]), "=r"((r)[1]), "=r"((r)[2]), "=r"((r)[3]) : "r"(addr))

#define MMA16816(d, a, b0, b1) \
    asm volatile("mma.sync.aligned.m16n8k16.row.col.f32.bf16.bf16.f32 " \
        "{%0,%1,%2,%3}, {%4,%5,%6,%7}, {%8,%9}, {%0,%1,%2,%3};" \
        : "+f"((d)[0]), "+f"((d)[1]), "+f"((d)[2]), "+f"((d)[3]) \
        : "r"((a)[0]), "r"((a)[1]), "r"((a)[2]), "r"((a)[3]), "r"(b0), "r"(b1))

// ---------------------------------------------------------------------------
// scratch (device globals)
// ---------------------------------------------------------------------------
__device__ float g_x  [NTOK*DMODEL];
__device__ float g_qkv[NTOK*3*DMODEL];
__device__ __nv_bfloat16 g_hn_hi[NTOK*DMODEL];
__device__ __nv_bfloat16 g_hn_lo[NTOK*DMODEL];
__device__ __nv_bfloat16 g_y_hi [NTOK*DMODEL];
__device__ __nv_bfloat16 g_y_lo [NTOK*DMODEL];
__device__ __nv_bfloat16 g_mlp_hi[NTOK*4*DMODEL];
__device__ __nv_bfloat16 g_mlp_lo[NTOK*4*DMODEL];
// weights, transposed [N,K] + swizzled tile format, hi/lo split
#define WTOTAL 83099648ull   // 4*12*MDD + 1024*32000
#define LWq 12582912ull
#define MDDq 1048576ull
__device__ __nv_bfloat16 g_w_hi[WTOTAL];
__device__ __nv_bfloat16 g_w_lo[WTOTAL];

// ---------------------------------------------------------------------------
// single-launch weight convert: all weights -> hi/lo bf16 [N,K] swizzled tiles
// grid = 10144 blocks; per-layer layout (elems):
//   QKV fused (nt 0..23) @ wb, proj @ wb+3M, W1 @ wb+4M, W2 @ wb+8M; head @ 4*LW
// ---------------------------------------------------------------------------
__global__ __launch_bounds__(256)
void convert_all(const float* __restrict__ Wq, const float* __restrict__ Wk,
                 const float* __restrict__ Wv, const float* __restrict__ Wp,
                 const float* __restrict__ W1, const float* __restrict__ W2,
                 const float* __restrict__ Whead,
                 __nv_bfloat16* __restrict__ wh, __nv_bfloat16* __restrict__ wl)
{
    int bid = blockIdx.x;
    const float* W; int N, kc, nt;
    size_t dstBlk;
    if (bid < 6144) {
        int l = bid / 1536, r = bid % 1536;
        size_t wb = (size_t)l * LWq;
        if (r < 384) {                       // fused QKV
            int nt_f = r >> 4; kc = r & 15;
            int sel = nt_f >> 3; nt = nt_f & 7;
            W = (sel == 0 ? Wq : (sel == 1 ? Wk : Wv)) + (size_t)l*DMODEL*DMODEL;
            N = 1024;
            dstBlk = wb + ((size_t)nt_f*16 + kc)*8192;
        } else if (r < 512) {                // proj
            int i = r - 384; nt = i >> 4; kc = i & 15;
            W = Wp + (size_t)l*DMODEL*DMODEL; N = 1024;
            dstBlk = wb + 3*MDDq + ((size_t)nt*16 + kc)*8192;
        } else if (r < 1024) {               // W1 [1024 -> 4096]
            int i = r - 512; nt = i >> 4; kc = i & 15;
            W = W1 + (size_t)l*DMODEL*4*DMODEL; N = 4096;
            dstBlk = wb + 4*MDDq + ((size_t)nt*16 + kc)*8192;
        } else {                             // W2 [4096 -> 1024]
            int i = r - 1024; nt = i >> 6; kc = i & 63;
            W = W2 + (size_t)l*DMODEL*4*DMODEL; N = 1024;
            dstBlk = wb + 8*MDDq + ((size_t)nt*64 + kc)*8192;
        }
    } else {                                 // head [1024 -> 32000]
        int i = bid - 6144; nt = i >> 4; kc = i & 15;
        W = Whead; N = 32000;
        dstBlk = 4*LWq + ((size_t)nt*16 + kc)*8192;
    }

    int t = threadIdx.x;
    int n_loc = t & 127, grp = t >> 7;
    uint4* hi4 = (uint4*)(wh + dstBlk);
    uint4* lo4 = (uint4*)(wl + dstBlk);
    #pragma unroll
    for (int g = 0; g < 4; g++) {
        int kg = grp + g*2;
        int k0 = kc*64 + kg*8;
        unsigned hs[8], ls[8];
        #pragma unroll
        for (int i = 0; i < 8; i++) {
            float v = W[(size_t)(k0 + i) * N + nt*128 + n_loc];
            __nv_bfloat16 h = __float2bfloat16(v);
            __nv_bfloat16 l = __float2bfloat16(v - __bfloat162float(h));
            hs[i] = __bfloat16_as_ushort(h);
            ls[i] = __bfloat16_as_ushort(l);
        }
        uint4 uh, ul;
        uh.x = hs[0] | (hs[1] << 16); uh.y = hs[2] | (hs[3] << 16);
        uh.z = hs[4] | (hs[5] << 16); uh.w = hs[6] | (hs[7] << 16);
        ul.x = ls[0] | (ls[1] << 16); ul.y = ls[2] | (ls[3] << 16);
        ul.z = ls[4] | (ls[5] << 16); ul.w = ls[6] | (ls[7] << 16);
        uint32_t bo = SWZ((uint32_t)n_loc*128 + (uint32_t)kg*16);
        hi4[bo >> 4] = uh;
        lo4[bo >> 4] = ul;
    }
}

// ---------------------------------------------------------------------------
// embed (fp32 residual stream)
// ---------------------------------------------------------------------------
__global__ __launch_bounds__(256)
void embed_kernel(const float* __restrict__ states, const int* __restrict__ timesteps,
                  const float* __restrict__ w1, const float* __restrict__ b1,
                  const float* __restrict__ w2, const float* __restrict__ b2,
                  const float* __restrict__ w3, const float* __restrict__ b3,
                  const float* __restrict__ pos_emb, const float* __restrict__ gpe,
                  float* __restrict__ x)
{
    int token = blockIdx.x;
    int b = token / SEQ, s = token % SEQ;
    __shared__ float st[4], h1[16], h2[16];
    int tid = threadIdx.x;
    if (tid < 4) st[tid] = states[token*4 + tid];
    __syncthreads();
    if (tid < 16) {
        float a = b1[tid];
        #pragma unroll
        for (int i = 0; i < 4; i++) a += st[i] * w1[i*16 + tid];
        h1[tid] = fmaxf(a, 0.0f);
    }
    __syncthreads();
    if (tid < 16) {
        float a = b2[tid];
        #pragma unroll
        for (int i = 0; i < 16; i++) a += h1[i] * w2[i*16 + tid];
        h2[tid] = fmaxf(a, 0.0f);
    }
    __syncthreads();
    int t = timesteps[b];
    for (int d = tid; d < DMODEL; d += blockDim.x) {
        float a = b3[d];
        #pragma unroll
        for (int i = 0; i < 16; i++) a += h2[i] * w3[i*DMODEL + d];
        x[(size_t)token*DMODEL + d] = tanhf(a) + gpe[(size_t)t*DMODEL + d]
                                      + pos_emb[(size_t)s*DMODEL + d];
    }
}

// ---------------------------------------------------------------------------
// layernorm: fp32 in -> bf16 hi/lo swizzled A-tiles (K=1024)
// ---------------------------------------------------------------------------
__global__ __launch_bounds__(256)
void ln_hilo_kernel(const float* __restrict__ X,
                    const float* __restrict__ g, const float* __restrict__ b,
                    __nv_bfloat16* __restrict__ ohi, __nv_bfloat16* __restrict__ olo)
{
    int row = blockIdx.x;
    const float* xr = X + (size_t)row*DMODEL;
    int tid = threadIdx.x;
    float4 v = *(const float4*)(xr + tid*4);
    float s = v.x+v.y+v.z+v.w;
    float sq = v.x*v.x + v.y*v.y + v.z*v.z + v.w*v.w;
    __shared__ float rs[8], rq[8];
    #pragma unroll
    for (int off = 16; off; off >>= 1) {
        s  += __shfl_xor_sync(0xffffffffu, s,  off);
        sq += __shfl_xor_sync(0xffffffffu, sq, off);
    }
    if ((tid & 31) == 0) { rs[tid>>5] = s; rq[tid>>5] = sq; }
    __syncthreads();
    if (tid < 32) {
        s  = (tid < 8) ? rs[tid] : 0.f;
        sq = (tid < 8) ? rq[tid] : 0.f;
        #pragma unroll
        for (int off = 4; off; off >>= 1) {
            s  += __shfl_xor_sync(0xffffffffu, s,  off);
            sq += __shfl_xor_sync(0xffffffffu, sq, off);
        }
        if (tid == 0) { rs[0] = s; rq[0] = sq; }
    }
    __syncthreads();
    float mu  = rs[0] * (1.0f/DMODEL);
    float var = rq[0] * (1.0f/DMODEL) - mu*mu;
    float r   = rsqrtf(var + 1e-5f);
    int k0 = tid*4;
    float o[4] = {v.x, v.y, v.z, v.w};
    unsigned hs[4], ls[4];
    #pragma unroll
    for (int i = 0; i < 4; i++) {
        int c = k0 + i;
        float val = (o[i] - mu) * r * g[c] + b[c];
        __nv_bfloat16 h = __float2bfloat16(val);
        __nv_bfloat16 l = __float2bfloat16(val - __bfloat162float(h));
        hs[i] = __bfloat16_as_ushort(h);
        ls[i] = __bfloat16_as_ushort(l);
    }
    int kc = k0 >> 6, c = k0 & 63;
    size_t tb = ((size_t)(row >> 7) * 16 + kc) * 8192;
    uint32_t bo = SWZ((uint32_t)(row & 127)*128 + (uint32_t)c*2);
    uint2 uh = { hs[0] | (hs[1] << 16), hs[2] | (hs[3] << 16) };
    uint2 ul = { ls[0] | (ls[1] << 16), ls[2] | (ls[3] << 16) };
    *(uint2*)((char*)(ohi + tb) + bo) = uh;
    *(uint2*)((char*)(olo + tb) + bo) = ul;
}

// ---------------------------------------------------------------------------
// mma.sync GEMM, 3-stage cp.async pipeline, split-term-outer MMA order.
// C[M,N] = A[M,K] x W[K,N]; grid (N/128, M/128), 256 thr (8 warps, 4x2).
// mode 0: C fp32      2: C fp32 = +bias +resid      3: gelu(+bias) -> Ohi/Olo
// ---------------------------------------------------------------------------
#define GEMM_SMEM 196608

__global__ __launch_bounds__(256, 1)
void gemm_mma(const uint4* __restrict__ Ahi, const uint4* __restrict__ Alo,
              const uint4* __restrict__ Bhi, const uint4* __restrict__ Blo,
              const float* __restrict__ bias, const float* __restrict__ resid,
              float* __restrict__ Cf,
              __nv_bfloat16* __restrict__ Ohi, __nv_bfloat16* __restrict__ Olo,
              int N, int K, int mode)
{
    extern __shared__ char sb[];
    uint32_t sbase = smem_u32(sb);
    int tid = threadIdx.x, wid = tid >> 5, lane = tid & 31;
    int nt = blockIdx.x, mt = blockIdx.y;
    int NC = K >> 6;
    int wm = wid & 3, wn = wid >> 2;

    const uint4* gA0h = Ahi + (size_t)mt * NC * 1024;
    const uint4* gA0l = Alo + (size_t)mt * NC * 1024;
    const uint4* gB0h = Bhi + (size_t)nt * NC * 1024;
    const uint4* gB0l = Blo + (size_t)nt * NC * 1024;

    float acc[2][8][4];
    #pragma unroll
    for (int i = 0; i < 2; i++)
        #pragma unroll
        for (int j = 0; j < 8; j++)
            #pragma unroll
            for (int q = 0; q < 4; q++) acc[i][j][q] = 0.f;

    auto load_chunk = [&](int c, int s) {
        uint32_t sA = sbase + s*65536;
        const uint4* ah = gA0h + (size_t)c*1024;
        const uint4* al = gA0l + (size_t)c*1024;
        const uint4* bh = gB0h + (size_t)c*1024;
        const uint4* bl = gB0l + (size_t)c*1024;
        #pragma unroll
        for (int i = 0; i < 4; i++) {
            int idx = tid + i*256;
            cp16(sA +         idx*16, ah + idx);
            cp16(sA + 16384 + idx*16, al + idx);
            cp16(sA + 32768 + idx*16, bh + idx);
            cp16(sA + 49152 + idx*16, bl + idx);
        }
    };

    load_chunk(0, 0);
    CP_COMMIT();
    if (NC > 1) { load_chunk(1, 1); CP_COMMIT(); }

    int lrow = lane & 15;
    int lkc8 = (lane >> 4) * 8;

    for (int c = 0; c < NC; c++) {
        int s = c % 3;
        if (c + 2 < NC) {
            load_chunk(c + 2, (c + 2) % 3);
            CP_COMMIT();
            CP_WAIT(2);
        } else if (c + 1 < NC) {
            CP_WAIT(1);
        } else {
            CP_WAIT(0);
        }
        __syncthreads();

        uint32_t sAh = sbase + s*65536;
        uint32_t sAl = sAh + 16384;
        uint32_t sBh = sAh + 32768;
        uint32_t sBl = sAh + 49152;

        #pragma unroll
        for (int ks = 0; ks < 4; ks++) {
            int k0 = ks*16;
            uint32_t ah[2][4], al[2][4];
            #pragma unroll
            for (int tm = 0; tm < 2; tm++) {
                uint32_t off = SWZ((uint32_t)(wm*32 + tm*16 + lrow)*128
                                   + (uint32_t)(k0 + lkc8)*2);
                LDSM4(ah[tm], sAh + off);
                LDSM4(al[tm], sAl + off);
            }
            uint32_t bh[4][4], bl[4][4];
            #pragma unroll
            for (int g = 0; g < 4; g++) {
                uint32_t off = SWZ((uint32_t)(wn*64 + g*16 + lrow)*128
                                   + (uint32_t)(k0 + lkc8)*2);
                LDSM4(bh[g], sBh + off);
                LDSM4(bl[g], sBl + off);
            }
            // term hh (16 MMAs), then hl, then lh — each acc's 3 MMAs are
            // spaced 16 instructions apart -> RAW latency hidden
            #pragma unroll
            for (int tm = 0; tm < 2; tm++)
                #pragma unroll
                for (int g = 0; g < 4; g++) {
                    MMA16816(acc[tm][2*g  ], ah[tm], bh[g][0], bh[g][2]);
                    MMA16816(acc[tm][2*g+1], ah[tm], bh[g][1], bh[g][3]);
                }
            #pragma unroll
            for (int tm = 0; tm < 2; tm++)
                #pragma unroll
                for (int g = 0; g < 4; g++) {
                    MMA16816(acc[tm][2*g  ], ah[tm], bl[g][0], bl[g][2]);
                    MMA16816(acc[tm][2*g+1], ah[tm], bl[g][1], bl[g][3]);
                }
            #pragma unroll
            for (int tm = 0; tm < 2; tm++)
                #pragma unroll
                for (int g = 0; g < 4; g++) {
                    MMA16816(acc[tm][2*g  ], al[tm], bh[g][0], bh[g][2]);
                    MMA16816(acc[tm][2*g+1], al[tm], bh[g][1], bh[g][3]);
                }
        }
    }

    // ---- epilogue ----
    int gr = lane >> 2, gc = lane & 3;
    #pragma unroll
    for (int tm = 0; tm < 2; tm++) {
        #pragma unroll
        for (int tn = 0; tn < 8; tn++) {
            float* a = acc[tm][tn];
            int rIn0 = wm*32 + tm*16 + gr;
            int col  = nt*128 + wn*64 + tn*8 + gc*2;
            if (mode == 3) {
                int kc = col >> 6, cc = col & 63;
                size_t tb = ((size_t)mt * (N >> 6) + kc) * 8192;
                #pragma unroll
                for (int hhalf = 0; hhalf < 2; hhalf++) {
                    int rIn = rIn0 + hhalf*8;
                    float v0 = a[hhalf*2]     + bias[col];
                    float v1 = a[hhalf*2 + 1] + bias[col + 1];
                    v0 = 0.5f * v0 * (1.0f + erff(v0 * 0.70710678118654752f));
                    v1 = 0.5f * v1 * (1.0f + erff(v1 * 0.70710678118654752f));
                    __nv_bfloat16 h0 = __float2bfloat16(v0);
                    __nv_bfloat16 l0 = __float2bfloat16(v0 - __bfloat162float(h0));
                    __nv_bfloat16 h1 = __float2bfloat16(v1);
                    __nv_bfloat16 l1 = __float2bfloat16(v1 - __bfloat162float(h1));
                    uint32_t uh = (uint32_t)__bfloat16_as_ushort(h0)
                                | ((uint32_t)__bfloat16_as_ushort(h1) << 16);
                    uint32_t ul = (uint32_t)__bfloat16_as_ushort(l0)
                                | ((uint32_t)__bfloat16_as_ushort(l1) << 16);
                    uint32_t bo = SWZ((uint32_t)rIn*128 + (uint32_t)cc*2);
                    *(uint32_t*)((char*)(Ohi + tb) + bo) = uh;
                    *(uint32_t*)((char*)(Olo + tb) + bo) = ul;
                }
            } else {
                #pragma unroll
                for (int hhalf = 0; hhalf < 2; hhalf++) {
                    int row = mt*128 + rIn0 + hhalf*8;
                    float v0 = a[hhalf*2], v1 = a[hhalf*2 + 1];
                    if (mode == 2) {
                        v0 += bias[col]     + resid[(size_t)row*N + col];
                        v1 += bias[col + 1] + resid[(size_t)row*N + col + 1];
                    }
                    float2 o = {v0, v1};
                    *(float2*)(Cf + (size_t)row*N + col) = o;
                }
            }
        }
    }
}

// ---------------------------------------------------------------------------
// causal flash attention fp32 (reads fused QKV, row stride 3072);
// outputs bf16 hi/lo swizzled A-tiles (K=1024)
// ---------------------------------------------------------------------------
#define QKVS (3*DMODEL)

__global__ __launch_bounds__(256)
void attn_kernel(const float* __restrict__ QKV,
                 __nv_bfloat16* __restrict__ yhi, __nv_bfloat16* __restrict__ ylo)
{
    __shared__ float qs[64][64];
    __shared__ float ks[64][64];
    __shared__ float vs[64][64];
    int qt = blockIdx.x, h = blockIdx.y, b = blockIdx.z;
    int tid = threadIdx.x, warp = tid >> 5, lane = tid & 31;
    size_t base = ((size_t)b * SEQ) * QKVS + h * DHEAD;
    const float* Q = QKV + base;
    const float* K = QKV + base + DMODEL;
    const float* V = QKV + base + 2*DMODEL;

    {
        int r = tid >> 2, c0 = (tid & 3) * 16;
        const float* src = Q + (size_t)(qt*64 + r) * QKVS + c0;
        float4* dst = (float4*)&qs[r][c0];
        #pragma unroll
        for (int i = 0; i < 4; i++) dst[i] = ((const float4*)src)[i];
    }
    float m[8], l[8], o0[8], o1[8];
    #pragma unroll
    for (int rr = 0; rr < 8; rr++) { m[rr] = -1e30f; l[rr] = 0.f; o0[rr] = 0.f; o1[rr] = 0.f; }
    __syncthreads();

    for (int kt = 0; kt <= qt; kt++) {
        {
            int j = tid >> 2, c0 = (tid & 3) * 16;
            const float* ksrc = K + (size_t)(kt*64 + j) * QKVS + c0;
            const float* vsrc = V + (size_t)(kt*64 + j) * QKVS + c0;
            #pragma unroll
            for (int i = 0; i < 4; i++) {
                float4 kv = ((const float4*)ksrc)[i];
                ks[c0 + i*4 + 0][j] = kv.x; ks[c0 + i*4 + 1][j] = kv.y;
                ks[c0 + i*4 + 2][j] = kv.z; ks[c0 + i*4 + 3][j] = kv.w;
                ((float4*)&vs[j][c0])[i] = ((const float4*)vsrc)[i];
            }
        }
        __syncthreads();
        bool diag = (kt == qt);
        float p0[8], p1[8];
        #pragma unroll
        for (int rr = 0; rr < 8; rr++) {
            int r = warp*8 + rr;
            float s0 = 0.f, s1 = 0.f;
            #pragma unroll 16
            for (int d = 0; d < 64; d++) {
                float qv = qs[r][d];
                s0 += qv * ks[d][lane];
                s1 += qv * ks[d][lane + 32];
            }
            s0 *= 0.125f; s1 *= 0.125f;
            if (diag) {
                if (lane > r)      s0 = -1e30f;
                if (lane + 32 > r) s1 = -1e30f;
            }
            float smax = fmaxf(s0, s1);
            #pragma unroll
            for (int off = 16; off; off >>= 1)
                smax = fmaxf(smax, __shfl_xor_sync(0xffffffffu, smax, off));
            float mnew  = fmaxf(m[rr], smax);
            float alpha = __expf(m[rr] - mnew);
            float e0 = __expf(s0 - mnew), e1 = __expf(s1 - mnew);
            float psum = e0 + e1;
            #pragma unroll
            for (int off = 16; off; off >>= 1)
                psum += __shfl_xor_sync(0xffffffffu, psum, off);
            l[rr] = l[rr]*alpha + psum;
            m[rr] = mnew;
            o0[rr] *= alpha; o1[rr] *= alpha;
            p0[rr] = e0; p1[rr] = e1;
        }
        __syncthreads();
        #pragma unroll
        for (int rr = 0; rr < 8; rr++) {
            int r = warp*8 + rr;
            ks[r][lane] = p0[rr]; ks[r][lane + 32] = p1[rr];
        }
        __syncwarp();
        #pragma unroll
        for (int rr = 0; rr < 8; rr++) {
            int r = warp*8 + rr;
            float a0 = 0.f, a1 = 0.f;
            #pragma unroll 16
            for (int j = 0; j < 64; j++) {
                float p = ks[r][j];
                a0 += p * vs[j][lane];
                a1 += p * vs[j][lane + 32];
            }
            o0[rr] += a0; o1[rr] += a1;
        }
        __syncthreads();
    }

    #pragma unroll
    for (int rr = 0; rr < 8; rr++) {
        int r = warp*8 + rr;
        float inv = 1.0f / l[rr];
        float v0 = o0[rr] * inv, v1 = o1[rr] * inv;
        int mtok = b*SEQ + qt*64 + r;
        size_t tb = ((size_t)(mtok >> 7) * 16 + h) * 8192;
        uint32_t bo0 = SWZ((uint32_t)(mtok & 127)*128 + (uint32_t)lane*2);
        uint32_t bo1 = SWZ((uint32_t)(mtok & 127)*128 + (uint32_t)(lane + 32)*2);
        __nv_bfloat16 h0 = __float2bfloat16(v0);
        __nv_bfloat16 l0 = __float2bfloat16(v0 - __bfloat162float(h0));
        __nv_bfloat16 h1 = __float2bfloat16(v1);
        __nv_bfloat16 l1 = __float2bfloat16(v1 - __bfloat162float(h1));
        *(__nv_bfloat16*)((char*)(yhi + tb) + bo0) = h0;
        *(__nv_bfloat16*)((char*)(ylo + tb) + bo0) = l0;
        *(__nv_bfloat16*)((char*)(yhi + tb) + bo1) = h1;
        *(__nv_bfloat16*)((char*)(ylo + tb) + bo1) = l1;
    }
}

// ---------------------------------------------------------------------------
// launch
// ---------------------------------------------------------------------------
extern "C" void kernel_launch(void* const* d_in, const int* in_sizes, int n_in,
                              void* d_out, int out_size)
{
    const float* states     = (const float*)d_in[0];
    const int*   timesteps  = (const int*)  d_in[1];
    const float* se_w1 = (const float*)d_in[2];
    const float* se_b1 = (const float*)d_in[3];
    const float* se_w2 = (const float*)d_in[4];
    const float* se_b2 = (const float*)d_in[5];
    const float* se_w3 = (const float*)d_in[6];
    const float* se_b3 = (const float*)d_in[7];
    const float* pos_emb = (const float*)d_in[8];
    const float* gpe     = (const float*)d_in[9];
    const float* ln1_g = (const float*)d_in[10];
    const float* ln1_b = (const float*)d_in[11];
    const float* Wq = (const float*)d_in[12];
    const float* Wk = (const float*)d_in[13];
    const float* Wv = (const float*)d_in[14];
    const float* Wp = (const float*)d_in[15];
    const float* bp = (const float*)d_in[16];
    const float* ln2_g = (const float*)d_in[17];
    const float* ln2_b = (const float*)d_in[18];
    const float* W1 = (const float*)d_in[19];
    const float* b1 = (const float*)d_in[20];
    const float* W2 = (const float*)d_in[21];
    const float* b2 = (const float*)d_in[22];
    const float* lnf_g = (const float*)d_in[23];
    const float* lnf_b = (const float*)d_in[24];
    const float* head_w = (const float*)d_in[25];

    float *x, *qkv;
    __nv_bfloat16 *hnh, *hnl, *yh, *yl, *mh, *ml, *wh, *wl;
    cudaGetSymbolAddress((void**)&x,   g_x);
    cudaGetSymbolAddress((void**)&qkv, g_qkv);
    cudaGetSymbolAddress((void**)&hnh, g_hn_hi);
    cudaGetSymbolAddress((void**)&hnl, g_hn_lo);
    cudaGetSymbolAddress((void**)&yh,  g_y_hi);
    cudaGetSymbolAddress((void**)&yl,  g_y_lo);
    cudaGetSymbolAddress((void**)&mh,  g_mlp_hi);
    cudaGetSymbolAddress((void**)&ml,  g_mlp_lo);
    cudaGetSymbolAddress((void**)&wh,  g_w_hi);
    cudaGetSymbolAddress((void**)&wl,  g_w_lo);

    cudaFuncSetAttribute(gemm_mma, cudaFuncAttributeMaxDynamicSharedMemorySize, GEMM_SMEM);

    // launch #0: all weight conversion in one kernel
    convert_all<<<10144, 256>>>(Wq, Wk, Wv, Wp, W1, W2, head_w, wh, wl);
    // launch #1
    embed_kernel<<<NTOK, 256>>>(states, timesteps, se_w1, se_b1, se_w2, se_b2,
                                se_w3, se_b3, pos_emb, gpe, x);

    const size_t LW = LWq, MDD = MDDq;
    dim3 gQKV(24, 32), gDD(8, 32), gD4(32, 32), gHead(250, 32);
    dim3 gAttn(SEQ/64, NHEAD, BATCH);

    for (int l = 0; l < NLAYER; l++) {
        size_t wb = (size_t)l * LW;
        // launch #2 (+7 per layer)
        ln_hilo_kernel<<<NTOK, 256>>>(x, ln1_g + l*DMODEL, ln1_b + l*DMODEL, hnh, hnl);
        // launch #3: fused QKV GEMM (N=3072)
        gemm_mma<<<gQKV, 256, GEMM_SMEM>>>((uint4*)hnh, (uint4*)hnl,
            (uint4*)(wh + wb), (uint4*)(wl + wb),
            nullptr, nullptr, qkv, nullptr, nullptr, 3*DMODEL, 1024, 0);
        // launch #4
        attn_kernel<<<gAttn, 256>>>(qkv, yh, yl);
        // launch #5: proj GEMM  <-- ncu -s 5 profiles this one
        gemm_mma<<<gDD, 256, GEMM_SMEM>>>((uint4*)yh, (uint4*)yl,
            (uint4*)(wh + wb + 3*MDD), (uint4*)(wl + wb + 3*MDD),
            bp + l*DMODEL, x, x, nullptr, nullptr, 1024, 1024, 2);
        ln_hilo_kernel<<<NTOK, 256>>>(x, ln2_g + l*DMODEL, ln2_b + l*DMODEL, hnh, hnl);
        gemm_mma<<<gD4, 256, GEMM_SMEM>>>((uint4*)hnh, (uint4*)hnl,
            (uint4*)(wh + wb + 4*MDD), (uint4*)(wl + wb + 4*MDD),
            b1 + (size_t)l*4*DMODEL, nullptr, nullptr, mh, ml, 4096, 1024, 3);
        gemm_mma<<<gDD, 256, GEMM_SMEM>>>((uint4*)mh, (uint4*)ml,
            (uint4*)(wh + wb + 8*MDD), (uint4*)(wl + wb + 8*MDD),
            b2 + l*DMODEL, x, x, nullptr, nullptr, 1024, 4096, 2);
    }

    ln_hilo_kernel<<<NTOK, 256>>>(x, lnf_g, lnf_b, hnh, hnl);
    gemm_mma<<<gHead, 256, GEMM_SMEM>>>((uint4*)hnh, (uint4*)hnl,
        (uint4*)(wh + 4*LW), (uint4*)(wl + 4*LW),
        nullptr, nullptr, (float*)d_out, nullptr, nullptr, 32000, 1024, 0);
}

// round 13
// speedup vs baseline: 2.1741x; 1.0047x over previous
#include <cuda_runtime.h>
#include <cuda_bf16.h>
#include <math.h>
#include <stdint.h>

#define BATCH 4
#define SEQ   1024
#define DMODEL 1024
#define NHEAD 16
#define NLAYER 4
#define VOCAB 32000
#define DHEAD 64
#define NTOK (BATCH*SEQ)   // 4096

// SW128 swizzle (Swizzle<3,4,3>)
#define SWZ(b) ((b) ^ ((((unsigned)(b)) >> 3) & 0x70u))

// ---------------------------------------------------------------------------
// PTX helpers (portable: sm_80+ PTX, runs on sm_103a)
// ---------------------------------------------------------------------------
__device__ __forceinline__ uint32_t smem_u32(const void* p) {
    uint32_t a;
    asm("{ .reg .u64 t; cvta.to.shared.u64 t, %1; cvt.u32.u64 %0, t; }" : "=r"(a) : "l"(p));
    return a;
}
__device__ __forceinline__ void cp16(uint32_t dst, const void* src) {
    asm volatile("cp.async.cg.shared.global [%0], [%1], 16;" :: "r"(dst), "l"(src));
}
#define CP_COMMIT() asm volatile("cp.async.commit_group;" ::: "memory")
#define CP_WAIT(n)  asm volatile("cp.async.wait_group %0;" :: "n"(n) : "memory")

#define LDSM4(r, addr) \
    asm volatile("ldmatrix.sync.aligned.m8n8.x4.shared.b16 {%0,%1,%2,%3}, [%4];" \
        : "=r"((r)[0]), "=r"((r)[1]), "=r"((r)[2]), "=r"((r)[3]) : "r"(addr))

#define MMA16816(d, a, b0, b1) \
    asm volatile("mma.sync.aligned.m16n8k16.row.col.f32.bf16.bf16.f32 " \
        "{%0,%1,%2,%3}, {%4,%5,%6,%7}, {%8,%9}, {%0,%1,%2,%3};" \
        : "+f"((d)[0]), "+f"((d)[1]), "+f"((d)[2]), "+f"((d)[3]) \
        : "r"((a)[0]), "r"((a)[1]), "r"((a)[2]), "r"((a)[3]), "r"(b0), "r"(b1))

// ---------------------------------------------------------------------------
// scratch (device globals)
// ---------------------------------------------------------------------------
__device__ float g_x  [NTOK*DMODEL];
__device__ float g_qkv[NTOK*3*DMODEL];
__device__ __nv_bfloat16 g_hn_hi[NTOK*DMODEL];
__device__ __nv_bfloat16 g_hn_lo[NTOK*DMODEL];
__device__ __nv_bfloat16 g_y_hi [NTOK*DMODEL];
__device__ __nv_bfloat16 g_y_lo [NTOK*DMODEL];
__device__ __nv_bfloat16 g_mlp_hi[NTOK*4*DMODEL];
__device__ __nv_bfloat16 g_mlp_lo[NTOK*4*DMODEL];
// weights, transposed [N,K] + swizzled tile format, hi/lo split
#define WTOTAL 83099648ull   // 4*12*MDD + 1024*32000
#define LWq 12582912ull
#define MDDq 1048576ull
__device__ __nv_bfloat16 g_w_hi[WTOTAL];
__device__ __nv_bfloat16 g_w_lo[WTOTAL];

// ---------------------------------------------------------------------------
// single-launch weight convert: all weights -> hi/lo bf16 [N,K] swizzled tiles
// grid = 10144 blocks; per-layer layout (elems):
//   QKV fused (nt 0..23) @ wb, proj @ wb+3M, W1 @ wb+4M, W2 @ wb+8M; head @ 4*LW
// ---------------------------------------------------------------------------
__global__ __launch_bounds__(256)
void convert_all(const float* __restrict__ Wq, const float* __restrict__ Wk,
                 const float* __restrict__ Wv, const float* __restrict__ Wp,
                 const float* __restrict__ W1, const float* __restrict__ W2,
                 const float* __restrict__ Whead,
                 __nv_bfloat16* __restrict__ wh, __nv_bfloat16* __restrict__ wl)
{
    int bid = blockIdx.x;
    const float* W; int N, kc, nt;
    size_t dstBlk;
    if (bid < 6144) {
        int l = bid / 1536, r = bid % 1536;
        size_t wb = (size_t)l * LWq;
        if (r < 384) {                       // fused QKV
            int nt_f = r >> 4; kc = r & 15;
            int sel = nt_f >> 3; nt = nt_f & 7;
            W = (sel == 0 ? Wq : (sel == 1 ? Wk : Wv)) + (size_t)l*DMODEL*DMODEL;
            N = 1024;
            dstBlk = wb + ((size_t)nt_f*16 + kc)*8192;
        } else if (r < 512) {                // proj
            int i = r - 384; nt = i >> 4; kc = i & 15;
            W = Wp + (size_t)l*DMODEL*DMODEL; N = 1024;
            dstBlk = wb + 3*MDDq + ((size_t)nt*16 + kc)*8192;
        } else if (r < 1024) {               // W1 [1024 -> 4096]
            int i = r - 512; nt = i >> 4; kc = i & 15;
            W = W1 + (size_t)l*DMODEL*4*DMODEL; N = 4096;
            dstBlk = wb + 4*MDDq + ((size_t)nt*16 + kc)*8192;
        } else {                             // W2 [4096 -> 1024]
            int i = r - 1024; nt = i >> 6; kc = i & 63;
            W = W2 + (size_t)l*DMODEL*4*DMODEL; N = 1024;
            dstBlk = wb + 8*MDDq + ((size_t)nt*64 + kc)*8192;
        }
    } else {                                 // head [1024 -> 32000]
        int i = bid - 6144; nt = i >> 4; kc = i & 15;
        W = Whead; N = 32000;
        dstBlk = 4*LWq + ((size_t)nt*16 + kc)*8192;
    }

    int t = threadIdx.x;
    int n_loc = t & 127, grp = t >> 7;
    uint4* hi4 = (uint4*)(wh + dstBlk);
    uint4* lo4 = (uint4*)(wl + dstBlk);
    #pragma unroll
    for (int g = 0; g < 4; g++) {
        int kg = grp + g*2;
        int k0 = kc*64 + kg*8;
        unsigned hs[8], ls[8];
        #pragma unroll
        for (int i = 0; i < 8; i++) {
            float v = W[(size_t)(k0 + i) * N + nt*128 + n_loc];
            __nv_bfloat16 h = __float2bfloat16(v);
            __nv_bfloat16 l = __float2bfloat16(v - __bfloat162float(h));
            hs[i] = __bfloat16_as_ushort(h);
            ls[i] = __bfloat16_as_ushort(l);
        }
        uint4 uh, ul;
        uh.x = hs[0] | (hs[1] << 16); uh.y = hs[2] | (hs[3] << 16);
        uh.z = hs[4] | (hs[5] << 16); uh.w = hs[6] | (hs[7] << 16);
        ul.x = ls[0] | (ls[1] << 16); ul.y = ls[2] | (ls[3] << 16);
        ul.z = ls[4] | (ls[5] << 16); ul.w = ls[6] | (ls[7] << 16);
        uint32_t bo = SWZ((uint32_t)n_loc*128 + (uint32_t)kg*16);
        hi4[bo >> 4] = uh;
        lo4[bo >> 4] = ul;
    }
}

// ---------------------------------------------------------------------------
// embed (fp32 residual stream)
// ---------------------------------------------------------------------------
__global__ __launch_bounds__(256)
void embed_kernel(const float* __restrict__ states, const int* __restrict__ timesteps,
                  const float* __restrict__ w1, const float* __restrict__ b1,
                  const float* __restrict__ w2, const float* __restrict__ b2,
                  const float* __restrict__ w3, const float* __restrict__ b3,
                  const float* __restrict__ pos_emb, const float* __restrict__ gpe,
                  float* __restrict__ x)
{
    int token = blockIdx.x;
    int b = token / SEQ, s = token % SEQ;
    __shared__ float st[4], h1[16], h2[16];
    int tid = threadIdx.x;
    if (tid < 4) st[tid] = states[token*4 + tid];
    __syncthreads();
    if (tid < 16) {
        float a = b1[tid];
        #pragma unroll
        for (int i = 0; i < 4; i++) a += st[i] * w1[i*16 + tid];
        h1[tid] = fmaxf(a, 0.0f);
    }
    __syncthreads();
    if (tid < 16) {
        float a = b2[tid];
        #pragma unroll
        for (int i = 0; i < 16; i++) a += h1[i] * w2[i*16 + tid];
        h2[tid] = fmaxf(a, 0.0f);
    }
    __syncthreads();
    int t = timesteps[b];
    for (int d = tid; d < DMODEL; d += blockDim.x) {
        float a = b3[d];
        #pragma unroll
        for (int i = 0; i < 16; i++) a += h2[i] * w3[i*DMODEL + d];
        x[(size_t)token*DMODEL + d] = tanhf(a) + gpe[(size_t)t*DMODEL + d]
                                      + pos_emb[(size_t)s*DMODEL + d];
    }
}

// ---------------------------------------------------------------------------
// layernorm: fp32 in -> bf16 hi/lo swizzled A-tiles (K=1024)
// ---------------------------------------------------------------------------
__global__ __launch_bounds__(256)
void ln_hilo_kernel(const float* __restrict__ X,
                    const float* __restrict__ g, const float* __restrict__ b,
                    __nv_bfloat16* __restrict__ ohi, __nv_bfloat16* __restrict__ olo)
{
    int row = blockIdx.x;
    const float* xr = X + (size_t)row*DMODEL;
    int tid = threadIdx.x;
    float4 v = *(const float4*)(xr + tid*4);
    float s = v.x+v.y+v.z+v.w;
    float sq = v.x*v.x + v.y*v.y + v.z*v.z + v.w*v.w;
    __shared__ float rs[8], rq[8];
    #pragma unroll
    for (int off = 16; off; off >>= 1) {
        s  += __shfl_xor_sync(0xffffffffu, s,  off);
        sq += __shfl_xor_sync(0xffffffffu, sq, off);
    }
    if ((tid & 31) == 0) { rs[tid>>5] = s; rq[tid>>5] = sq; }
    __syncthreads();
    if (tid < 32) {
        s  = (tid < 8) ? rs[tid] : 0.f;
        sq = (tid < 8) ? rq[tid] : 0.f;
        #pragma unroll
        for (int off = 4; off; off >>= 1) {
            s  += __shfl_xor_sync(0xffffffffu, s,  off);
            sq += __shfl_xor_sync(0xffffffffu, sq, off);
        }
        if (tid == 0) { rs[0] = s; rq[0] = sq; }
    }
    __syncthreads();
    float mu  = rs[0] * (1.0f/DMODEL);
    float var = rq[0] * (1.0f/DMODEL) - mu*mu;
    float r   = rsqrtf(var + 1e-5f);
    int k0 = tid*4;
    float o[4] = {v.x, v.y, v.z, v.w};
    unsigned hs[4], ls[4];
    #pragma unroll
    for (int i = 0; i < 4; i++) {
        int c = k0 + i;
        float val = (o[i] - mu) * r * g[c] + b[c];
        __nv_bfloat16 h = __float2bfloat16(val);
        __nv_bfloat16 l = __float2bfloat16(val - __bfloat162float(h));
        hs[i] = __bfloat16_as_ushort(h);
        ls[i] = __bfloat16_as_ushort(l);
    }
    int kc = k0 >> 6, c = k0 & 63;
    size_t tb = ((size_t)(row >> 7) * 16 + kc) * 8192;
    uint32_t bo = SWZ((uint32_t)(row & 127)*128 + (uint32_t)c*2);
    uint2 uh = { hs[0] | (hs[1] << 16), hs[2] | (hs[3] << 16) };
    uint2 ul = { ls[0] | (ls[1] << 16), ls[2] | (ls[3] << 16) };
    *(uint2*)((char*)(ohi + tb) + bo) = uh;
    *(uint2*)((char*)(olo + tb) + bo) = ul;
}

// ---------------------------------------------------------------------------
// mma.sync GEMM, 3-stage cp.async pipeline, split-term-outer MMA order.
// 512 threads = 16 warps (4x4 warp grid), warp tile 32x32 -> low per-thread
// register state (acc 32 + frags 32), 4 warps/SMSP to fill the tensor pipe.
// C[M,N] = A[M,K] x W[K,N]; grid (N/128, M/128).
// mode 0: C fp32      2: C fp32 = +bias +resid      3: gelu(+bias) -> Ohi/Olo
// ---------------------------------------------------------------------------
#define GEMM_SMEM 196608

__global__ __launch_bounds__(512, 1)
void gemm_mma(const uint4* __restrict__ Ahi, const uint4* __restrict__ Alo,
              const uint4* __restrict__ Bhi, const uint4* __restrict__ Blo,
              const float* __restrict__ bias, const float* __restrict__ resid,
              float* __restrict__ Cf,
              __nv_bfloat16* __restrict__ Ohi, __nv_bfloat16* __restrict__ Olo,
              int N, int K, int mode)
{
    extern __shared__ char sb[];
    uint32_t sbase = smem_u32(sb);
    int tid = threadIdx.x, wid = tid >> 5, lane = tid & 31;
    int nt = blockIdx.x, mt = blockIdx.y;
    int NC = K >> 6;
    int wm = wid & 3, wn = wid >> 2;   // 4x4 warp grid; warp tile 32 rows x 32 cols

    const uint4* gA0h = Ahi + (size_t)mt * NC * 1024;
    const uint4* gA0l = Alo + (size_t)mt * NC * 1024;
    const uint4* gB0h = Bhi + (size_t)nt * NC * 1024;
    const uint4* gB0l = Blo + (size_t)nt * NC * 1024;

    float acc[2][4][4];
    #pragma unroll
    for (int i = 0; i < 2; i++)
        #pragma unroll
        for (int j = 0; j < 4; j++)
            #pragma unroll
            for (int q = 0; q < 4; q++) acc[i][j][q] = 0.f;

    auto load_chunk = [&](int c, int s) {
        uint32_t sA = sbase + s*65536;
        const uint4* ah = gA0h + (size_t)c*1024;
        const uint4* al = gA0l + (size_t)c*1024;
        const uint4* bh = gB0h + (size_t)c*1024;
        const uint4* bl = gB0l + (size_t)c*1024;
        #pragma unroll
        for (int i = 0; i < 2; i++) {
            int idx = tid + i*512;
            cp16(sA +         idx*16, ah + idx);
            cp16(sA + 16384 + idx*16, al + idx);
            cp16(sA + 32768 + idx*16, bh + idx);
            cp16(sA + 49152 + idx*16, bl + idx);
        }
    };

    load_chunk(0, 0);
    CP_COMMIT();
    if (NC > 1) { load_chunk(1, 1); CP_COMMIT(); }

    int lrow = lane & 15;
    int lkc8 = (lane >> 4) * 8;

    for (int c = 0; c < NC; c++) {
        int s = c % 3;
        if (c + 2 < NC) {
            load_chunk(c + 2, (c + 2) % 3);
            CP_COMMIT();
            CP_WAIT(2);
        } else if (c + 1 < NC) {
            CP_WAIT(1);
        } else {
            CP_WAIT(0);
        }
        __syncthreads();

        uint32_t sAh = sbase + s*65536;
        uint32_t sAl = sAh + 16384;
        uint32_t sBh = sAh + 32768;
        uint32_t sBl = sAh + 49152;

        #pragma unroll
        for (int ks = 0; ks < 4; ks++) {
            int k0 = ks*16;
            uint32_t ah[2][4], al[2][4];
            #pragma unroll
            for (int tm = 0; tm < 2; tm++) {
                uint32_t off = SWZ((uint32_t)(wm*32 + tm*16 + lrow)*128
                                   + (uint32_t)(k0 + lkc8)*2);
                LDSM4(ah[tm], sAh + off);
                LDSM4(al[tm], sAl + off);
            }
            uint32_t bh[2][4], bl[2][4];
            #pragma unroll
            for (int g = 0; g < 2; g++) {
                uint32_t off = SWZ((uint32_t)(wn*32 + g*16 + lrow)*128
                                   + (uint32_t)(k0 + lkc8)*2);
                LDSM4(bh[g], sBh + off);
                LDSM4(bl[g], sBl + off);
            }
            // hh (8 MMAs), then hl, then lh — same-acc MMAs spaced 8 apart
            #pragma unroll
            for (int tm = 0; tm < 2; tm++)
                #pragma unroll
                for (int g = 0; g < 2; g++) {
                    MMA16816(acc[tm][2*g  ], ah[tm], bh[g][0], bh[g][2]);
                    MMA16816(acc[tm][2*g+1], ah[tm], bh[g][1], bh[g][3]);
                }
            #pragma unroll
            for (int tm = 0; tm < 2; tm++)
                #pragma unroll
                for (int g = 0; g < 2; g++) {
                    MMA16816(acc[tm][2*g  ], ah[tm], bl[g][0], bl[g][2]);
                    MMA16816(acc[tm][2*g+1], ah[tm], bl[g][1], bl[g][3]);
                }
            #pragma unroll
            for (int tm = 0; tm < 2; tm++)
                #pragma unroll
                for (int g = 0; g < 2; g++) {
                    MMA16816(acc[tm][2*g  ], al[tm], bh[g][0], bh[g][2]);
                    MMA16816(acc[tm][2*g+1], al[tm], bh[g][1], bh[g][3]);
                }
        }
    }

    // ---- epilogue: warp covers rows wm*32..+31, cols wn*32..+31 ----
    int gr = lane >> 2, gc = lane & 3;
    #pragma unroll
    for (int tm = 0; tm < 2; tm++) {
        #pragma unroll
        for (int tn = 0; tn < 4; tn++) {
            float* a = acc[tm][tn];
            int rIn0 = wm*32 + tm*16 + gr;
            int col  = nt*128 + wn*32 + tn*8 + gc*2;
            if (mode == 3) {
                int kc = col >> 6, cc = col & 63;
                size_t tb = ((size_t)mt * (N >> 6) + kc) * 8192;
                #pragma unroll
                for (int hhalf = 0; hhalf < 2; hhalf++) {
                    int rIn = rIn0 + hhalf*8;
                    float v0 = a[hhalf*2]     + bias[col];
                    float v1 = a[hhalf*2 + 1] + bias[col + 1];
                    v0 = 0.5f * v0 * (1.0f + erff(v0 * 0.70710678118654752f));
                    v1 = 0.5f * v1 * (1.0f + erff(v1 * 0.70710678118654752f));
                    __nv_bfloat16 h0 = __float2bfloat16(v0);
                    __nv_bfloat16 l0 = __float2bfloat16(v0 - __bfloat162float(h0));
                    __nv_bfloat16 h1 = __float2bfloat16(v1);
                    __nv_bfloat16 l1 = __float2bfloat16(v1 - __bfloat162float(h1));
                    uint32_t uh = (uint32_t)__bfloat16_as_ushort(h0)
                                | ((uint32_t)__bfloat16_as_ushort(h1) << 16);
                    uint32_t ul = (uint32_t)__bfloat16_as_ushort(l0)
                                | ((uint32_t)__bfloat16_as_ushort(l1) << 16);
                    uint32_t bo = SWZ((uint32_t)rIn*128 + (uint32_t)cc*2);
                    *(uint32_t*)((char*)(Ohi + tb) + bo) = uh;
                    *(uint32_t*)((char*)(Olo + tb) + bo) = ul;
                }
            } else {
                #pragma unroll
                for (int hhalf = 0; hhalf < 2; hhalf++) {
                    int row = mt*128 + rIn0 + hhalf*8;
                    float v0 = a[hhalf*2], v1 = a[hhalf*2 + 1];
                    if (mode == 2) {
                        v0 += bias[col]     + resid[(size_t)row*N + col];
                        v1 += bias[col + 1] + resid[(size_t)row*N + col + 1];
                    }
                    float2 o = {v0, v1};
                    *(float2*)(Cf + (size_t)row*N + col) = o;
                }
            }
        }
    }
}

// ---------------------------------------------------------------------------
// causal flash attention fp32 (reads fused QKV, row stride 3072);
// outputs bf16 hi/lo swizzled A-tiles (K=1024)
// ---------------------------------------------------------------------------
#define QKVS (3*DMODEL)

__global__ __launch_bounds__(256)
void attn_kernel(const float* __restrict__ QKV,
                 __nv_bfloat16* __restrict__ yhi, __nv_bfloat16* __restrict__ ylo)
{
    __shared__ float qs[64][64];
    __shared__ float ks[64][64];
    __shared__ float vs[64][64];
    int qt = blockIdx.x, h = blockIdx.y, b = blockIdx.z;
    int tid = threadIdx.x, warp = tid >> 5, lane = tid & 31;
    size_t base = ((size_t)b * SEQ) * QKVS + h * DHEAD;
    const float* Q = QKV + base;
    const float* K = QKV + base + DMODEL;
    const float* V = QKV + base + 2*DMODEL;

    {
        int r = tid >> 2, c0 = (tid & 3) * 16;
        const float* src = Q + (size_t)(qt*64 + r) * QKVS + c0;
        float4* dst = (float4*)&qs[r][c0];
        #pragma unroll
        for (int i = 0; i < 4; i++) dst[i] = ((const float4*)src)[i];
    }
    float m[8], l[8], o0[8], o1[8];
    #pragma unroll
    for (int rr = 0; rr < 8; rr++) { m[rr] = -1e30f; l[rr] = 0.f; o0[rr] = 0.f; o1[rr] = 0.f; }
    __syncthreads();

    for (int kt = 0; kt <= qt; kt++) {
        {
            int j = tid >> 2, c0 = (tid & 3) * 16;
            const float* ksrc = K + (size_t)(kt*64 + j) * QKVS + c0;
            const float* vsrc = V + (size_t)(kt*64 + j) * QKVS + c0;
            #pragma unroll
            for (int i = 0; i < 4; i++) {
                float4 kv = ((const float4*)ksrc)[i];
                ks[c0 + i*4 + 0][j] = kv.x; ks[c0 + i*4 + 1][j] = kv.y;
                ks[c0 + i*4 + 2][j] = kv.z; ks[c0 + i*4 + 3][j] = kv.w;
                ((float4*)&vs[j][c0])[i] = ((const float4*)vsrc)[i];
            }
        }
        __syncthreads();
        bool diag = (kt == qt);
        float p0[8], p1[8];
        #pragma unroll
        for (int rr = 0; rr < 8; rr++) {
            int r = warp*8 + rr;
            float s0 = 0.f, s1 = 0.f;
            #pragma unroll 16
            for (int d = 0; d < 64; d++) {
                float qv = qs[r][d];
                s0 += qv * ks[d][lane];
                s1 += qv * ks[d][lane + 32];
            }
            s0 *= 0.125f; s1 *= 0.125f;
            if (diag) {
                if (lane > r)      s0 = -1e30f;
                if (lane + 32 > r) s1 = -1e30f;
            }
            float smax = fmaxf(s0, s1);
            #pragma unroll
            for (int off = 16; off; off >>= 1)
                smax = fmaxf(smax, __shfl_xor_sync(0xffffffffu, smax, off));
            float mnew  = fmaxf(m[rr], smax);
            float alpha = __expf(m[rr] - mnew);
            float e0 = __expf(s0 - mnew), e1 = __expf(s1 - mnew);
            float psum = e0 + e1;
            #pragma unroll
            for (int off = 16; off; off >>= 1)
                psum += __shfl_xor_sync(0xffffffffu, psum, off);
            l[rr] = l[rr]*alpha + psum;
            m[rr] = mnew;
            o0[rr] *= alpha; o1[rr] *= alpha;
            p0[rr] = e0; p1[rr] = e1;
        }
        __syncthreads();
        #pragma unroll
        for (int rr = 0; rr < 8; rr++) {
            int r = warp*8 + rr;
            ks[r][lane] = p0[rr]; ks[r][lane + 32] = p1[rr];
        }
        __syncwarp();
        #pragma unroll
        for (int rr = 0; rr < 8; rr++) {
            int r = warp*8 + rr;
            float a0 = 0.f, a1 = 0.f;
            #pragma unroll 16
            for (int j = 0; j < 64; j++) {
                float p = ks[r][j];
                a0 += p * vs[j][lane];
                a1 += p * vs[j][lane + 32];
            }
            o0[rr] += a0; o1[rr] += a1;
        }
        __syncthreads();
    }

    #pragma unroll
    for (int rr = 0; rr < 8; rr++) {
        int r = warp*8 + rr;
        float inv = 1.0f / l[rr];
        float v0 = o0[rr] * inv, v1 = o1[rr] * inv;
        int mtok = b*SEQ + qt*64 + r;
        size_t tb = ((size_t)(mtok >> 7) * 16 + h) * 8192;
        uint32_t bo0 = SWZ((uint32_t)(mtok & 127)*128 + (uint32_t)lane*2);
        uint32_t bo1 = SWZ((uint32_t)(mtok & 127)*128 + (uint32_t)(lane + 32)*2);
        __nv_bfloat16 h0 = __float2bfloat16(v0);
        __nv_bfloat16 l0 = __float2bfloat16(v0 - __bfloat162float(h0));
        __nv_bfloat16 h1 = __float2bfloat16(v1);
        __nv_bfloat16 l1 = __float2bfloat16(v1 - __bfloat162float(h1));
        *(__nv_bfloat16*)((char*)(yhi + tb) + bo0) = h0;
        *(__nv_bfloat16*)((char*)(ylo + tb) + bo0) = l0;
        *(__nv_bfloat16*)((char*)(yhi + tb) + bo1) = h1;
        *(__nv_bfloat16*)((char*)(ylo + tb) + bo1) = l1;
    }
}

// ---------------------------------------------------------------------------
// launch
// ---------------------------------------------------------------------------
extern "C" void kernel_launch(void* const* d_in, const int* in_sizes, int n_in,
                              void* d_out, int out_size)
{
    const float* states     = (const float*)d_in[0];
    const int*   timesteps  = (const int*)  d_in[1];
    const float* se_w1 = (const float*)d_in[2];
    const float* se_b1 = (const float*)d_in[3];
    const float* se_w2 = (const float*)d_in[4];
    const float* se_b2 = (const float*)d_in[5];
    const float* se_w3 = (const float*)d_in[6];
    const float* se_b3 = (const float*)d_in[7];
    const float* pos_emb = (const float*)d_in[8];
    const float* gpe     = (const float*)d_in[9];
    const float* ln1_g = (const float*)d_in[10];
    const float* ln1_b = (const float*)d_in[11];
    const float* Wq = (const float*)d_in[12];
    const float* Wk = (const float*)d_in[13];
    const float* Wv = (const float*)d_in[14];
    const float* Wp = (const float*)d_in[15];
    const float* bp = (const float*)d_in[16];
    const float* ln2_g = (const float*)d_in[17];
    const float* ln2_b = (const float*)d_in[18];
    const float* W1 = (const float*)d_in[19];
    const float* b1 = (const float*)d_in[20];
    const float* W2 = (const float*)d_in[21];
    const float* b2 = (const float*)d_in[22];
    const float* lnf_g = (const float*)d_in[23];
    const float* lnf_b = (const float*)d_in[24];
    const float* head_w = (const float*)d_in[25];

    float *x, *qkv;
    __nv_bfloat16 *hnh, *hnl, *yh, *yl, *mh, *ml, *wh, *wl;
    cudaGetSymbolAddress((void**)&x,   g_x);
    cudaGetSymbolAddress((void**)&qkv, g_qkv);
    cudaGetSymbolAddress((void**)&hnh, g_hn_hi);
    cudaGetSymbolAddress((void**)&hnl, g_hn_lo);
    cudaGetSymbolAddress((void**)&yh,  g_y_hi);
    cudaGetSymbolAddress((void**)&yl,  g_y_lo);
    cudaGetSymbolAddress((void**)&mh,  g_mlp_hi);
    cudaGetSymbolAddress((void**)&ml,  g_mlp_lo);
    cudaGetSymbolAddress((void**)&wh,  g_w_hi);
    cudaGetSymbolAddress((void**)&wl,  g_w_lo);

    cudaFuncSetAttribute(gemm_mma, cudaFuncAttributeMaxDynamicSharedMemorySize, GEMM_SMEM);

    // launch #0: all weight conversion in one kernel
    convert_all<<<10144, 256>>>(Wq, Wk, Wv, Wp, W1, W2, head_w, wh, wl);
    // launch #1
    embed_kernel<<<NTOK, 256>>>(states, timesteps, se_w1, se_b1, se_w2, se_b2,
                                se_w3, se_b3, pos_emb, gpe, x);

    const size_t LW = LWq, MDD = MDDq;
    dim3 gQKV(24, 32), gDD(8, 32), gD4(32, 32), gHead(250, 32);
    dim3 gAttn(SEQ/64, NHEAD, BATCH);

    for (int l = 0; l < NLAYER; l++) {
        size_t wb = (size_t)l * LW;
        // launch #2 (+7 per layer)
        ln_hilo_kernel<<<NTOK, 256>>>(x, ln1_g + l*DMODEL, ln1_b + l*DMODEL, hnh, hnl);
        // launch #3: fused QKV GEMM (N=3072)
        gemm_mma<<<gQKV, 512, GEMM_SMEM>>>((uint4*)hnh, (uint4*)hnl,
            (uint4*)(wh + wb), (uint4*)(wl + wb),
            nullptr, nullptr, qkv, nullptr, nullptr, 3*DMODEL, 1024, 0);
        // launch #4
        attn_kernel<<<gAttn, 256>>>(qkv, yh, yl);
        // launch #5: proj GEMM  <-- ncu -s 5 profiles this one
        gemm_mma<<<gDD, 512, GEMM_SMEM>>>((uint4*)yh, (uint4*)yl,
            (uint4*)(wh + wb + 3*MDD), (uint4*)(wl + wb + 3*MDD),
            bp + l*DMODEL, x, x, nullptr, nullptr, 1024, 1024, 2);
        ln_hilo_kernel<<<NTOK, 256>>>(x, ln2_g + l*DMODEL, ln2_b + l*DMODEL, hnh, hnl);
        gemm_mma<<<gD4, 512, GEMM_SMEM>>>((uint4*)hnh, (uint4*)hnl,
            (uint4*)(wh + wb + 4*MDD), (uint4*)(wl + wb + 4*MDD),
            b1 + (size_t)l*4*DMODEL, nullptr, nullptr, mh, ml, 4096, 1024, 3);
        gemm_mma<<<gDD, 512, GEMM_SMEM>>>((uint4*)mh, (uint4*)ml,
            (uint4*)(wh + wb + 8*MDD), (uint4*)(wl + wb + 8*MDD),
            b2 + l*DMODEL, x, x, nullptr, nullptr, 1024, 4096, 2);
    }

    ln_hilo_kernel<<<NTOK, 256>>>(x, lnf_g, lnf_b, hnh, hnl);
    gemm_mma<<<gHead, 512, GEMM_SMEM>>>((uint4*)hnh, (uint4*)hnl,
        (uint4*)(wh + 4*LW), (uint4*)(wl + 4*LW),
        nullptr, nullptr, (float*)d_out, nullptr, nullptr, 32000, 1024, 0);
}

// round 14
// speedup vs baseline: 3.3043x; 1.5199x over previous
#include <cuda_runtime.h>
#include <cuda_bf16.h>
#include <math.h>
#include <stdint.h>

#define BATCH 4
#define SEQ   1024
#define DMODEL 1024
#define NHEAD 16
#define NLAYER 4
#define VOCAB 32000
#define DHEAD 64
#define NTOK (BATCH*SEQ)   // 4096

// SW128 swizzle (Swizzle<3,4,3>)
#define SWZ(b) ((b) ^ ((((unsigned)(b)) >> 3) & 0x70u))

// ---------------------------------------------------------------------------
// PTX helpers (portable: sm_80+ PTX, runs on sm_103a)
// ---------------------------------------------------------------------------
__device__ __forceinline__ uint32_t smem_u32(const void* p) {
    uint32_t a;
    asm("{ .reg .u64 t; cvta.to.shared.u64 t, %1; cvt.u32.u64 %0, t; }" : "=r"(a) : "l"(p));
    return a;
}
__device__ __forceinline__ void cp16(uint32_t dst, const void* src) {
    asm volatile("cp.async.cg.shared.global [%0], [%1], 16;" :: "r"(dst), "l"(src));
}
#define CP_COMMIT() asm volatile("cp.async.commit_group;" ::: "memory")
#define CP_WAIT(n)  asm volatile("cp.async.wait_group %0;" :: "n"(n) : "memory")

#define LDSM4(r, addr) \
    asm volatile("ldmatrix.sync.aligned.m8n8.x4.shared.b16 {%0,%1,%2,%3}, [%4];" \
        : "=r"((r)[0]), "=r"((r)[1]), "=r"((r)[2]), "=r"((r)[3]) : "r"(addr))

#define MMA16816(d, a, b0, b1) \
    asm volatile("mma.sync.aligned.m16n8k16.row.col.f32.bf16.bf16.f32 " \
        "{%0,%1,%2,%3}, {%4,%5,%6,%7}, {%8,%9}, {%0,%1,%2,%3};" \
        : "+f"((d)[0]), "+f"((d)[1]), "+f"((d)[2]), "+f"((d)[3]) \
        : "r"((a)[0]), "r"((a)[1]), "r"((a)[2]), "r"((a)[3]), "r"(b0), "r"(b1))

__device__ __forceinline__ void pack2(float v0, float v1, uint32_t& hi, uint32_t& lo) {
    __nv_bfloat16 h0 = __float2bfloat16(v0);
    __nv_bfloat16 l0 = __float2bfloat16(v0 - __bfloat162float(h0));
    __nv_bfloat16 h1 = __float2bfloat16(v1);
    __nv_bfloat16 l1 = __float2bfloat16(v1 - __bfloat162float(h1));
    hi = (uint32_t)__bfloat16_as_ushort(h0) | ((uint32_t)__bfloat16_as_ushort(h1) << 16);
    lo = (uint32_t)__bfloat16_as_ushort(l0) | ((uint32_t)__bfloat16_as_ushort(l1) << 16);
}

// ---------------------------------------------------------------------------
// scratch (device globals)
// ---------------------------------------------------------------------------
__device__ float g_x  [NTOK*DMODEL];
__device__ __nv_bfloat16 g_hn_hi[NTOK*DMODEL];
__device__ __nv_bfloat16 g_hn_lo[NTOK*DMODEL];
__device__ __nv_bfloat16 g_y_hi [NTOK*DMODEL];
__device__ __nv_bfloat16 g_y_lo [NTOK*DMODEL];
__device__ __nv_bfloat16 g_mlp_hi[NTOK*4*DMODEL];
__device__ __nv_bfloat16 g_mlp_lo[NTOK*4*DMODEL];
// attention operand tiles: Q @0, K @QS1, VT @2*QS1 (each 64bh x 16 tiles x 4096)
#define QS1 4194304ull
__device__ __nv_bfloat16 g_qkvt_hi[3*QS1];
__device__ __nv_bfloat16 g_qkvt_lo[3*QS1];
// weights, transposed [N,K] + swizzled tile format, hi/lo split
#define WTOTAL 83099648ull   // 4*12*MDD + 1024*32000
#define LWq 12582912ull
#define MDDq 1048576ull
__device__ __nv_bfloat16 g_w_hi[WTOTAL];
__device__ __nv_bfloat16 g_w_lo[WTOTAL];

// ---------------------------------------------------------------------------
// single-launch weight convert: all weights -> hi/lo bf16 [N,K] swizzled tiles
// ---------------------------------------------------------------------------
__global__ __launch_bounds__(256)
void convert_all(const float* __restrict__ Wq, const float* __restrict__ Wk,
                 const float* __restrict__ Wv, const float* __restrict__ Wp,
                 const float* __restrict__ W1, const float* __restrict__ W2,
                 const float* __restrict__ Whead,
                 __nv_bfloat16* __restrict__ wh, __nv_bfloat16* __restrict__ wl)
{
    int bid = blockIdx.x;
    const float* W; int N, kc, nt;
    size_t dstBlk;
    if (bid < 6144) {
        int l = bid / 1536, r = bid % 1536;
        size_t wb = (size_t)l * LWq;
        if (r < 384) {                       // fused QKV
            int nt_f = r >> 4; kc = r & 15;
            int sel = nt_f >> 3; nt = nt_f & 7;
            W = (sel == 0 ? Wq : (sel == 1 ? Wk : Wv)) + (size_t)l*DMODEL*DMODEL;
            N = 1024;
            dstBlk = wb + ((size_t)nt_f*16 + kc)*8192;
        } else if (r < 512) {                // proj
            int i = r - 384; nt = i >> 4; kc = i & 15;
            W = Wp + (size_t)l*DMODEL*DMODEL; N = 1024;
            dstBlk = wb + 3*MDDq + ((size_t)nt*16 + kc)*8192;
        } else if (r < 1024) {               // W1 [1024 -> 4096]
            int i = r - 512; nt = i >> 4; kc = i & 15;
            W = W1 + (size_t)l*DMODEL*4*DMODEL; N = 4096;
            dstBlk = wb + 4*MDDq + ((size_t)nt*16 + kc)*8192;
        } else {                             // W2 [4096 -> 1024]
            int i = r - 1024; nt = i >> 6; kc = i & 63;
            W = W2 + (size_t)l*DMODEL*4*DMODEL; N = 1024;
            dstBlk = wb + 8*MDDq + ((size_t)nt*64 + kc)*8192;
        }
    } else {                                 // head [1024 -> 32000]
        int i = bid - 6144; nt = i >> 4; kc = i & 15;
        W = Whead; N = 32000;
        dstBlk = 4*LWq + ((size_t)nt*16 + kc)*8192;
    }

    int t = threadIdx.x;
    int n_loc = t & 127, grp = t >> 7;
    uint4* hi4 = (uint4*)(wh + dstBlk);
    uint4* lo4 = (uint4*)(wl + dstBlk);
    #pragma unroll
    for (int g = 0; g < 4; g++) {
        int kg = grp + g*2;
        int k0 = kc*64 + kg*8;
        unsigned hs[8], ls[8];
        #pragma unroll
        for (int i = 0; i < 8; i++) {
            float v = W[(size_t)(k0 + i) * N + nt*128 + n_loc];
            __nv_bfloat16 h = __float2bfloat16(v);
            __nv_bfloat16 l = __float2bfloat16(v - __bfloat162float(h));
            hs[i] = __bfloat16_as_ushort(h);
            ls[i] = __bfloat16_as_ushort(l);
        }
        uint4 uh, ul;
        uh.x = hs[0] | (hs[1] << 16); uh.y = hs[2] | (hs[3] << 16);
        uh.z = hs[4] | (hs[5] << 16); uh.w = hs[6] | (hs[7] << 16);
        ul.x = ls[0] | (ls[1] << 16); ul.y = ls[2] | (ls[3] << 16);
        ul.z = ls[4] | (ls[5] << 16); ul.w = ls[6] | (ls[7] << 16);
        uint32_t bo = SWZ((uint32_t)n_loc*128 + (uint32_t)kg*16);
        hi4[bo >> 4] = uh;
        lo4[bo >> 4] = ul;
    }
}

// ---------------------------------------------------------------------------
// embed (fp32 residual stream)
// ---------------------------------------------------------------------------
__global__ __launch_bounds__(256)
void embed_kernel(const float* __restrict__ states, const int* __restrict__ timesteps,
                  const float* __restrict__ w1, const float* __restrict__ b1,
                  const float* __restrict__ w2, const float* __restrict__ b2,
                  const float* __restrict__ w3, const float* __restrict__ b3,
                  const float* __restrict__ pos_emb, const float* __restrict__ gpe,
                  float* __restrict__ x)
{
    int token = blockIdx.x;
    int b = token / SEQ, s = token % SEQ;
    __shared__ float st[4], h1[16], h2[16];
    int tid = threadIdx.x;
    if (tid < 4) st[tid] = states[token*4 + tid];
    __syncthreads();
    if (tid < 16) {
        float a = b1[tid];
        #pragma unroll
        for (int i = 0; i < 4; i++) a += st[i] * w1[i*16 + tid];
        h1[tid] = fmaxf(a, 0.0f);
    }
    __syncthreads();
    if (tid < 16) {
        float a = b2[tid];
        #pragma unroll
        for (int i = 0; i < 16; i++) a += h1[i] * w2[i*16 + tid];
        h2[tid] = fmaxf(a, 0.0f);
    }
    __syncthreads();
    int t = timesteps[b];
    for (int d = tid; d < DMODEL; d += blockDim.x) {
        float a = b3[d];
        #pragma unroll
        for (int i = 0; i < 16; i++) a += h2[i] * w3[i*DMODEL + d];
        x[(size_t)token*DMODEL + d] = tanhf(a) + gpe[(size_t)t*DMODEL + d]
                                      + pos_emb[(size_t)s*DMODEL + d];
    }
}

// ---------------------------------------------------------------------------
// layernorm: fp32 in -> bf16 hi/lo swizzled A-tiles (K=1024)
// ---------------------------------------------------------------------------
__global__ __launch_bounds__(256)
void ln_hilo_kernel(const float* __restrict__ X,
                    const float* __restrict__ g, const float* __restrict__ b,
                    __nv_bfloat16* __restrict__ ohi, __nv_bfloat16* __restrict__ olo)
{
    int row = blockIdx.x;
    const float* xr = X + (size_t)row*DMODEL;
    int tid = threadIdx.x;
    float4 v = *(const float4*)(xr + tid*4);
    float s = v.x+v.y+v.z+v.w;
    float sq = v.x*v.x + v.y*v.y + v.z*v.z + v.w*v.w;
    __shared__ float rs[8], rq[8];
    #pragma unroll
    for (int off = 16; off; off >>= 1) {
        s  += __shfl_xor_sync(0xffffffffu, s,  off);
        sq += __shfl_xor_sync(0xffffffffu, sq, off);
    }
    if ((tid & 31) == 0) { rs[tid>>5] = s; rq[tid>>5] = sq; }
    __syncthreads();
    if (tid < 32) {
        s  = (tid < 8) ? rs[tid] : 0.f;
        sq = (tid < 8) ? rq[tid] : 0.f;
        #pragma unroll
        for (int off = 4; off; off >>= 1) {
            s  += __shfl_xor_sync(0xffffffffu, s,  off);
            sq += __shfl_xor_sync(0xffffffffu, sq, off);
        }
        if (tid == 0) { rs[0] = s; rq[0] = sq; }
    }
    __syncthreads();
    float mu  = rs[0] * (1.0f/DMODEL);
    float var = rq[0] * (1.0f/DMODEL) - mu*mu;
    float r   = rsqrtf(var + 1e-5f);
    int k0 = tid*4;
    float o[4] = {v.x, v.y, v.z, v.w};
    unsigned hs[4], ls[4];
    #pragma unroll
    for (int i = 0; i < 4; i++) {
        int c = k0 + i;
        float val = (o[i] - mu) * r * g[c] + b[c];
        __nv_bfloat16 h = __float2bfloat16(val);
        __nv_bfloat16 l = __float2bfloat16(val - __bfloat162float(h));
        hs[i] = __bfloat16_as_ushort(h);
        ls[i] = __bfloat16_as_ushort(l);
    }
    int kc = k0 >> 6, c = k0 & 63;
    size_t tb = ((size_t)(row >> 7) * 16 + kc) * 8192;
    uint32_t bo = SWZ((uint32_t)(row & 127)*128 + (uint32_t)c*2);
    uint2 uh = { hs[0] | (hs[1] << 16), hs[2] | (hs[3] << 16) };
    uint2 ul = { ls[0] | (ls[1] << 16), ls[2] | (ls[3] << 16) };
    *(uint2*)((char*)(ohi + tb) + bo) = uh;
    *(uint2*)((char*)(olo + tb) + bo) = ul;
}

// ---------------------------------------------------------------------------
// mma.sync GEMM, 3-stage cp.async pipeline, split-term-outer MMA order.
// 512 threads = 16 warps (4x4), warp tile 32x32.
// mode 0: C fp32   2: C fp32 +bias +resid   3: gelu(+bias)->Ohi/Olo (A tiles)
// mode 4: QKV -> attention tiles: Q/K [row][d], V transposed [d][key], hi/lo
// ---------------------------------------------------------------------------
#define GEMM_SMEM 196608

__global__ __launch_bounds__(512, 1)
void gemm_mma(const uint4* __restrict__ Ahi, const uint4* __restrict__ Alo,
              const uint4* __restrict__ Bhi, const uint4* __restrict__ Blo,
              const float* __restrict__ bias, const float* __restrict__ resid,
              float* __restrict__ Cf,
              __nv_bfloat16* __restrict__ Ohi, __nv_bfloat16* __restrict__ Olo,
              int N, int K, int mode)
{
    extern __shared__ char sb[];
    uint32_t sbase = smem_u32(sb);
    int tid = threadIdx.x, wid = tid >> 5, lane = tid & 31;
    int nt = blockIdx.x, mt = blockIdx.y;
    int NC = K >> 6;
    int wm = wid & 3, wn = wid >> 2;

    const uint4* gA0h = Ahi + (size_t)mt * NC * 1024;
    const uint4* gA0l = Alo + (size_t)mt * NC * 1024;
    const uint4* gB0h = Bhi + (size_t)nt * NC * 1024;
    const uint4* gB0l = Blo + (size_t)nt * NC * 1024;

    float acc[2][4][4];
    #pragma unroll
    for (int i = 0; i < 2; i++)
        #pragma unroll
        for (int j = 0; j < 4; j++)
            #pragma unroll
            for (int q = 0; q < 4; q++) acc[i][j][q] = 0.f;

    auto load_chunk = [&](int c, int s) {
        uint32_t sA = sbase + s*65536;
        const uint4* ah = gA0h + (size_t)c*1024;
        const uint4* al = gA0l + (size_t)c*1024;
        const uint4* bh = gB0h + (size_t)c*1024;
        const uint4* bl = gB0l + (size_t)c*1024;
        #pragma unroll
        for (int i = 0; i < 2; i++) {
            int idx = tid + i*512;
            cp16(sA +         idx*16, ah + idx);
            cp16(sA + 16384 + idx*16, al + idx);
            cp16(sA + 32768 + idx*16, bh + idx);
            cp16(sA + 49152 + idx*16, bl + idx);
        }
    };

    load_chunk(0, 0);
    CP_COMMIT();
    if (NC > 1) { load_chunk(1, 1); CP_COMMIT(); }

    int lrow = lane & 15;
    int lkc8 = (lane >> 4) * 8;

    for (int c = 0; c < NC; c++) {
        int s = c % 3;
        if (c + 2 < NC) {
            load_chunk(c + 2, (c + 2) % 3);
            CP_COMMIT();
            CP_WAIT(2);
        } else if (c + 1 < NC) {
            CP_WAIT(1);
        } else {
            CP_WAIT(0);
        }
        __syncthreads();

        uint32_t sAh = sbase + s*65536;
        uint32_t sAl = sAh + 16384;
        uint32_t sBh = sAh + 32768;
        uint32_t sBl = sAh + 49152;

        #pragma unroll
        for (int ks = 0; ks < 4; ks++) {
            int k0 = ks*16;
            uint32_t ah[2][4], al[2][4];
            #pragma unroll
            for (int tm = 0; tm < 2; tm++) {
                uint32_t off = SWZ((uint32_t)(wm*32 + tm*16 + lrow)*128
                                   + (uint32_t)(k0 + lkc8)*2);
                LDSM4(ah[tm], sAh + off);
                LDSM4(al[tm], sAl + off);
            }
            uint32_t bh[2][4], bl[2][4];
            #pragma unroll
            for (int g = 0; g < 2; g++) {
                uint32_t off = SWZ((uint32_t)(wn*32 + g*16 + lrow)*128
                                   + (uint32_t)(k0 + lkc8)*2);
                LDSM4(bh[g], sBh + off);
                LDSM4(bl[g], sBl + off);
            }
            #pragma unroll
            for (int tm = 0; tm < 2; tm++)
                #pragma unroll
                for (int g = 0; g < 2; g++) {
                    MMA16816(acc[tm][2*g  ], ah[tm], bh[g][0], bh[g][2]);
                    MMA16816(acc[tm][2*g+1], ah[tm], bh[g][1], bh[g][3]);
                }
            #pragma unroll
            for (int tm = 0; tm < 2; tm++)
                #pragma unroll
                for (int g = 0; g < 2; g++) {
                    MMA16816(acc[tm][2*g  ], ah[tm], bl[g][0], bl[g][2]);
                    MMA16816(acc[tm][2*g+1], ah[tm], bl[g][1], bl[g][3]);
                }
            #pragma unroll
            for (int tm = 0; tm < 2; tm++)
                #pragma unroll
                for (int g = 0; g < 2; g++) {
                    MMA16816(acc[tm][2*g  ], al[tm], bh[g][0], bh[g][2]);
                    MMA16816(acc[tm][2*g+1], al[tm], bh[g][1], bh[g][3]);
                }
        }
    }

    // ---- epilogue ----
    int gr = lane >> 2, gc = lane & 3;
    #pragma unroll
    for (int tm = 0; tm < 2; tm++) {
        #pragma unroll
        for (int tn = 0; tn < 4; tn++) {
            float* a = acc[tm][tn];
            int rIn0 = wm*32 + tm*16 + gr;
            int col  = nt*128 + wn*32 + tn*8 + gc*2;
            if (mode == 3) {
                int kc = col >> 6, cc = col & 63;
                size_t tb = ((size_t)mt * (N >> 6) + kc) * 8192;
                #pragma unroll
                for (int hhalf = 0; hhalf < 2; hhalf++) {
                    int rIn = rIn0 + hhalf*8;
                    float v0 = a[hhalf*2]     + bias[col];
                    float v1 = a[hhalf*2 + 1] + bias[col + 1];
                    v0 = 0.5f * v0 * (1.0f + erff(v0 * 0.70710678118654752f));
                    v1 = 0.5f * v1 * (1.0f + erff(v1 * 0.70710678118654752f));
                    uint32_t uh, ul;
                    pack2(v0, v1, uh, ul);
                    uint32_t bo = SWZ((uint32_t)rIn*128 + (uint32_t)cc*2);
                    *(uint32_t*)((char*)(Ohi + tb) + bo) = uh;
                    *(uint32_t*)((char*)(Olo + tb) + bo) = ul;
                }
            } else if (mode == 4) {
                int sect = col >> 10;          // 0=Q, 1=K, 2=V
                int df   = col & 1023;
                int hh2  = df >> 6;            // head
                int cc   = df & 63;            // d within head
                #pragma unroll
                for (int hhalf = 0; hhalf < 2; hhalf++) {
                    int row = mt*128 + rIn0 + hhalf*8;     // token
                    int bq = row >> 10;
                    int tt = (row >> 6) & 15;              // tile index
                    int r  = row & 63;                     // row within tile
                    int bh = bq*NHEAD + hh2;
                    size_t tbase = (size_t)sect * QS1 + ((size_t)(bh*16 + tt))*4096;
                    float v0 = a[hhalf*2], v1 = a[hhalf*2 + 1];
                    uint32_t uh, ul;
                    pack2(v0, v1, uh, ul);
                    if (sect < 2) {
                        uint32_t bo = SWZ((uint32_t)r*128 + (uint32_t)cc*2);
                        *(uint32_t*)((char*)(Ohi + tbase) + bo) = uh;
                        *(uint32_t*)((char*)(Olo + tbase) + bo) = ul;
                    } else {
                        // V transposed: tile row = d (cc), col = key (r)
                        uint32_t bo0 = SWZ((uint32_t)cc*128 + (uint32_t)r*2);
                        uint32_t bo1 = SWZ((uint32_t)(cc+1)*128 + (uint32_t)r*2);
                        *(uint16_t*)((char*)(Ohi + tbase) + bo0) = (uint16_t)(uh & 0xffff);
                        *(uint16_t*)((char*)(Ohi + tbase) + bo1) = (uint16_t)(uh >> 16);
                        *(uint16_t*)((char*)(Olo + tbase) + bo0) = (uint16_t)(ul & 0xffff);
                        *(uint16_t*)((char*)(Olo + tbase) + bo1) = (uint16_t)(ul >> 16);
                    }
                }
            } else {
                #pragma unroll
                for (int hhalf = 0; hhalf < 2; hhalf++) {
                    int row = mt*128 + rIn0 + hhalf*8;
                    float v0 = a[hhalf*2], v1 = a[hhalf*2 + 1];
                    if (mode == 2) {
                        v0 += bias[col]     + resid[(size_t)row*N + col];
                        v1 += bias[col + 1] + resid[(size_t)row*N + col + 1];
                    }
                    float2 o = {v0, v1};
                    *(float2*)(Cf + (size_t)row*N + col) = o;
                }
            }
        }
    }
}

// ---------------------------------------------------------------------------
// mma.sync causal flash attention. 128 thr (4 warps), 64x64 tiles.
// Inputs: bf16 hi/lo tiles (Q/K [row][d], VT [d][key]) from QKV mode-4 epilogue.
// Output: bf16 hi/lo swizzled A-tiles for proj (K=1024, kc == head).
// smem: Qh 8K | Ql 8K | 2 stages x (Kh,Kl,Vh,Vl 8K each) = 80KB
// ---------------------------------------------------------------------------
#define ATTN_SMEM 81920

__global__ __launch_bounds__(128)
void attn_mma(const __nv_bfloat16* __restrict__ qkvt_hi,
              const __nv_bfloat16* __restrict__ qkvt_lo,
              __nv_bfloat16* __restrict__ yhi, __nv_bfloat16* __restrict__ ylo)
{
    extern __shared__ char sb[];
    uint32_t sbase = smem_u32(sb);
    int qt = blockIdx.x, h = blockIdx.y, b = blockIdx.z;
    int tid = threadIdx.x, w = tid >> 5, lane = tid & 31;
    int bh = b*NHEAD + h;
    int lrow = lane & 15, lkc8 = (lane >> 4) * 8;
    int gr = lane >> 2, gc = lane & 3;

    // load Q tiles
    {
        const uint4* gQh = (const uint4*)(qkvt_hi + ((size_t)(bh*16 + qt))*4096);
        const uint4* gQl = (const uint4*)(qkvt_lo + ((size_t)(bh*16 + qt))*4096);
        #pragma unroll
        for (int i = 0; i < 4; i++) {
            int idx = tid + i*128;
            cp16(sbase +        idx*16, gQh + idx);
            cp16(sbase + 8192 + idx*16, gQl + idx);
        }
    }
    CP_COMMIT();

    auto load_kv = [&](int kt, int s) {
        uint32_t st = sbase + 16384 + s*32768;
        size_t toff = (size_t)(bh*16 + kt)*4096;
        const uint4* kh = (const uint4*)(qkvt_hi +   QS1 + toff);
        const uint4* kl = (const uint4*)(qkvt_lo +   QS1 + toff);
        const uint4* vh = (const uint4*)(qkvt_hi + 2*QS1 + toff);
        const uint4* vl = (const uint4*)(qkvt_lo + 2*QS1 + toff);
        #pragma unroll
        for (int i = 0; i < 4; i++) {
            int idx = tid + i*128;
            cp16(st +         idx*16, kh + idx);
            cp16(st +  8192 + idx*16, kl + idx);
            cp16(st + 16384 + idx*16, vh + idx);
            cp16(st + 24576 + idx*16, vl + idx);
        }
    };
    load_kv(0, 0);
    CP_COMMIT();
    CP_WAIT(0);
    __syncthreads();

    // Q fragments (held for whole kernel)
    uint32_t qh[4][4], ql[4][4];
    #pragma unroll
    for (int kk = 0; kk < 4; kk++) {
        uint32_t off = SWZ((uint32_t)(w*16 + lrow)*128 + (uint32_t)(kk*16 + lkc8)*2);
        LDSM4(qh[kk], sbase + off);
        LDSM4(ql[kk], sbase + 8192 + off);
    }

    float oAcc[8][4];
    #pragma unroll
    for (int j = 0; j < 8; j++)
        #pragma unroll
        for (int q4 = 0; q4 < 4; q4++) oAcc[j][q4] = 0.f;
    float m0 = -1e30f, m1 = -1e30f, l0 = 0.f, l1 = 0.f;

    int qrow0 = qt*64 + w*16 + gr, qrow1 = qrow0 + 8;

    for (int kt = 0; kt <= qt; kt++) {
        int s = kt & 1;
        if (kt + 1 <= qt) {
            load_kv(kt + 1, (kt + 1) & 1);
            CP_COMMIT();
            CP_WAIT(1);
        } else {
            CP_WAIT(0);
        }
        __syncthreads();
        uint32_t sK = sbase + 16384 + s*32768;

        // S = Q K^T (3-term split), fp32 accum
        float sAcc[8][4];
        #pragma unroll
        for (int j = 0; j < 8; j++)
            #pragma unroll
            for (int q4 = 0; q4 < 4; q4++) sAcc[j][q4] = 0.f;

        #pragma unroll
        for (int kk = 0; kk < 4; kk++) {
            #pragma unroll
            for (int g = 0; g < 4; g++) {
                uint32_t off = SWZ((uint32_t)(g*16 + lrow)*128 + (uint32_t)(kk*16 + lkc8)*2);
                uint32_t kh4[4], kl4[4];
                LDSM4(kh4, sK + off);
                LDSM4(kl4, sK + 8192 + off);
                MMA16816(sAcc[2*g  ], qh[kk], kh4[0], kh4[2]);
                MMA16816(sAcc[2*g+1], qh[kk], kh4[1], kh4[3]);
                MMA16816(sAcc[2*g  ], qh[kk], kl4[0], kl4[2]);
                MMA16816(sAcc[2*g+1], qh[kk], kl4[1], kl4[3]);
                MMA16816(sAcc[2*g  ], ql[kk], kh4[0], kh4[2]);
                MMA16816(sAcc[2*g+1], ql[kk], kh4[1], kh4[3]);
            }
        }

        // scale + causal mask (diag tile only)
        bool diag = (kt == qt);
        #pragma unroll
        for (int j = 0; j < 8; j++) {
            #pragma unroll
            for (int q4 = 0; q4 < 4; q4++) sAcc[j][q4] *= 0.125f;
            if (diag) {
                int key0 = kt*64 + j*8 + gc*2;
                if (key0     > qrow0) sAcc[j][0] = -1e30f;
                if (key0 + 1 > qrow0) sAcc[j][1] = -1e30f;
                if (key0     > qrow1) sAcc[j][2] = -1e30f;
                if (key0 + 1 > qrow1) sAcc[j][3] = -1e30f;
            }
        }

        // row max (4 lanes per row)
        float rm0 = -1e30f, rm1 = -1e30f;
        #pragma unroll
        for (int j = 0; j < 8; j++) {
            rm0 = fmaxf(rm0, fmaxf(sAcc[j][0], sAcc[j][1]));
            rm1 = fmaxf(rm1, fmaxf(sAcc[j][2], sAcc[j][3]));
        }
        rm0 = fmaxf(rm0, __shfl_xor_sync(0xffffffffu, rm0, 1));
        rm0 = fmaxf(rm0, __shfl_xor_sync(0xffffffffu, rm0, 2));
        rm1 = fmaxf(rm1, __shfl_xor_sync(0xffffffffu, rm1, 1));
        rm1 = fmaxf(rm1, __shfl_xor_sync(0xffffffffu, rm1, 2));

        float mn0 = fmaxf(m0, rm0), mn1 = fmaxf(m1, rm1);
        float al0 = __expf(m0 - mn0), al1 = __expf(m1 - mn1);

        float ps0 = 0.f, ps1 = 0.f;
        #pragma unroll
        for (int j = 0; j < 8; j++) {
            sAcc[j][0] = __expf(sAcc[j][0] - mn0);
            sAcc[j][1] = __expf(sAcc[j][1] - mn0);
            sAcc[j][2] = __expf(sAcc[j][2] - mn1);
            sAcc[j][3] = __expf(sAcc[j][3] - mn1);
            ps0 += sAcc[j][0] + sAcc[j][1];
            ps1 += sAcc[j][2] + sAcc[j][3];
        }
        ps0 += __shfl_xor_sync(0xffffffffu, ps0, 1);
        ps0 += __shfl_xor_sync(0xffffffffu, ps0, 2);
        ps1 += __shfl_xor_sync(0xffffffffu, ps1, 1);
        ps1 += __shfl_xor_sync(0xffffffffu, ps1, 2);

        l0 = l0*al0 + ps0;  l1 = l1*al1 + ps1;
        m0 = mn0;           m1 = mn1;
        #pragma unroll
        for (int j = 0; j < 8; j++) {
            oAcc[j][0] *= al0; oAcc[j][1] *= al0;
            oAcc[j][2] *= al1; oAcc[j][3] *= al1;
        }

        // O += P V  (P c-frags -> a-frags, 3-term split)
        #pragma unroll
        for (int kk2 = 0; kk2 < 4; kk2++) {
            uint32_t ph[4], pl[4];
            pack2(sAcc[2*kk2  ][0], sAcc[2*kk2  ][1], ph[0], pl[0]);
            pack2(sAcc[2*kk2  ][2], sAcc[2*kk2  ][3], ph[1], pl[1]);
            pack2(sAcc[2*kk2+1][0], sAcc[2*kk2+1][1], ph[2], pl[2]);
            pack2(sAcc[2*kk2+1][2], sAcc[2*kk2+1][3], ph[3], pl[3]);
            #pragma unroll
            for (int g = 0; g < 4; g++) {
                uint32_t off = SWZ((uint32_t)(g*16 + lrow)*128 + (uint32_t)(kk2*16 + lkc8)*2);
                uint32_t vh4[4], vl4[4];
                LDSM4(vh4, sK + 16384 + off);
                LDSM4(vl4, sK + 24576 + off);
                MMA16816(oAcc[2*g  ], ph, vh4[0], vh4[2]);
                MMA16816(oAcc[2*g+1], ph, vh4[1], vh4[3]);
                MMA16816(oAcc[2*g  ], ph, vl4[0], vl4[2]);
                MMA16816(oAcc[2*g+1], ph, vl4[1], vl4[3]);
                MMA16816(oAcc[2*g  ], pl, vh4[0], vh4[2]);
                MMA16816(oAcc[2*g+1], pl, vh4[1], vh4[3]);
            }
        }
        __syncthreads();   // all warps done with stage s before it is reloaded
    }

    // epilogue: y = O / l  -> hi/lo swizzled A-tiles (kc == h)
    float inv0 = 1.0f / l0, inv1 = 1.0f / l1;
    int mtok0 = b*SEQ + qt*64 + w*16 + gr;
    size_t tb = ((size_t)(mtok0 >> 7) * 16 + h) * 8192;
    #pragma unroll
    for (int g = 0; g < 8; g++) {
        int cc = g*8 + gc*2;
        uint32_t uh0, ul0, uh1, ul1;
        pack2(oAcc[g][0]*inv0, oAcc[g][1]*inv0, uh0, ul0);
        pack2(oAcc[g][2]*inv1, oAcc[g][3]*inv1, uh1, ul1);
        uint32_t bo0 = SWZ((uint32_t)(mtok0 & 127)*128 + (uint32_t)cc*2);
        uint32_t bo1 = SWZ((uint32_t)((mtok0 + 8) & 127)*128 + (uint32_t)cc*2);
        *(uint32_t*)((char*)(yhi + tb) + bo0) = uh0;
        *(uint32_t*)((char*)(ylo + tb) + bo0) = ul0;
        *(uint32_t*)((char*)(yhi + tb) + bo1) = uh1;
        *(uint32_t*)((char*)(ylo + tb) + bo1) = ul1;
    }
}

// ---------------------------------------------------------------------------
// launch
// ---------------------------------------------------------------------------
extern "C" void kernel_launch(void* const* d_in, const int* in_sizes, int n_in,
                              void* d_out, int out_size)
{
    const float* states     = (const float*)d_in[0];
    const int*   timesteps  = (const int*)  d_in[1];
    const float* se_w1 = (const float*)d_in[2];
    const float* se_b1 = (const float*)d_in[3];
    const float* se_w2 = (const float*)d_in[4];
    const float* se_b2 = (const float*)d_in[5];
    const float* se_w3 = (const float*)d_in[6];
    const float* se_b3 = (const float*)d_in[7];
    const float* pos_emb = (const float*)d_in[8];
    const float* gpe     = (const float*)d_in[9];
    const float* ln1_g = (const float*)d_in[10];
    const float* ln1_b = (const float*)d_in[11];
    const float* Wq = (const float*)d_in[12];
    const float* Wk = (const float*)d_in[13];
    const float* Wv = (const float*)d_in[14];
    const float* Wp = (const float*)d_in[15];
    const float* bp = (const float*)d_in[16];
    const float* ln2_g = (const float*)d_in[17];
    const float* ln2_b = (const float*)d_in[18];
    const float* W1 = (const float*)d_in[19];
    const float* b1 = (const float*)d_in[20];
    const float* W2 = (const float*)d_in[21];
    const float* b2 = (const float*)d_in[22];
    const float* lnf_g = (const float*)d_in[23];
    const float* lnf_b = (const float*)d_in[24];
    const float* head_w = (const float*)d_in[25];

    float *x;
    __nv_bfloat16 *hnh, *hnl, *yh, *yl, *mh, *ml, *wh, *wl, *qth, *qtl;
    cudaGetSymbolAddress((void**)&x,   g_x);
    cudaGetSymbolAddress((void**)&hnh, g_hn_hi);
    cudaGetSymbolAddress((void**)&hnl, g_hn_lo);
    cudaGetSymbolAddress((void**)&yh,  g_y_hi);
    cudaGetSymbolAddress((void**)&yl,  g_y_lo);
    cudaGetSymbolAddress((void**)&mh,  g_mlp_hi);
    cudaGetSymbolAddress((void**)&ml,  g_mlp_lo);
    cudaGetSymbolAddress((void**)&wh,  g_w_hi);
    cudaGetSymbolAddress((void**)&wl,  g_w_lo);
    cudaGetSymbolAddress((void**)&qth, g_qkvt_hi);
    cudaGetSymbolAddress((void**)&qtl, g_qkvt_lo);

    cudaFuncSetAttribute(gemm_mma, cudaFuncAttributeMaxDynamicSharedMemorySize, GEMM_SMEM);
    cudaFuncSetAttribute(attn_mma, cudaFuncAttributeMaxDynamicSharedMemorySize, ATTN_SMEM);

    convert_all<<<10144, 256>>>(Wq, Wk, Wv, Wp, W1, W2, head_w, wh, wl);
    embed_kernel<<<NTOK, 256>>>(states, timesteps, se_w1, se_b1, se_w2, se_b2,
                                se_w3, se_b3, pos_emb, gpe, x);

    const size_t LW = LWq, MDD = MDDq;
    dim3 gQKV(24, 32), gDD(8, 32), gD4(32, 32), gHead(250, 32);
    dim3 gAttn(SEQ/64, NHEAD, BATCH);

    for (int l = 0; l < NLAYER; l++) {
        size_t wb = (size_t)l * LW;
        ln_hilo_kernel<<<NTOK, 256>>>(x, ln1_g + l*DMODEL, ln1_b + l*DMODEL, hnh, hnl);
        // fused QKV GEMM -> attention tiles (mode 4)
        gemm_mma<<<gQKV, 512, GEMM_SMEM>>>((uint4*)hnh, (uint4*)hnl,
            (uint4*)(wh + wb), (uint4*)(wl + wb),
            nullptr, nullptr, nullptr, qth, qtl, 3*DMODEL, 1024, 4);
        attn_mma<<<gAttn, 128, ATTN_SMEM>>>(qth, qtl, yh, yl);
        // proj GEMM
        gemm_mma<<<gDD, 512, GEMM_SMEM>>>((uint4*)yh, (uint4*)yl,
            (uint4*)(wh + wb + 3*MDD), (uint4*)(wl + wb + 3*MDD),
            bp + l*DMODEL, x, x, nullptr, nullptr, 1024, 1024, 2);
        ln_hilo_kernel<<<NTOK, 256>>>(x, ln2_g + l*DMODEL, ln2_b + l*DMODEL, hnh, hnl);
        gemm_mma<<<gD4, 512, GEMM_SMEM>>>((uint4*)hnh, (uint4*)hnl,
            (uint4*)(wh + wb + 4*MDD), (uint4*)(wl + wb + 4*MDD),
            b1 + (size_t)l*4*DMODEL, nullptr, nullptr, mh, ml, 4096, 1024, 3);
        gemm_mma<<<gDD, 512, GEMM_SMEM>>>((uint4*)mh, (uint4*)ml,
            (uint4*)(wh + wb + 8*MDD), (uint4*)(wl + wb + 8*MDD),
            b2 + l*DMODEL, x, x, nullptr, nullptr, 1024, 4096, 2);
    }

    ln_hilo_kernel<<<NTOK, 256>>>(x, lnf_g, lnf_b, hnh, hnl);
    gemm_mma<<<gHead, 512, GEMM_SMEM>>>((uint4*)hnh, (uint4*)hnl,
        (uint4*)(wh + 4*LW), (uint4*)(wl + 4*LW),
        nullptr, nullptr, (float*)d_out, nullptr, nullptr, 32000, 1024, 0);
}

// round 15
// speedup vs baseline: 3.6446x; 1.1030x over previous
#include <cuda_runtime.h>
#include <cuda_bf16.h>
#include <cuda_fp16.h>
#include <math.h>
#include <stdint.h>

#define BATCH 4
#define SEQ   1024
#define DMODEL 1024
#define NHEAD 16
#define NLAYER 4
#define VOCAB 32000
#define DHEAD 64
#define NTOK (BATCH*SEQ)   // 4096

// SW128 swizzle (Swizzle<3,4,3>)
#define SWZ(b) ((b) ^ ((((unsigned)(b)) >> 3) & 0x70u))

// ---------------------------------------------------------------------------
// PTX helpers (portable: sm_80+ PTX, runs on sm_103a)
// ---------------------------------------------------------------------------
__device__ __forceinline__ uint32_t smem_u32(const void* p) {
    uint32_t a;
    asm("{ .reg .u64 t; cvta.to.shared.u64 t, %1; cvt.u32.u64 %0, t; }" : "=r"(a) : "l"(p));
    return a;
}
__device__ __forceinline__ void cp16(uint32_t dst, const void* src) {
    asm volatile("cp.async.cg.shared.global [%0], [%1], 16;" :: "r"(dst), "l"(src));
}
#define CP_COMMIT() asm volatile("cp.async.commit_group;" ::: "memory")
#define CP_WAIT(n)  asm volatile("cp.async.wait_group %0;" :: "n"(n) : "memory")

#define LDSM4(r, addr) \
    asm volatile("ldmatrix.sync.aligned.m8n8.x4.shared.b16 {%0,%1,%2,%3}, [%4];" \
        : "=r"((r)[0]), "=r"((r)[1]), "=r"((r)[2]), "=r"((r)[3]) : "r"(addr))

#define MMA16816(d, a, b0, b1) \
    asm volatile("mma.sync.aligned.m16n8k16.row.col.f32.bf16.bf16.f32 " \
        "{%0,%1,%2,%3}, {%4,%5,%6,%7}, {%8,%9}, {%0,%1,%2,%3};" \
        : "+f"((d)[0]), "+f"((d)[1]), "+f"((d)[2]), "+f"((d)[3]) \
        : "r"((a)[0]), "r"((a)[1]), "r"((a)[2]), "r"((a)[3]), "r"(b0), "r"(b1))

#define MMAF16(d, a, b0, b1) \
    asm volatile("mma.sync.aligned.m16n8k16.row.col.f32.f16.f16.f32 " \
        "{%0,%1,%2,%3}, {%4,%5,%6,%7}, {%8,%9}, {%0,%1,%2,%3};" \
        : "+f"((d)[0]), "+f"((d)[1]), "+f"((d)[2]), "+f"((d)[3]) \
        : "r"((a)[0]), "r"((a)[1]), "r"((a)[2]), "r"((a)[3]), "r"(b0), "r"(b1))

__device__ __forceinline__ void pack2(float v0, float v1, uint32_t& hi, uint32_t& lo) {
    __nv_bfloat16 h0 = __float2bfloat16(v0);
    __nv_bfloat16 l0 = __float2bfloat16(v0 - __bfloat162float(h0));
    __nv_bfloat16 h1 = __float2bfloat16(v1);
    __nv_bfloat16 l1 = __float2bfloat16(v1 - __bfloat162float(h1));
    hi = (uint32_t)__bfloat16_as_ushort(h0) | ((uint32_t)__bfloat16_as_ushort(h1) << 16);
    lo = (uint32_t)__bfloat16_as_ushort(l0) | ((uint32_t)__bfloat16_as_ushort(l1) << 16);
}

__device__ __forceinline__ void pack2h(float v0, float v1, uint32_t& hi, uint32_t& lo) {
    __half h0 = __float2half(v0);
    __half l0 = __float2half(v0 - __half2float(h0));
    __half h1 = __float2half(v1);
    __half l1 = __float2half(v1 - __half2float(h1));
    hi = (uint32_t)__half_as_ushort(h0) | ((uint32_t)__half_as_ushort(h1) << 16);
    lo = (uint32_t)__half_as_ushort(l0) | ((uint32_t)__half_as_ushort(l1) << 16);
}

// ---------------------------------------------------------------------------
// scratch (device globals)
// ---------------------------------------------------------------------------
__device__ float g_x  [NTOK*DMODEL];
__device__ __nv_bfloat16 g_hn_hi[NTOK*DMODEL];
__device__ __nv_bfloat16 g_hn_lo[NTOK*DMODEL];
__device__ __nv_bfloat16 g_y_hi [NTOK*DMODEL];
__device__ __nv_bfloat16 g_y_lo [NTOK*DMODEL];
__device__ __nv_bfloat16 g_mlp_hi[NTOK*4*DMODEL];
__device__ __nv_bfloat16 g_mlp_lo[NTOK*4*DMODEL];
// attention operand tiles: Q @0, K @QS1, VT @2*QS1 (each 64bh x 16 tiles x 4096)
#define QS1 4194304ull
__device__ __nv_bfloat16 g_qkvt_hi[3*QS1];
__device__ __nv_bfloat16 g_qkvt_lo[3*QS1];
// weights, transposed [N,K] + swizzled tile format, hi/lo split (layer GEMMs)
#define WTOTAL 50331648ull   // 4*12*MDD (head moved to fp16 buffer)
#define LWq 12582912ull
#define MDDq 1048576ull
__device__ __nv_bfloat16 g_w_hi[WTOTAL];
__device__ __nv_bfloat16 g_w_lo[WTOTAL];
// head weights, fp16 single, [N,K] swizzled tiles
__device__ __half g_w16[32768000ull];   // 32000*1024

// ---------------------------------------------------------------------------
// single-launch weight convert
// ---------------------------------------------------------------------------
__global__ __launch_bounds__(256)
void convert_all(const float* __restrict__ Wq, const float* __restrict__ Wk,
                 const float* __restrict__ Wv, const float* __restrict__ Wp,
                 const float* __restrict__ W1, const float* __restrict__ W2,
                 const float* __restrict__ Whead,
                 __nv_bfloat16* __restrict__ wh, __nv_bfloat16* __restrict__ wl,
                 __half* __restrict__ w16)
{
    int bid = blockIdx.x;
    int t = threadIdx.x;
    int n_loc = t & 127, grp = t >> 7;

    if (bid >= 6144) {                       // head [1024 -> 32000] -> fp16
        int i = bid - 6144;
        int nt = i >> 4, kc = i & 15;
        const float* W = Whead;
        size_t dstBlk = ((size_t)nt*16 + kc)*8192;
        uint4* o4 = (uint4*)(w16 + dstBlk);
        #pragma unroll
        for (int g = 0; g < 4; g++) {
            int kg = grp + g*2;
            int k0 = kc*64 + kg*8;
            unsigned hs[8];
            #pragma unroll
            for (int i2 = 0; i2 < 8; i2++) {
                float v = W[(size_t)(k0 + i2) * 32000 + nt*128 + n_loc];
                hs[i2] = __half_as_ushort(__float2half(v));
            }
            uint4 uh;
            uh.x = hs[0] | (hs[1] << 16); uh.y = hs[2] | (hs[3] << 16);
            uh.z = hs[4] | (hs[5] << 16); uh.w = hs[6] | (hs[7] << 16);
            uint32_t bo = SWZ((uint32_t)n_loc*128 + (uint32_t)kg*16);
            o4[bo >> 4] = uh;
        }
        return;
    }

    const float* W; int N, kc, nt;
    size_t dstBlk;
    {
        int l = bid / 1536, r = bid % 1536;
        size_t wb = (size_t)l * LWq;
        if (r < 384) {                       // fused QKV
            int nt_f = r >> 4; kc = r & 15;
            int sel = nt_f >> 3; nt = nt_f & 7;
            W = (sel == 0 ? Wq : (sel == 1 ? Wk : Wv)) + (size_t)l*DMODEL*DMODEL;
            N = 1024;
            dstBlk = wb + ((size_t)nt_f*16 + kc)*8192;
        } else if (r < 512) {                // proj
            int i = r - 384; nt = i >> 4; kc = i & 15;
            W = Wp + (size_t)l*DMODEL*DMODEL; N = 1024;
            dstBlk = wb + 3*MDDq + ((size_t)nt*16 + kc)*8192;
        } else if (r < 1024) {               // W1 [1024 -> 4096]
            int i = r - 512; nt = i >> 4; kc = i & 15;
            W = W1 + (size_t)l*DMODEL*4*DMODEL; N = 4096;
            dstBlk = wb + 4*MDDq + ((size_t)nt*16 + kc)*8192;
        } else {                             // W2 [4096 -> 1024]
            int i = r - 1024; nt = i >> 6; kc = i & 63;
            W = W2 + (size_t)l*DMODEL*4*DMODEL; N = 1024;
            dstBlk = wb + 8*MDDq + ((size_t)nt*64 + kc)*8192;
        }
    }

    uint4* hi4 = (uint4*)(wh + dstBlk);
    uint4* lo4 = (uint4*)(wl + dstBlk);
    #pragma unroll
    for (int g = 0; g < 4; g++) {
        int kg = grp + g*2;
        int k0 = kc*64 + kg*8;
        unsigned hs[8], ls[8];
        #pragma unroll
        for (int i = 0; i < 8; i++) {
            float v = W[(size_t)(k0 + i) * N + nt*128 + n_loc];
            __nv_bfloat16 h = __float2bfloat16(v);
            __nv_bfloat16 l = __float2bfloat16(v - __bfloat162float(h));
            hs[i] = __bfloat16_as_ushort(h);
            ls[i] = __bfloat16_as_ushort(l);
        }
        uint4 uh, ul;
        uh.x = hs[0] | (hs[1] << 16); uh.y = hs[2] | (hs[3] << 16);
        uh.z = hs[4] | (hs[5] << 16); uh.w = hs[6] | (hs[7] << 16);
        ul.x = ls[0] | (ls[1] << 16); ul.y = ls[2] | (ls[3] << 16);
        ul.z = ls[4] | (ls[5] << 16); ul.w = ls[6] | (ls[7] << 16);
        uint32_t bo = SWZ((uint32_t)n_loc*128 + (uint32_t)kg*16);
        hi4[bo >> 4] = uh;
        lo4[bo >> 4] = ul;
    }
}

// ---------------------------------------------------------------------------
// embed (fp32 residual stream)
// ---------------------------------------------------------------------------
__global__ __launch_bounds__(256)
void embed_kernel(const float* __restrict__ states, const int* __restrict__ timesteps,
                  const float* __restrict__ w1, const float* __restrict__ b1,
                  const float* __restrict__ w2, const float* __restrict__ b2,
                  const float* __restrict__ w3, const float* __restrict__ b3,
                  const float* __restrict__ pos_emb, const float* __restrict__ gpe,
                  float* __restrict__ x)
{
    int token = blockIdx.x;
    int b = token / SEQ, s = token % SEQ;
    __shared__ float st[4], h1[16], h2[16];
    int tid = threadIdx.x;
    if (tid < 4) st[tid] = states[token*4 + tid];
    __syncthreads();
    if (tid < 16) {
        float a = b1[tid];
        #pragma unroll
        for (int i = 0; i < 4; i++) a += st[i] * w1[i*16 + tid];
        h1[tid] = fmaxf(a, 0.0f);
    }
    __syncthreads();
    if (tid < 16) {
        float a = b2[tid];
        #pragma unroll
        for (int i = 0; i < 16; i++) a += h1[i] * w2[i*16 + tid];
        h2[tid] = fmaxf(a, 0.0f);
    }
    __syncthreads();
    int t = timesteps[b];
    for (int d = tid; d < DMODEL; d += blockDim.x) {
        float a = b3[d];
        #pragma unroll
        for (int i = 0; i < 16; i++) a += h2[i] * w3[i*DMODEL + d];
        x[(size_t)token*DMODEL + d] = tanhf(a) + gpe[(size_t)t*DMODEL + d]
                                      + pos_emb[(size_t)s*DMODEL + d];
    }
}

// ---------------------------------------------------------------------------
// layernorm: fp32 in -> bf16 hi/lo swizzled A-tiles (K=1024)
// fmt 0: bf16 hi/lo    fmt 1: fp16 hi/lo (for head GEMM)
// ---------------------------------------------------------------------------
__global__ __launch_bounds__(256)
void ln_hilo_kernel(const float* __restrict__ X,
                    const float* __restrict__ g, const float* __restrict__ b,
                    __nv_bfloat16* __restrict__ ohi, __nv_bfloat16* __restrict__ olo,
                    int fmt)
{
    int row = blockIdx.x;
    const float* xr = X + (size_t)row*DMODEL;
    int tid = threadIdx.x;
    float4 v = *(const float4*)(xr + tid*4);
    float s = v.x+v.y+v.z+v.w;
    float sq = v.x*v.x + v.y*v.y + v.z*v.z + v.w*v.w;
    __shared__ float rs[8], rq[8];
    #pragma unroll
    for (int off = 16; off; off >>= 1) {
        s  += __shfl_xor_sync(0xffffffffu, s,  off);
        sq += __shfl_xor_sync(0xffffffffu, sq, off);
    }
    if ((tid & 31) == 0) { rs[tid>>5] = s; rq[tid>>5] = sq; }
    __syncthreads();
    if (tid < 32) {
        s  = (tid < 8) ? rs[tid] : 0.f;
        sq = (tid < 8) ? rq[tid] : 0.f;
        #pragma unroll
        for (int off = 4; off; off >>= 1) {
            s  += __shfl_xor_sync(0xffffffffu, s,  off);
            sq += __shfl_xor_sync(0xffffffffu, sq, off);
        }
        if (tid == 0) { rs[0] = s; rq[0] = sq; }
    }
    __syncthreads();
    float mu  = rs[0] * (1.0f/DMODEL);
    float var = rq[0] * (1.0f/DMODEL) - mu*mu;
    float r   = rsqrtf(var + 1e-5f);
    int k0 = tid*4;
    float o[4] = {v.x, v.y, v.z, v.w};
    unsigned hs[4], ls[4];
    #pragma unroll
    for (int i = 0; i < 4; i++) {
        int c = k0 + i;
        float val = (o[i] - mu) * r * g[c] + b[c];
        if (fmt == 0) {
            __nv_bfloat16 h = __float2bfloat16(val);
            __nv_bfloat16 l = __float2bfloat16(val - __bfloat162float(h));
            hs[i] = __bfloat16_as_ushort(h);
            ls[i] = __bfloat16_as_ushort(l);
        } else {
            __half h = __float2half(val);
            __half l = __float2half(val - __half2float(h));
            hs[i] = __half_as_ushort(h);
            ls[i] = __half_as_ushort(l);
        }
    }
    int kc = k0 >> 6, c = k0 & 63;
    size_t tb = ((size_t)(row >> 7) * 16 + kc) * 8192;
    uint32_t bo = SWZ((uint32_t)(row & 127)*128 + (uint32_t)c*2);
    uint2 uh = { hs[0] | (hs[1] << 16), hs[2] | (hs[3] << 16) };
    uint2 ul = { ls[0] | (ls[1] << 16), ls[2] | (ls[3] << 16) };
    *(uint2*)((char*)(ohi + tb) + bo) = uh;
    *(uint2*)((char*)(olo + tb) + bo) = ul;
}

// ---------------------------------------------------------------------------
// mma.sync GEMM (bf16 3-term), 3-stage cp.async pipeline.
// 512 threads = 16 warps (4x4), warp tile 32x32.
// mode 0: C fp32   2: C fp32 +bias +resid   3: gelu(+bias)->Ohi/Olo (A tiles)
// mode 4: QKV -> attention tiles: Q/K [row][d], V transposed [d][key], hi/lo
// ---------------------------------------------------------------------------
#define GEMM_SMEM 196608

__global__ __launch_bounds__(512, 1)
void gemm_mma(const uint4* __restrict__ Ahi, const uint4* __restrict__ Alo,
              const uint4* __restrict__ Bhi, const uint4* __restrict__ Blo,
              const float* __restrict__ bias, const float* __restrict__ resid,
              float* __restrict__ Cf,
              __nv_bfloat16* __restrict__ Ohi, __nv_bfloat16* __restrict__ Olo,
              int N, int K, int mode)
{
    extern __shared__ char sb[];
    uint32_t sbase = smem_u32(sb);
    int tid = threadIdx.x, wid = tid >> 5, lane = tid & 31;
    int nt = blockIdx.x, mt = blockIdx.y;
    int NC = K >> 6;
    int wm = wid & 3, wn = wid >> 2;

    const uint4* gA0h = Ahi + (size_t)mt * NC * 1024;
    const uint4* gA0l = Alo + (size_t)mt * NC * 1024;
    const uint4* gB0h = Bhi + (size_t)nt * NC * 1024;
    const uint4* gB0l = Blo + (size_t)nt * NC * 1024;

    float acc[2][4][4];
    #pragma unroll
    for (int i = 0; i < 2; i++)
        #pragma unroll
        for (int j = 0; j < 4; j++)
            #pragma unroll
            for (int q = 0; q < 4; q++) acc[i][j][q] = 0.f;

    auto load_chunk = [&](int c, int s) {
        uint32_t sA = sbase + s*65536;
        const uint4* ah = gA0h + (size_t)c*1024;
        const uint4* al = gA0l + (size_t)c*1024;
        const uint4* bh = gB0h + (size_t)c*1024;
        const uint4* bl = gB0l + (size_t)c*1024;
        #pragma unroll
        for (int i = 0; i < 2; i++) {
            int idx = tid + i*512;
            cp16(sA +         idx*16, ah + idx);
            cp16(sA + 16384 + idx*16, al + idx);
            cp16(sA + 32768 + idx*16, bh + idx);
            cp16(sA + 49152 + idx*16, bl + idx);
        }
    };

    load_chunk(0, 0);
    CP_COMMIT();
    if (NC > 1) { load_chunk(1, 1); CP_COMMIT(); }

    int lrow = lane & 15;
    int lkc8 = (lane >> 4) * 8;

    for (int c = 0; c < NC; c++) {
        int s = c % 3;
        if (c + 2 < NC) {
            load_chunk(c + 2, (c + 2) % 3);
            CP_COMMIT();
            CP_WAIT(2);
        } else if (c + 1 < NC) {
            CP_WAIT(1);
        } else {
            CP_WAIT(0);
        }
        __syncthreads();

        uint32_t sAh = sbase + s*65536;
        uint32_t sAl = sAh + 16384;
        uint32_t sBh = sAh + 32768;
        uint32_t sBl = sAh + 49152;

        #pragma unroll
        for (int ks = 0; ks < 4; ks++) {
            int k0 = ks*16;
            uint32_t ah[2][4], al[2][4];
            #pragma unroll
            for (int tm = 0; tm < 2; tm++) {
                uint32_t off = SWZ((uint32_t)(wm*32 + tm*16 + lrow)*128
                                   + (uint32_t)(k0 + lkc8)*2);
                LDSM4(ah[tm], sAh + off);
                LDSM4(al[tm], sAl + off);
            }
            uint32_t bh[2][4], bl[2][4];
            #pragma unroll
            for (int g = 0; g < 2; g++) {
                uint32_t off = SWZ((uint32_t)(wn*32 + g*16 + lrow)*128
                                   + (uint32_t)(k0 + lkc8)*2);
                LDSM4(bh[g], sBh + off);
                LDSM4(bl[g], sBl + off);
            }
            #pragma unroll
            for (int tm = 0; tm < 2; tm++)
                #pragma unroll
                for (int g = 0; g < 2; g++) {
                    MMA16816(acc[tm][2*g  ], ah[tm], bh[g][0], bh[g][2]);
                    MMA16816(acc[tm][2*g+1], ah[tm], bh[g][1], bh[g][3]);
                }
            #pragma unroll
            for (int tm = 0; tm < 2; tm++)
                #pragma unroll
                for (int g = 0; g < 2; g++) {
                    MMA16816(acc[tm][2*g  ], ah[tm], bl[g][0], bl[g][2]);
                    MMA16816(acc[tm][2*g+1], ah[tm], bl[g][1], bl[g][3]);
                }
            #pragma unroll
            for (int tm = 0; tm < 2; tm++)
                #pragma unroll
                for (int g = 0; g < 2; g++) {
                    MMA16816(acc[tm][2*g  ], al[tm], bh[g][0], bh[g][2]);
                    MMA16816(acc[tm][2*g+1], al[tm], bh[g][1], bh[g][3]);
                }
        }
    }

    // ---- epilogue ----
    int gr = lane >> 2, gc = lane & 3;
    #pragma unroll
    for (int tm = 0; tm < 2; tm++) {
        #pragma unroll
        for (int tn = 0; tn < 4; tn++) {
            float* a = acc[tm][tn];
            int rIn0 = wm*32 + tm*16 + gr;
            int col  = nt*128 + wn*32 + tn*8 + gc*2;
            if (mode == 3) {
                int kc = col >> 6, cc = col & 63;
                size_t tb = ((size_t)mt * (N >> 6) + kc) * 8192;
                #pragma unroll
                for (int hhalf = 0; hhalf < 2; hhalf++) {
                    int rIn = rIn0 + hhalf*8;
                    float v0 = a[hhalf*2]     + bias[col];
                    float v1 = a[hhalf*2 + 1] + bias[col + 1];
                    v0 = 0.5f * v0 * (1.0f + erff(v0 * 0.70710678118654752f));
                    v1 = 0.5f * v1 * (1.0f + erff(v1 * 0.70710678118654752f));
                    uint32_t uh, ul;
                    pack2(v0, v1, uh, ul);
                    uint32_t bo = SWZ((uint32_t)rIn*128 + (uint32_t)cc*2);
                    *(uint32_t*)((char*)(Ohi + tb) + bo) = uh;
                    *(uint32_t*)((char*)(Olo + tb) + bo) = ul;
                }
            } else if (mode == 4) {
                int sect = col >> 10;          // 0=Q, 1=K, 2=V
                int df   = col & 1023;
                int hh2  = df >> 6;            // head
                int cc   = df & 63;            // d within head
                #pragma unroll
                for (int hhalf = 0; hhalf < 2; hhalf++) {
                    int row = mt*128 + rIn0 + hhalf*8;     // token
                    int bq = row >> 10;
                    int tt = (row >> 6) & 15;              // tile index
                    int r  = row & 63;                     // row within tile
                    int bh = bq*NHEAD + hh2;
                    size_t tbase = (size_t)sect * QS1 + ((size_t)(bh*16 + tt))*4096;
                    float v0 = a[hhalf*2], v1 = a[hhalf*2 + 1];
                    uint32_t uh, ul;
                    pack2(v0, v1, uh, ul);
                    if (sect < 2) {
                        uint32_t bo = SWZ((uint32_t)r*128 + (uint32_t)cc*2);
                        *(uint32_t*)((char*)(Ohi + tbase) + bo) = uh;
                        *(uint32_t*)((char*)(Olo + tbase) + bo) = ul;
                    } else {
                        // V transposed: tile row = d (cc), col = key (r)
                        uint32_t bo0 = SWZ((uint32_t)cc*128 + (uint32_t)r*2);
                        uint32_t bo1 = SWZ((uint32_t)(cc+1)*128 + (uint32_t)r*2);
                        *(uint16_t*)((char*)(Ohi + tbase) + bo0) = (uint16_t)(uh & 0xffff);
                        *(uint16_t*)((char*)(Ohi + tbase) + bo1) = (uint16_t)(uh >> 16);
                        *(uint16_t*)((char*)(Olo + tbase) + bo0) = (uint16_t)(ul & 0xffff);
                        *(uint16_t*)((char*)(Olo + tbase) + bo1) = (uint16_t)(ul >> 16);
                    }
                }
            } else {
                #pragma unroll
                for (int hhalf = 0; hhalf < 2; hhalf++) {
                    int row = mt*128 + rIn0 + hhalf*8;
                    float v0 = a[hhalf*2], v1 = a[hhalf*2 + 1];
                    if (mode == 2) {
                        v0 += bias[col]     + resid[(size_t)row*N + col];
                        v1 += bias[col + 1] + resid[(size_t)row*N + col + 1];
                    }
                    float2 o = {v0, v1};
                    *(float2*)(Cf + (size_t)row*N + col) = o;
                }
            }
        }
    }
}

// ---------------------------------------------------------------------------
// fp16 head GEMM: C = A x W, A = fp16 2-term (hi+lo), B = fp16 1-term.
// 2 MMAs per (m,n,k) instead of 3. 48KB/stage x 3 stages. Plain fp32 output.
// ---------------------------------------------------------------------------
#define GEMMF16_SMEM 147456

__global__ __launch_bounds__(512, 1)
void gemm_f16(const uint4* __restrict__ Ahi, const uint4* __restrict__ Alo,
              const uint4* __restrict__ B16, float* __restrict__ Cf, int N, int K)
{
    extern __shared__ char sb[];
    uint32_t sbase = smem_u32(sb);
    int tid = threadIdx.x, wid = tid >> 5, lane = tid & 31;
    int nt = blockIdx.x, mt = blockIdx.y;
    int NC = K >> 6;
    int wm = wid & 3, wn = wid >> 2;

    const uint4* gAh = Ahi + (size_t)mt * NC * 1024;
    const uint4* gAl = Alo + (size_t)mt * NC * 1024;
    const uint4* gB  = B16 + (size_t)nt * NC * 1024;

    float acc[2][4][4];
    #pragma unroll
    for (int i = 0; i < 2; i++)
        #pragma unroll
        for (int j = 0; j < 4; j++)
            #pragma unroll
            for (int q = 0; q < 4; q++) acc[i][j][q] = 0.f;

    auto load_chunk = [&](int c, int s) {
        uint32_t sA = sbase + s*49152;
        const uint4* ah = gAh + (size_t)c*1024;
        const uint4* al = gAl + (size_t)c*1024;
        const uint4* bb = gB  + (size_t)c*1024;
        #pragma unroll
        for (int i = 0; i < 2; i++) {
            int idx = tid + i*512;
            cp16(sA +         idx*16, ah + idx);
            cp16(sA + 16384 + idx*16, al + idx);
            cp16(sA + 32768 + idx*16, bb + idx);
        }
    };

    load_chunk(0, 0);
    CP_COMMIT();
    if (NC > 1) { load_chunk(1, 1); CP_COMMIT(); }

    int lrow = lane & 15;
    int lkc8 = (lane >> 4) * 8;

    for (int c = 0; c < NC; c++) {
        int s = c % 3;
        if (c + 2 < NC) {
            load_chunk(c + 2, (c + 2) % 3);
            CP_COMMIT();
            CP_WAIT(2);
        } else if (c + 1 < NC) {
            CP_WAIT(1);
        } else {
            CP_WAIT(0);
        }
        __syncthreads();

        uint32_t sAh = sbase + s*49152;
        uint32_t sAl = sAh + 16384;
        uint32_t sB  = sAh + 32768;

        #pragma unroll
        for (int ks = 0; ks < 4; ks++) {
            int k0 = ks*16;
            uint32_t ah[2][4], al[2][4];
            #pragma unroll
            for (int tm = 0; tm < 2; tm++) {
                uint32_t off = SWZ((uint32_t)(wm*32 + tm*16 + lrow)*128
                                   + (uint32_t)(k0 + lkc8)*2);
                LDSM4(ah[tm], sAh + off);
                LDSM4(al[tm], sAl + off);
            }
            uint32_t bb[2][4];
            #pragma unroll
            for (int g = 0; g < 2; g++) {
                uint32_t off = SWZ((uint32_t)(wn*32 + g*16 + lrow)*128
                                   + (uint32_t)(k0 + lkc8)*2);
                LDSM4(bb[g], sB + off);
            }
            #pragma unroll
            for (int tm = 0; tm < 2; tm++)
                #pragma unroll
                for (int g = 0; g < 2; g++) {
                    MMAF16(acc[tm][2*g  ], ah[tm], bb[g][0], bb[g][2]);
                    MMAF16(acc[tm][2*g+1], ah[tm], bb[g][1], bb[g][3]);
                }
            #pragma unroll
            for (int tm = 0; tm < 2; tm++)
                #pragma unroll
                for (int g = 0; g < 2; g++) {
                    MMAF16(acc[tm][2*g  ], al[tm], bb[g][0], bb[g][2]);
                    MMAF16(acc[tm][2*g+1], al[tm], bb[g][1], bb[g][3]);
                }
        }
    }

    int gr = lane >> 2, gc = lane & 3;
    #pragma unroll
    for (int tm = 0; tm < 2; tm++) {
        #pragma unroll
        for (int tn = 0; tn < 4; tn++) {
            float* a = acc[tm][tn];
            int rIn0 = wm*32 + tm*16 + gr;
            int col  = nt*128 + wn*32 + tn*8 + gc*2;
            #pragma unroll
            for (int hhalf = 0; hhalf < 2; hhalf++) {
                int row = mt*128 + rIn0 + hhalf*8;
                float2 o = {a[hhalf*2], a[hhalf*2 + 1]};
                *(float2*)(Cf + (size_t)row*N + col) = o;
            }
        }
    }
}

// ---------------------------------------------------------------------------
// mma.sync causal flash attention. 128 thr (4 warps), 64x64 tiles.
// ---------------------------------------------------------------------------
#define ATTN_SMEM 81920

__global__ __launch_bounds__(128)
void attn_mma(const __nv_bfloat16* __restrict__ qkvt_hi,
              const __nv_bfloat16* __restrict__ qkvt_lo,
              __nv_bfloat16* __restrict__ yhi, __nv_bfloat16* __restrict__ ylo)
{
    extern __shared__ char sb[];
    uint32_t sbase = smem_u32(sb);
    int qt = blockIdx.x, h = blockIdx.y, b = blockIdx.z;
    int tid = threadIdx.x, w = tid >> 5, lane = tid & 31;
    int bh = b*NHEAD + h;
    int lrow = lane & 15, lkc8 = (lane >> 4) * 8;
    int gr = lane >> 2, gc = lane & 3;

    {
        const uint4* gQh = (const uint4*)(qkvt_hi + ((size_t)(bh*16 + qt))*4096);
        const uint4* gQl = (const uint4*)(qkvt_lo + ((size_t)(bh*16 + qt))*4096);
        #pragma unroll
        for (int i = 0; i < 4; i++) {
            int idx = tid + i*128;
            cp16(sbase +        idx*16, gQh + idx);
            cp16(sbase + 8192 + idx*16, gQl + idx);
        }
    }
    CP_COMMIT();

    auto load_kv = [&](int kt, int s) {
        uint32_t st = sbase + 16384 + s*32768;
        size_t toff = (size_t)(bh*16 + kt)*4096;
        const uint4* kh = (const uint4*)(qkvt_hi +   QS1 + toff);
        const uint4* kl = (const uint4*)(qkvt_lo +   QS1 + toff);
        const uint4* vh = (const uint4*)(qkvt_hi + 2*QS1 + toff);
        const uint4* vl = (const uint4*)(qkvt_lo + 2*QS1 + toff);
        #pragma unroll
        for (int i = 0; i < 4; i++) {
            int idx = tid + i*128;
            cp16(st +         idx*16, kh + idx);
            cp16(st +  8192 + idx*16, kl + idx);
            cp16(st + 16384 + idx*16, vh + idx);
            cp16(st + 24576 + idx*16, vl + idx);
        }
    };
    load_kv(0, 0);
    CP_COMMIT();
    CP_WAIT(0);
    __syncthreads();

    uint32_t qh[4][4], ql[4][4];
    #pragma unroll
    for (int kk = 0; kk < 4; kk++) {
        uint32_t off = SWZ((uint32_t)(w*16 + lrow)*128 + (uint32_t)(kk*16 + lkc8)*2);
        LDSM4(qh[kk], sbase + off);
        LDSM4(ql[kk], sbase + 8192 + off);
    }

    float oAcc[8][4];
    #pragma unroll
    for (int j = 0; j < 8; j++)
        #pragma unroll
        for (int q4 = 0; q4 < 4; q4++) oAcc[j][q4] = 0.f;
    float m0 = -1e30f, m1 = -1e30f, l0 = 0.f, l1 = 0.f;

    int qrow0 = qt*64 + w*16 + gr, qrow1 = qrow0 + 8;

    for (int kt = 0; kt <= qt; kt++) {
        int s = kt & 1;
        if (kt + 1 <= qt) {
            load_kv(kt + 1, (kt + 1) & 1);
            CP_COMMIT();
            CP_WAIT(1);
        } else {
            CP_WAIT(0);
        }
        __syncthreads();
        uint32_t sK = sbase + 16384 + s*32768;

        float sAcc[8][4];
        #pragma unroll
        for (int j = 0; j < 8; j++)
            #pragma unroll
            for (int q4 = 0; q4 < 4; q4++) sAcc[j][q4] = 0.f;

        #pragma unroll
        for (int kk = 0; kk < 4; kk++) {
            #pragma unroll
            for (int g = 0; g < 4; g++) {
                uint32_t off = SWZ((uint32_t)(g*16 + lrow)*128 + (uint32_t)(kk*16 + lkc8)*2);
                uint32_t kh4[4], kl4[4];
                LDSM4(kh4, sK + off);
                LDSM4(kl4, sK + 8192 + off);
                MMA16816(sAcc[2*g  ], qh[kk], kh4[0], kh4[2]);
                MMA16816(sAcc[2*g+1], qh[kk], kh4[1], kh4[3]);
                MMA16816(sAcc[2*g  ], qh[kk], kl4[0], kl4[2]);
                MMA16816(sAcc[2*g+1], qh[kk], kl4[1], kl4[3]);
                MMA16816(sAcc[2*g  ], ql[kk], kh4[0], kh4[2]);
                MMA16816(sAcc[2*g+1], ql[kk], kh4[1], kh4[3]);
            }
        }

        bool diag = (kt == qt);
        #pragma unroll
        for (int j = 0; j < 8; j++) {
            #pragma unroll
            for (int q4 = 0; q4 < 4; q4++) sAcc[j][q4] *= 0.125f;
            if (diag) {
                int key0 = kt*64 + j*8 + gc*2;
                if (key0     > qrow0) sAcc[j][0] = -1e30f;
                if (key0 + 1 > qrow0) sAcc[j][1] = -1e30f;
                if (key0     > qrow1) sAcc[j][2] = -1e30f;
                if (key0 + 1 > qrow1) sAcc[j][3] = -1e30f;
            }
        }

        float rm0 = -1e30f, rm1 = -1e30f;
        #pragma unroll
        for (int j = 0; j < 8; j++) {
            rm0 = fmaxf(rm0, fmaxf(sAcc[j][0], sAcc[j][1]));
            rm1 = fmaxf(rm1, fmaxf(sAcc[j][2], sAcc[j][3]));
        }
        rm0 = fmaxf(rm0, __shfl_xor_sync(0xffffffffu, rm0, 1));
        rm0 = fmaxf(rm0, __shfl_xor_sync(0xffffffffu, rm0, 2));
        rm1 = fmaxf(rm1, __shfl_xor_sync(0xffffffffu, rm1, 1));
        rm1 = fmaxf(rm1, __shfl_xor_sync(0xffffffffu, rm1, 2));

        float mn0 = fmaxf(m0, rm0), mn1 = fmaxf(m1, rm1);
        float al0 = __expf(m0 - mn0), al1 = __expf(m1 - mn1);

        float ps0 = 0.f, ps1 = 0.f;
        #pragma unroll
        for (int j = 0; j < 8; j++) {
            sAcc[j][0] = __expf(sAcc[j][0] - mn0);
            sAcc[j][1] = __expf(sAcc[j][1] - mn0);
            sAcc[j][2] = __expf(sAcc[j][2] - mn1);
            sAcc[j][3] = __expf(sAcc[j][3] - mn1);
            ps0 += sAcc[j][0] + sAcc[j][1];
            ps1 += sAcc[j][2] + sAcc[j][3];
        }
        ps0 += __shfl_xor_sync(0xffffffffu, ps0, 1);
        ps0 += __shfl_xor_sync(0xffffffffu, ps0, 2);
        ps1 += __shfl_xor_sync(0xffffffffu, ps1, 1);
        ps1 += __shfl_xor_sync(0xffffffffu, ps1, 2);

        l0 = l0*al0 + ps0;  l1 = l1*al1 + ps1;
        m0 = mn0;           m1 = mn1;
        #pragma unroll
        for (int j = 0; j < 8; j++) {
            oAcc[j][0] *= al0; oAcc[j][1] *= al0;
            oAcc[j][2] *= al1; oAcc[j][3] *= al1;
        }

        #pragma unroll
        for (int kk2 = 0; kk2 < 4; kk2++) {
            uint32_t ph[4], pl[4];
            pack2(sAcc[2*kk2  ][0], sAcc[2*kk2  ][1], ph[0], pl[0]);
            pack2(sAcc[2*kk2  ][2], sAcc[2*kk2  ][3], ph[1], pl[1]);
            pack2(sAcc[2*kk2+1][0], sAcc[2*kk2+1][1], ph[2], pl[2]);
            pack2(sAcc[2*kk2+1][2], sAcc[2*kk2+1][3], ph[3], pl[3]);
            #pragma unroll
            for (int g = 0; g < 4; g++) {
                uint32_t off = SWZ((uint32_t)(g*16 + lrow)*128 + (uint32_t)(kk2*16 + lkc8)*2);
                uint32_t vh4[4], vl4[4];
                LDSM4(vh4, sK + 16384 + off);
                LDSM4(vl4, sK + 24576 + off);
                MMA16816(oAcc[2*g  ], ph, vh4[0], vh4[2]);
                MMA16816(oAcc[2*g+1], ph, vh4[1], vh4[3]);
                MMA16816(oAcc[2*g  ], ph, vl4[0], vl4[2]);
                MMA16816(oAcc[2*g+1], ph, vl4[1], vl4[3]);
                MMA16816(oAcc[2*g  ], pl, vh4[0], vh4[2]);
                MMA16816(oAcc[2*g+1], pl, vh4[1], vh4[3]);
            }
        }
        __syncthreads();
    }

    float inv0 = 1.0f / l0, inv1 = 1.0f / l1;
    int mtok0 = b*SEQ + qt*64 + w*16 + gr;
    size_t tb = ((size_t)(mtok0 >> 7) * 16 + h) * 8192;
    #pragma unroll
    for (int g = 0; g < 8; g++) {
        int cc = g*8 + gc*2;
        uint32_t uh0, ul0, uh1, ul1;
        pack2(oAcc[g][0]*inv0, oAcc[g][1]*inv0, uh0, ul0);
        pack2(oAcc[g][2]*inv1, oAcc[g][3]*inv1, uh1, ul1);
        uint32_t bo0 = SWZ((uint32_t)(mtok0 & 127)*128 + (uint32_t)cc*2);
        uint32_t bo1 = SWZ((uint32_t)((mtok0 + 8) & 127)*128 + (uint32_t)cc*2);
        *(uint32_t*)((char*)(yhi + tb) + bo0) = uh0;
        *(uint32_t*)((char*)(ylo + tb) + bo0) = ul0;
        *(uint32_t*)((char*)(yhi + tb) + bo1) = uh1;
        *(uint32_t*)((char*)(ylo + tb) + bo1) = ul1;
    }
}

// ---------------------------------------------------------------------------
// launch
// ---------------------------------------------------------------------------
extern "C" void kernel_launch(void* const* d_in, const int* in_sizes, int n_in,
                              void* d_out, int out_size)
{
    const float* states     = (const float*)d_in[0];
    const int*   timesteps  = (const int*)  d_in[1];
    const float* se_w1 = (const float*)d_in[2];
    const float* se_b1 = (const float*)d_in[3];
    const float* se_w2 = (const float*)d_in[4];
    const float* se_b2 = (const float*)d_in[5];
    const float* se_w3 = (const float*)d_in[6];
    const float* se_b3 = (const float*)d_in[7];
    const float* pos_emb = (const float*)d_in[8];
    const float* gpe     = (const float*)d_in[9];
    const float* ln1_g = (const float*)d_in[10];
    const float* ln1_b = (const float*)d_in[11];
    const float* Wq = (const float*)d_in[12];
    const float* Wk = (const float*)d_in[13];
    const float* Wv = (const float*)d_in[14];
    const float* Wp = (const float*)d_in[15];
    const float* bp = (const float*)d_in[16];
    const float* ln2_g = (const float*)d_in[17];
    const float* ln2_b = (const float*)d_in[18];
    const float* W1 = (const float*)d_in[19];
    const float* b1 = (const float*)d_in[20];
    const float* W2 = (const float*)d_in[21];
    const float* b2 = (const float*)d_in[22];
    const float* lnf_g = (const float*)d_in[23];
    const float* lnf_b = (const float*)d_in[24];
    const float* head_w = (const float*)d_in[25];

    float *x;
    __nv_bfloat16 *hnh, *hnl, *yh, *yl, *mh, *ml, *wh, *wl, *qth, *qtl;
    __half *w16;
    cudaGetSymbolAddress((void**)&x,   g_x);
    cudaGetSymbolAddress((void**)&hnh, g_hn_hi);
    cudaGetSymbolAddress((void**)&hnl, g_hn_lo);
    cudaGetSymbolAddress((void**)&yh,  g_y_hi);
    cudaGetSymbolAddress((void**)&yl,  g_y_lo);
    cudaGetSymbolAddress((void**)&mh,  g_mlp_hi);
    cudaGetSymbolAddress((void**)&ml,  g_mlp_lo);
    cudaGetSymbolAddress((void**)&wh,  g_w_hi);
    cudaGetSymbolAddress((void**)&wl,  g_w_lo);
    cudaGetSymbolAddress((void**)&qth, g_qkvt_hi);
    cudaGetSymbolAddress((void**)&qtl, g_qkvt_lo);
    cudaGetSymbolAddress((void**)&w16, g_w16);

    cudaFuncSetAttribute(gemm_mma, cudaFuncAttributeMaxDynamicSharedMemorySize, GEMM_SMEM);
    cudaFuncSetAttribute(gemm_f16, cudaFuncAttributeMaxDynamicSharedMemorySize, GEMMF16_SMEM);
    cudaFuncSetAttribute(attn_mma, cudaFuncAttributeMaxDynamicSharedMemorySize, ATTN_SMEM);

    convert_all<<<10144, 256>>>(Wq, Wk, Wv, Wp, W1, W2, head_w, wh, wl, w16);
    embed_kernel<<<NTOK, 256>>>(states, timesteps, se_w1, se_b1, se_w2, se_b2,
                                se_w3, se_b3, pos_emb, gpe, x);

    const size_t LW = LWq, MDD = MDDq;
    dim3 gQKV(24, 32), gDD(8, 32), gD4(32, 32), gHead(250, 32);
    dim3 gAttn(SEQ/64, NHEAD, BATCH);

    for (int l = 0; l < NLAYER; l++) {
        size_t wb = (size_t)l * LW;
        ln_hilo_kernel<<<NTOK, 256>>>(x, ln1_g + l*DMODEL, ln1_b + l*DMODEL, hnh, hnl, 0);
        gemm_mma<<<gQKV, 512, GEMM_SMEM>>>((uint4*)hnh, (uint4*)hnl,
            (uint4*)(wh + wb), (uint4*)(wl + wb),
            nullptr, nullptr, nullptr, qth, qtl, 3*DMODEL, 1024, 4);
        attn_mma<<<gAttn, 128, ATTN_SMEM>>>(qth, qtl, yh, yl);
        gemm_mma<<<gDD, 512, GEMM_SMEM>>>((uint4*)yh, (uint4*)yl,
            (uint4*)(wh + wb + 3*MDD), (uint4*)(wl + wb + 3*MDD),
            bp + l*DMODEL, x, x, nullptr, nullptr, 1024, 1024, 2);
        ln_hilo_kernel<<<NTOK, 256>>>(x, ln2_g + l*DMODEL, ln2_b + l*DMODEL, hnh, hnl, 0);
        gemm_mma<<<gD4, 512, GEMM_SMEM>>>((uint4*)hnh, (uint4*)hnl,
            (uint4*)(wh + wb + 4*MDD), (uint4*)(wl + wb + 4*MDD),
            b1 + (size_t)l*4*DMODEL, nullptr, nullptr, mh, ml, 4096, 1024, 3);
        gemm_mma<<<gDD, 512, GEMM_SMEM>>>((uint4*)mh, (uint4*)ml,
            (uint4*)(wh + wb + 8*MDD), (uint4*)(wl + wb + 8*MDD),
            b2 + l*DMODEL, x, x, nullptr, nullptr, 1024, 4096, 2);
    }

    // final LN in fp16 hi/lo format (reuse hn buffers), fp16 head GEMM
    ln_hilo_kernel<<<NTOK, 256>>>(x, lnf_g, lnf_b, hnh, hnl, 1);
    gemm_f16<<<gHead, 512, GEMMF16_SMEM>>>((uint4*)hnh, (uint4*)hnl,
        (uint4*)w16, (float*)d_out, 32000, 1024);
}

// round 16
// speedup vs baseline: 4.2330x; 1.1614x over previous
#include <cuda_runtime.h>
#include <cuda_bf16.h>
#include <cuda_fp16.h>
#include <math.h>
#include <stdint.h>

#define BATCH 4
#define SEQ   1024
#define DMODEL 1024
#define NHEAD 16
#define NLAYER 4
#define VOCAB 32000
#define DHEAD 64
#define NTOK (BATCH*SEQ)   // 4096

// SW128 swizzle (Swizzle<3,4,3>)
#define SWZ(b) ((b) ^ ((((unsigned)(b)) >> 3) & 0x70u))

// ---------------------------------------------------------------------------
// PTX helpers (portable: sm_80+ PTX, runs on sm_103a)
// ---------------------------------------------------------------------------
__device__ __forceinline__ uint32_t smem_u32(const void* p) {
    uint32_t a;
    asm("{ .reg .u64 t; cvta.to.shared.u64 t, %1; cvt.u32.u64 %0, t; }" : "=r"(a) : "l"(p));
    return a;
}
__device__ __forceinline__ void cp16(uint32_t dst, const void* src) {
    asm volatile("cp.async.cg.shared.global [%0], [%1], 16;" :: "r"(dst), "l"(src));
}
#define CP_COMMIT() asm volatile("cp.async.commit_group;" ::: "memory")
#define CP_WAIT(n)  asm volatile("cp.async.wait_group %0;" :: "n"(n) : "memory")

#define LDSM4(r, addr) \
    asm volatile("ldmatrix.sync.aligned.m8n8.x4.shared.b16 {%0,%1,%2,%3}, [%4];" \
        : "=r"((r)[0]), "=r"((r)[1]), "=r"((r)[2]), "=r"((r)[3]) : "r"(addr))

#define MMA16816(d, a, b0, b1) \
    asm volatile("mma.sync.aligned.m16n8k16.row.col.f32.bf16.bf16.f32 " \
        "{%0,%1,%2,%3}, {%4,%5,%6,%7}, {%8,%9}, {%0,%1,%2,%3};" \
        : "+f"((d)[0]), "+f"((d)[1]), "+f"((d)[2]), "+f"((d)[3]) \
        : "r"((a)[0]), "r"((a)[1]), "r"((a)[2]), "r"((a)[3]), "r"(b0), "r"(b1))

#define MMAF16(d, a, b0, b1) \
    asm volatile("mma.sync.aligned.m16n8k16.row.col.f32.f16.f16.f32 " \
        "{%0,%1,%2,%3}, {%4,%5,%6,%7}, {%8,%9}, {%0,%1,%2,%3};" \
        : "+f"((d)[0]), "+f"((d)[1]), "+f"((d)[2]), "+f"((d)[3]) \
        : "r"((a)[0]), "r"((a)[1]), "r"((a)[2]), "r"((a)[3]), "r"(b0), "r"(b1))

__device__ __forceinline__ void pack2(float v0, float v1, uint32_t& hi, uint32_t& lo) {
    __nv_bfloat16 h0 = __float2bfloat16(v0);
    __nv_bfloat16 l0 = __float2bfloat16(v0 - __bfloat162float(h0));
    __nv_bfloat16 h1 = __float2bfloat16(v1);
    __nv_bfloat16 l1 = __float2bfloat16(v1 - __bfloat162float(h1));
    hi = (uint32_t)__bfloat16_as_ushort(h0) | ((uint32_t)__bfloat16_as_ushort(h1) << 16);
    lo = (uint32_t)__bfloat16_as_ushort(l0) | ((uint32_t)__bfloat16_as_ushort(l1) << 16);
}

__device__ __forceinline__ void pack2h(float v0, float v1, uint32_t& hi, uint32_t& lo) {
    __half h0 = __float2half(v0);
    __half l0 = __float2half(v0 - __half2float(h0));
    __half h1 = __float2half(v1);
    __half l1 = __float2half(v1 - __half2float(h1));
    hi = (uint32_t)__half_as_ushort(h0) | ((uint32_t)__half_as_ushort(h1) << 16);
    lo = (uint32_t)__half_as_ushort(l0) | ((uint32_t)__half_as_ushort(l1) << 16);
}

// ---------------------------------------------------------------------------
// scratch (device globals)
// ---------------------------------------------------------------------------
__device__ float g_x  [NTOK*DMODEL];
__device__ __nv_bfloat16 g_hn_hi[NTOK*DMODEL];
__device__ __nv_bfloat16 g_hn_lo[NTOK*DMODEL];
__device__ __nv_bfloat16 g_y_hi [NTOK*DMODEL];
__device__ __nv_bfloat16 g_y_lo [NTOK*DMODEL];
// mlp buffers hold fp16 bits (written by mode-3 epilogue as raw u32)
__device__ __nv_bfloat16 g_mlp_hi[NTOK*4*DMODEL];
__device__ __nv_bfloat16 g_mlp_lo[NTOK*4*DMODEL];
// attention operand tiles: Q @0, K @QS1, VT @2*QS1 (each 64bh x 16 tiles x 4096)
#define QS1 4194304ull
__device__ __nv_bfloat16 g_qkvt_hi[3*QS1];
__device__ __nv_bfloat16 g_qkvt_lo[3*QS1];
// weights, transposed [N,K] + swizzled tile format, hi/lo split (QKV/proj/W1)
#define WTOTAL 50331648ull
#define LWq 12582912ull
#define MDDq 1048576ull
__device__ __nv_bfloat16 g_w_hi[WTOTAL];
__device__ __nv_bfloat16 g_w_lo[WTOTAL];
// fp16-single weights: head [32000,1024], W2 [4 layers x 1024,4096]
__device__ __half g_w16  [32768000ull];
__device__ __half g_w16w2[16777216ull];

// ---------------------------------------------------------------------------
// single-launch weight convert
// ---------------------------------------------------------------------------
__global__ __launch_bounds__(256)
void convert_all(const float* __restrict__ Wq, const float* __restrict__ Wk,
                 const float* __restrict__ Wv, const float* __restrict__ Wp,
                 const float* __restrict__ W1, const float* __restrict__ W2,
                 const float* __restrict__ Whead,
                 __nv_bfloat16* __restrict__ wh, __nv_bfloat16* __restrict__ wl,
                 __half* __restrict__ w16, __half* __restrict__ w16w2)
{
    int bid = blockIdx.x;
    int t = threadIdx.x;
    int n_loc = t & 127, grp = t >> 7;

    if (bid >= 6144) {                       // head [1024 -> 32000] -> fp16
        int i = bid - 6144;
        int nt = i >> 4, kc = i & 15;
        const float* W = Whead;
        size_t dstBlk = ((size_t)nt*16 + kc)*8192;
        uint4* o4 = (uint4*)(w16 + dstBlk);
        #pragma unroll
        for (int g = 0; g < 4; g++) {
            int kg = grp + g*2;
            int k0 = kc*64 + kg*8;
            unsigned hs[8];
            #pragma unroll
            for (int i2 = 0; i2 < 8; i2++) {
                float v = W[(size_t)(k0 + i2) * 32000 + nt*128 + n_loc];
                hs[i2] = __half_as_ushort(__float2half(v));
            }
            uint4 uh;
            uh.x = hs[0] | (hs[1] << 16); uh.y = hs[2] | (hs[3] << 16);
            uh.z = hs[4] | (hs[5] << 16); uh.w = hs[6] | (hs[7] << 16);
            uint32_t bo = SWZ((uint32_t)n_loc*128 + (uint32_t)kg*16);
            o4[bo >> 4] = uh;
        }
        return;
    }

    int l = bid / 1536, r = bid % 1536;

    if (r >= 1024) {                         // W2 [4096 -> 1024] -> fp16 single
        int i = r - 1024;
        int nt = i >> 6, kc = i & 63;
        const float* W = W2 + (size_t)l*DMODEL*4*DMODEL;
        size_t dstBlk = (size_t)l*4194304ull + ((size_t)nt*64 + kc)*8192;
        uint4* o4 = (uint4*)(w16w2 + dstBlk);
        #pragma unroll
        for (int g = 0; g < 4; g++) {
            int kg = grp + g*2;
            int k0 = kc*64 + kg*8;
            unsigned hs[8];
            #pragma unroll
            for (int i2 = 0; i2 < 8; i2++) {
                float v = W[(size_t)(k0 + i2) * 1024 + nt*128 + n_loc];
                hs[i2] = __half_as_ushort(__float2half(v));
            }
            uint4 uh;
            uh.x = hs[0] | (hs[1] << 16); uh.y = hs[2] | (hs[3] << 16);
            uh.z = hs[4] | (hs[5] << 16); uh.w = hs[6] | (hs[7] << 16);
            uint32_t bo = SWZ((uint32_t)n_loc*128 + (uint32_t)kg*16);
            o4[bo >> 4] = uh;
        }
        return;
    }

    const float* W; int N, kc, nt;
    size_t dstBlk;
    {
        size_t wb = (size_t)l * LWq;
        if (r < 384) {                       // fused QKV
            int nt_f = r >> 4; kc = r & 15;
            int sel = nt_f >> 3; nt = nt_f & 7;
            W = (sel == 0 ? Wq : (sel == 1 ? Wk : Wv)) + (size_t)l*DMODEL*DMODEL;
            N = 1024;
            dstBlk = wb + ((size_t)nt_f*16 + kc)*8192;
        } else if (r < 512) {                // proj
            int i = r - 384; nt = i >> 4; kc = i & 15;
            W = Wp + (size_t)l*DMODEL*DMODEL; N = 1024;
            dstBlk = wb + 3*MDDq + ((size_t)nt*16 + kc)*8192;
        } else {                             // W1 [1024 -> 4096]
            int i = r - 512; nt = i >> 4; kc = i & 15;
            W = W1 + (size_t)l*DMODEL*4*DMODEL; N = 4096;
            dstBlk = wb + 4*MDDq + ((size_t)nt*16 + kc)*8192;
        }
    }

    uint4* hi4 = (uint4*)(wh + dstBlk);
    uint4* lo4 = (uint4*)(wl + dstBlk);
    #pragma unroll
    for (int g = 0; g < 4; g++) {
        int kg = grp + g*2;
        int k0 = kc*64 + kg*8;
        unsigned hs[8], ls[8];
        #pragma unroll
        for (int i = 0; i < 8; i++) {
            float v = W[(size_t)(k0 + i) * N + nt*128 + n_loc];
            __nv_bfloat16 h = __float2bfloat16(v);
            __nv_bfloat16 l = __float2bfloat16(v - __bfloat162float(h));
            hs[i] = __bfloat16_as_ushort(h);
            ls[i] = __bfloat16_as_ushort(l);
        }
        uint4 uh, ul;
        uh.x = hs[0] | (hs[1] << 16); uh.y = hs[2] | (hs[3] << 16);
        uh.z = hs[4] | (hs[5] << 16); uh.w = hs[6] | (hs[7] << 16);
        ul.x = ls[0] | (ls[1] << 16); ul.y = ls[2] | (ls[3] << 16);
        ul.z = ls[4] | (ls[5] << 16); ul.w = ls[6] | (ls[7] << 16);
        uint32_t bo = SWZ((uint32_t)n_loc*128 + (uint32_t)kg*16);
        hi4[bo >> 4] = uh;
        lo4[bo >> 4] = ul;
    }
}

// ---------------------------------------------------------------------------
// embed (fp32 residual stream)
// ---------------------------------------------------------------------------
__global__ __launch_bounds__(256)
void embed_kernel(const float* __restrict__ states, const int* __restrict__ timesteps,
                  const float* __restrict__ w1, const float* __restrict__ b1,
                  const float* __restrict__ w2, const float* __restrict__ b2,
                  const float* __restrict__ w3, const float* __restrict__ b3,
                  const float* __restrict__ pos_emb, const float* __restrict__ gpe,
                  float* __restrict__ x)
{
    int token = blockIdx.x;
    int b = token / SEQ, s = token % SEQ;
    __shared__ float st[4], h1[16], h2[16];
    int tid = threadIdx.x;
    if (tid < 4) st[tid] = states[token*4 + tid];
    __syncthreads();
    if (tid < 16) {
        float a = b1[tid];
        #pragma unroll
        for (int i = 0; i < 4; i++) a += st[i] * w1[i*16 + tid];
        h1[tid] = fmaxf(a, 0.0f);
    }
    __syncthreads();
    if (tid < 16) {
        float a = b2[tid];
        #pragma unroll
        for (int i = 0; i < 16; i++) a += h1[i] * w2[i*16 + tid];
        h2[tid] = fmaxf(a, 0.0f);
    }
    __syncthreads();
    int t = timesteps[b];
    for (int d = tid; d < DMODEL; d += blockDim.x) {
        float a = b3[d];
        #pragma unroll
        for (int i = 0; i < 16; i++) a += h2[i] * w3[i*DMODEL + d];
        x[(size_t)token*DMODEL + d] = tanhf(a) + gpe[(size_t)t*DMODEL + d]
                                      + pos_emb[(size_t)s*DMODEL + d];
    }
}

// ---------------------------------------------------------------------------
// layernorm: fp32 in -> hi/lo swizzled A-tiles (K=1024)
// fmt 0: bf16 hi/lo    fmt 1: fp16 hi/lo
// ---------------------------------------------------------------------------
__global__ __launch_bounds__(256)
void ln_hilo_kernel(const float* __restrict__ X,
                    const float* __restrict__ g, const float* __restrict__ b,
                    __nv_bfloat16* __restrict__ ohi, __nv_bfloat16* __restrict__ olo,
                    int fmt)
{
    int row = blockIdx.x;
    const float* xr = X + (size_t)row*DMODEL;
    int tid = threadIdx.x;
    float4 v = *(const float4*)(xr + tid*4);
    float s = v.x+v.y+v.z+v.w;
    float sq = v.x*v.x + v.y*v.y + v.z*v.z + v.w*v.w;
    __shared__ float rs[8], rq[8];
    #pragma unroll
    for (int off = 16; off; off >>= 1) {
        s  += __shfl_xor_sync(0xffffffffu, s,  off);
        sq += __shfl_xor_sync(0xffffffffu, sq, off);
    }
    if ((tid & 31) == 0) { rs[tid>>5] = s; rq[tid>>5] = sq; }
    __syncthreads();
    if (tid < 32) {
        s  = (tid < 8) ? rs[tid] : 0.f;
        sq = (tid < 8) ? rq[tid] : 0.f;
        #pragma unroll
        for (int off = 4; off; off >>= 1) {
            s  += __shfl_xor_sync(0xffffffffu, s,  off);
            sq += __shfl_xor_sync(0xffffffffu, sq, off);
        }
        if (tid == 0) { rs[0] = s; rq[0] = sq; }
    }
    __syncthreads();
    float mu  = rs[0] * (1.0f/DMODEL);
    float var = rq[0] * (1.0f/DMODEL) - mu*mu;
    float r   = rsqrtf(var + 1e-5f);
    int k0 = tid*4;
    float o[4] = {v.x, v.y, v.z, v.w};
    unsigned hs[4], ls[4];
    #pragma unroll
    for (int i = 0; i < 4; i++) {
        int c = k0 + i;
        float val = (o[i] - mu) * r * g[c] + b[c];
        if (fmt == 0) {
            __nv_bfloat16 h = __float2bfloat16(val);
            __nv_bfloat16 l = __float2bfloat16(val - __bfloat162float(h));
            hs[i] = __bfloat16_as_ushort(h);
            ls[i] = __bfloat16_as_ushort(l);
        } else {
            __half h = __float2half(val);
            __half l = __float2half(val - __half2float(h));
            hs[i] = __half_as_ushort(h);
            ls[i] = __half_as_ushort(l);
        }
    }
    int kc = k0 >> 6, c = k0 & 63;
    size_t tb = ((size_t)(row >> 7) * 16 + kc) * 8192;
    uint32_t bo = SWZ((uint32_t)(row & 127)*128 + (uint32_t)c*2);
    uint2 uh = { hs[0] | (hs[1] << 16), hs[2] | (hs[3] << 16) };
    uint2 ul = { ls[0] | (ls[1] << 16), ls[2] | (ls[3] << 16) };
    *(uint2*)((char*)(ohi + tb) + bo) = uh;
    *(uint2*)((char*)(olo + tb) + bo) = ul;
}

// ---------------------------------------------------------------------------
// mma.sync GEMM (bf16 3-term), 3-stage cp.async pipeline.
// 512 threads = 16 warps (4x4), warp tile 32x32.
// mode 0: C fp32   2: C fp32 +bias +resid
// mode 3: gelu(+bias) -> Ohi/Olo as *fp16* hi/lo A tiles (for fp16 MLP2)
// mode 4: QKV -> attention tiles: Q/K [row][d], V transposed [d][key], bf16 hi/lo
// ---------------------------------------------------------------------------
#define GEMM_SMEM 196608

__global__ __launch_bounds__(512, 1)
void gemm_mma(const uint4* __restrict__ Ahi, const uint4* __restrict__ Alo,
              const uint4* __restrict__ Bhi, const uint4* __restrict__ Blo,
              const float* __restrict__ bias, const float* __restrict__ resid,
              float* __restrict__ Cf,
              __nv_bfloat16* __restrict__ Ohi, __nv_bfloat16* __restrict__ Olo,
              int N, int K, int mode)
{
    extern __shared__ char sb[];
    uint32_t sbase = smem_u32(sb);
    int tid = threadIdx.x, wid = tid >> 5, lane = tid & 31;
    int nt = blockIdx.x, mt = blockIdx.y;
    int NC = K >> 6;
    int wm = wid & 3, wn = wid >> 2;

    const uint4* gA0h = Ahi + (size_t)mt * NC * 1024;
    const uint4* gA0l = Alo + (size_t)mt * NC * 1024;
    const uint4* gB0h = Bhi + (size_t)nt * NC * 1024;
    const uint4* gB0l = Blo + (size_t)nt * NC * 1024;

    float acc[2][4][4];
    #pragma unroll
    for (int i = 0; i < 2; i++)
        #pragma unroll
        for (int j = 0; j < 4; j++)
            #pragma unroll
            for (int q = 0; q < 4; q++) acc[i][j][q] = 0.f;

    auto load_chunk = [&](int c, int s) {
        uint32_t sA = sbase + s*65536;
        const uint4* ah = gA0h + (size_t)c*1024;
        const uint4* al = gA0l + (size_t)c*1024;
        const uint4* bh = gB0h + (size_t)c*1024;
        const uint4* bl = gB0l + (size_t)c*1024;
        #pragma unroll
        for (int i = 0; i < 2; i++) {
            int idx = tid + i*512;
            cp16(sA +         idx*16, ah + idx);
            cp16(sA + 16384 + idx*16, al + idx);
            cp16(sA + 32768 + idx*16, bh + idx);
            cp16(sA + 49152 + idx*16, bl + idx);
        }
    };

    load_chunk(0, 0);
    CP_COMMIT();
    if (NC > 1) { load_chunk(1, 1); CP_COMMIT(); }

    int lrow = lane & 15;
    int lkc8 = (lane >> 4) * 8;

    for (int c = 0; c < NC; c++) {
        int s = c % 3;
        if (c + 2 < NC) {
            load_chunk(c + 2, (c + 2) % 3);
            CP_COMMIT();
            CP_WAIT(2);
        } else if (c + 1 < NC) {
            CP_WAIT(1);
        } else {
            CP_WAIT(0);
        }
        __syncthreads();

        uint32_t sAh = sbase + s*65536;
        uint32_t sAl = sAh + 16384;
        uint32_t sBh = sAh + 32768;
        uint32_t sBl = sAh + 49152;

        #pragma unroll
        for (int ks = 0; ks < 4; ks++) {
            int k0 = ks*16;
            uint32_t ah[2][4], al[2][4];
            #pragma unroll
            for (int tm = 0; tm < 2; tm++) {
                uint32_t off = SWZ((uint32_t)(wm*32 + tm*16 + lrow)*128
                                   + (uint32_t)(k0 + lkc8)*2);
                LDSM4(ah[tm], sAh + off);
                LDSM4(al[tm], sAl + off);
            }
            uint32_t bh[2][4], bl[2][4];
            #pragma unroll
            for (int g = 0; g < 2; g++) {
                uint32_t off = SWZ((uint32_t)(wn*32 + g*16 + lrow)*128
                                   + (uint32_t)(k0 + lkc8)*2);
                LDSM4(bh[g], sBh + off);
                LDSM4(bl[g], sBl + off);
            }
            #pragma unroll
            for (int tm = 0; tm < 2; tm++)
                #pragma unroll
                for (int g = 0; g < 2; g++) {
                    MMA16816(acc[tm][2*g  ], ah[tm], bh[g][0], bh[g][2]);
                    MMA16816(acc[tm][2*g+1], ah[tm], bh[g][1], bh[g][3]);
                }
            #pragma unroll
            for (int tm = 0; tm < 2; tm++)
                #pragma unroll
                for (int g = 0; g < 2; g++) {
                    MMA16816(acc[tm][2*g  ], ah[tm], bl[g][0], bl[g][2]);
                    MMA16816(acc[tm][2*g+1], ah[tm], bl[g][1], bl[g][3]);
                }
            #pragma unroll
            for (int tm = 0; tm < 2; tm++)
                #pragma unroll
                for (int g = 0; g < 2; g++) {
                    MMA16816(acc[tm][2*g  ], al[tm], bh[g][0], bh[g][2]);
                    MMA16816(acc[tm][2*g+1], al[tm], bh[g][1], bh[g][3]);
                }
        }
    }

    // ---- epilogue ----
    int gr = lane >> 2, gc = lane & 3;
    #pragma unroll
    for (int tm = 0; tm < 2; tm++) {
        #pragma unroll
        for (int tn = 0; tn < 4; tn++) {
            float* a = acc[tm][tn];
            int rIn0 = wm*32 + tm*16 + gr;
            int col  = nt*128 + wn*32 + tn*8 + gc*2;
            if (mode == 3) {
                int kc = col >> 6, cc = col & 63;
                size_t tb = ((size_t)mt * (N >> 6) + kc) * 8192;
                #pragma unroll
                for (int hhalf = 0; hhalf < 2; hhalf++) {
                    int rIn = rIn0 + hhalf*8;
                    float v0 = a[hhalf*2]     + bias[col];
                    float v1 = a[hhalf*2 + 1] + bias[col + 1];
                    v0 = 0.5f * v0 * (1.0f + erff(v0 * 0.70710678118654752f));
                    v1 = 0.5f * v1 * (1.0f + erff(v1 * 0.70710678118654752f));
                    uint32_t uh, ul;
                    pack2h(v0, v1, uh, ul);            // fp16 hi/lo for MLP2
                    uint32_t bo = SWZ((uint32_t)rIn*128 + (uint32_t)cc*2);
                    *(uint32_t*)((char*)(Ohi + tb) + bo) = uh;
                    *(uint32_t*)((char*)(Olo + tb) + bo) = ul;
                }
            } else if (mode == 4) {
                int sect = col >> 10;          // 0=Q, 1=K, 2=V
                int df   = col & 1023;
                int hh2  = df >> 6;            // head
                int cc   = df & 63;            // d within head
                #pragma unroll
                for (int hhalf = 0; hhalf < 2; hhalf++) {
                    int row = mt*128 + rIn0 + hhalf*8;     // token
                    int bq = row >> 10;
                    int tt = (row >> 6) & 15;              // tile index
                    int r  = row & 63;                     // row within tile
                    int bh = bq*NHEAD + hh2;
                    size_t tbase = (size_t)sect * QS1 + ((size_t)(bh*16 + tt))*4096;
                    float v0 = a[hhalf*2], v1 = a[hhalf*2 + 1];
                    uint32_t uh, ul;
                    pack2(v0, v1, uh, ul);
                    if (sect < 2) {
                        uint32_t bo = SWZ((uint32_t)r*128 + (uint32_t)cc*2);
                        *(uint32_t*)((char*)(Ohi + tbase) + bo) = uh;
                        *(uint32_t*)((char*)(Olo + tbase) + bo) = ul;
                    } else {
                        uint32_t bo0 = SWZ((uint32_t)cc*128 + (uint32_t)r*2);
                        uint32_t bo1 = SWZ((uint32_t)(cc+1)*128 + (uint32_t)r*2);
                        *(uint16_t*)((char*)(Ohi + tbase) + bo0) = (uint16_t)(uh & 0xffff);
                        *(uint16_t*)((char*)(Ohi + tbase) + bo1) = (uint16_t)(uh >> 16);
                        *(uint16_t*)((char*)(Olo + tbase) + bo0) = (uint16_t)(ul & 0xffff);
                        *(uint16_t*)((char*)(Olo + tbase) + bo1) = (uint16_t)(ul >> 16);
                    }
                }
            } else {
                #pragma unroll
                for (int hhalf = 0; hhalf < 2; hhalf++) {
                    int row = mt*128 + rIn0 + hhalf*8;
                    float v0 = a[hhalf*2], v1 = a[hhalf*2 + 1];
                    if (mode == 2) {
                        v0 += bias[col]     + resid[(size_t)row*N + col];
                        v1 += bias[col + 1] + resid[(size_t)row*N + col + 1];
                    }
                    float2 o = {v0, v1};
                    *(float2*)(Cf + (size_t)row*N + col) = o;
                }
            }
        }
    }
}

// ---------------------------------------------------------------------------
// fp16 GEMM: C = A x W.  A = fp16 (hi [+ lo if terms==2]), B = fp16 single.
// terms: 1 or 2 MMAs per (m,n,k).  mode 0: plain fp32 C;  2: +bias +resid.
// ---------------------------------------------------------------------------
#define GEMMF16_SMEM 147456

__global__ __launch_bounds__(512, 1)
void gemm_f16(const uint4* __restrict__ Ahi, const uint4* __restrict__ Alo,
              const uint4* __restrict__ B16,
              const float* __restrict__ bias, const float* __restrict__ resid,
              float* __restrict__ Cf, int N, int K, int terms, int mode)
{
    extern __shared__ char sb[];
    uint32_t sbase = smem_u32(sb);
    int tid = threadIdx.x, wid = tid >> 5, lane = tid & 31;
    int nt = blockIdx.x, mt = blockIdx.y;
    int NC = K >> 6;
    int wm = wid & 3, wn = wid >> 2;

    const uint4* gAh = Ahi + (size_t)mt * NC * 1024;
    const uint4* gAl = Alo + (size_t)mt * NC * 1024;
    const uint4* gB  = B16 + (size_t)nt * NC * 1024;

    float acc[2][4][4];
    #pragma unroll
    for (int i = 0; i < 2; i++)
        #pragma unroll
        for (int j = 0; j < 4; j++)
            #pragma unroll
            for (int q = 0; q < 4; q++) acc[i][j][q] = 0.f;

    auto load_chunk = [&](int c, int s) {
        uint32_t sA = sbase + s*49152;
        const uint4* ah = gAh + (size_t)c*1024;
        const uint4* al = gAl + (size_t)c*1024;
        const uint4* bb = gB  + (size_t)c*1024;
        #pragma unroll
        for (int i = 0; i < 2; i++) {
            int idx = tid + i*512;
            cp16(sA +         idx*16, ah + idx);
            if (terms == 2) cp16(sA + 16384 + idx*16, al + idx);
            cp16(sA + 32768 + idx*16, bb + idx);
        }
    };

    load_chunk(0, 0);
    CP_COMMIT();
    if (NC > 1) { load_chunk(1, 1); CP_COMMIT(); }

    int lrow = lane & 15;
    int lkc8 = (lane >> 4) * 8;

    for (int c = 0; c < NC; c++) {
        int s = c % 3;
        if (c + 2 < NC) {
            load_chunk(c + 2, (c + 2) % 3);
            CP_COMMIT();
            CP_WAIT(2);
        } else if (c + 1 < NC) {
            CP_WAIT(1);
        } else {
            CP_WAIT(0);
        }
        __syncthreads();

        uint32_t sAh = sbase + s*49152;
        uint32_t sAl = sAh + 16384;
        uint32_t sB  = sAh + 32768;

        #pragma unroll
        for (int ks = 0; ks < 4; ks++) {
            int k0 = ks*16;
            uint32_t ah[2][4], al[2][4];
            #pragma unroll
            for (int tm = 0; tm < 2; tm++) {
                uint32_t off = SWZ((uint32_t)(wm*32 + tm*16 + lrow)*128
                                   + (uint32_t)(k0 + lkc8)*2);
                LDSM4(ah[tm], sAh + off);
                if (terms == 2) LDSM4(al[tm], sAl + off);
            }
            uint32_t bb[2][4];
            #pragma unroll
            for (int g = 0; g < 2; g++) {
                uint32_t off = SWZ((uint32_t)(wn*32 + g*16 + lrow)*128
                                   + (uint32_t)(k0 + lkc8)*2);
                LDSM4(bb[g], sB + off);
            }
            #pragma unroll
            for (int tm = 0; tm < 2; tm++)
                #pragma unroll
                for (int g = 0; g < 2; g++) {
                    MMAF16(acc[tm][2*g  ], ah[tm], bb[g][0], bb[g][2]);
                    MMAF16(acc[tm][2*g+1], ah[tm], bb[g][1], bb[g][3]);
                }
            if (terms == 2) {
                #pragma unroll
                for (int tm = 0; tm < 2; tm++)
                    #pragma unroll
                    for (int g = 0; g < 2; g++) {
                        MMAF16(acc[tm][2*g  ], al[tm], bb[g][0], bb[g][2]);
                        MMAF16(acc[tm][2*g+1], al[tm], bb[g][1], bb[g][3]);
                    }
            }
        }
    }

    int gr = lane >> 2, gc = lane & 3;
    #pragma unroll
    for (int tm = 0; tm < 2; tm++) {
        #pragma unroll
        for (int tn = 0; tn < 4; tn++) {
            float* a = acc[tm][tn];
            int rIn0 = wm*32 + tm*16 + gr;
            int col  = nt*128 + wn*32 + tn*8 + gc*2;
            #pragma unroll
            for (int hhalf = 0; hhalf < 2; hhalf++) {
                int row = mt*128 + rIn0 + hhalf*8;
                float v0 = a[hhalf*2], v1 = a[hhalf*2 + 1];
                if (mode == 2) {
                    v0 += bias[col]     + resid[(size_t)row*N + col];
                    v1 += bias[col + 1] + resid[(size_t)row*N + col + 1];
                }
                float2 o = {v0, v1};
                *(float2*)(Cf + (size_t)row*N + col) = o;
            }
        }
    }
}

// ---------------------------------------------------------------------------
// mma.sync causal flash attention. 128 thr (4 warps), 64x64 tiles.
// ---------------------------------------------------------------------------
#define ATTN_SMEM 81920

__global__ __launch_bounds__(128)
void attn_mma(const __nv_bfloat16* __restrict__ qkvt_hi,
              const __nv_bfloat16* __restrict__ qkvt_lo,
              __nv_bfloat16* __restrict__ yhi, __nv_bfloat16* __restrict__ ylo)
{
    extern __shared__ char sb[];
    uint32_t sbase = smem_u32(sb);
    int qt = blockIdx.x, h = blockIdx.y, b = blockIdx.z;
    int tid = threadIdx.x, w = tid >> 5, lane = tid & 31;
    int bh = b*NHEAD + h;
    int lrow = lane & 15, lkc8 = (lane >> 4) * 8;
    int gr = lane >> 2, gc = lane & 3;

    {
        const uint4* gQh = (const uint4*)(qkvt_hi + ((size_t)(bh*16 + qt))*4096);
        const uint4* gQl = (const uint4*)(qkvt_lo + ((size_t)(bh*16 + qt))*4096);
        #pragma unroll
        for (int i = 0; i < 4; i++) {
            int idx = tid + i*128;
            cp16(sbase +        idx*16, gQh + idx);
            cp16(sbase + 8192 + idx*16, gQl + idx);
        }
    }
    CP_COMMIT();

    auto load_kv = [&](int kt, int s) {
        uint32_t st = sbase + 16384 + s*32768;
        size_t toff = (size_t)(bh*16 + kt)*4096;
        const uint4* kh = (const uint4*)(qkvt_hi +   QS1 + toff);
        const uint4* kl = (const uint4*)(qkvt_lo +   QS1 + toff);
        const uint4* vh = (const uint4*)(qkvt_hi + 2*QS1 + toff);
        const uint4* vl = (const uint4*)(qkvt_lo + 2*QS1 + toff);
        #pragma unroll
        for (int i = 0; i < 4; i++) {
            int idx = tid + i*128;
            cp16(st +         idx*16, kh + idx);
            cp16(st +  8192 + idx*16, kl + idx);
            cp16(st + 16384 + idx*16, vh + idx);
            cp16(st + 24576 + idx*16, vl + idx);
        }
    };
    load_kv(0, 0);
    CP_COMMIT();
    CP_WAIT(0);
    __syncthreads();

    uint32_t qh[4][4], ql[4][4];
    #pragma unroll
    for (int kk = 0; kk < 4; kk++) {
        uint32_t off = SWZ((uint32_t)(w*16 + lrow)*128 + (uint32_t)(kk*16 + lkc8)*2);
        LDSM4(qh[kk], sbase + off);
        LDSM4(ql[kk], sbase + 8192 + off);
    }

    float oAcc[8][4];
    #pragma unroll
    for (int j = 0; j < 8; j++)
        #pragma unroll
        for (int q4 = 0; q4 < 4; q4++) oAcc[j][q4] = 0.f;
    float m0 = -1e30f, m1 = -1e30f, l0 = 0.f, l1 = 0.f;

    int qrow0 = qt*64 + w*16 + gr, qrow1 = qrow0 + 8;

    for (int kt = 0; kt <= qt; kt++) {
        int s = kt & 1;
        if (kt + 1 <= qt) {
            load_kv(kt + 1, (kt + 1) & 1);
            CP_COMMIT();
            CP_WAIT(1);
        } else {
            CP_WAIT(0);
        }
        __syncthreads();
        uint32_t sK = sbase + 16384 + s*32768;

        float sAcc[8][4];
        #pragma unroll
        for (int j = 0; j < 8; j++)
            #pragma unroll
            for (int q4 = 0; q4 < 4; q4++) sAcc[j][q4] = 0.f;

        #pragma unroll
        for (int kk = 0; kk < 4; kk++) {
            #pragma unroll
            for (int g = 0; g < 4; g++) {
                uint32_t off = SWZ((uint32_t)(g*16 + lrow)*128 + (uint32_t)(kk*16 + lkc8)*2);
                uint32_t kh4[4], kl4[4];
                LDSM4(kh4, sK + off);
                LDSM4(kl4, sK + 8192 + off);
                MMA16816(sAcc[2*g  ], qh[kk], kh4[0], kh4[2]);
                MMA16816(sAcc[2*g+1], qh[kk], kh4[1], kh4[3]);
                MMA16816(sAcc[2*g  ], qh[kk], kl4[0], kl4[2]);
                MMA16816(sAcc[2*g+1], qh[kk], kl4[1], kl4[3]);
                MMA16816(sAcc[2*g  ], ql[kk], kh4[0], kh4[2]);
                MMA16816(sAcc[2*g+1], ql[kk], kh4[1], kh4[3]);
            }
        }

        bool diag = (kt == qt);
        #pragma unroll
        for (int j = 0; j < 8; j++) {
            #pragma unroll
            for (int q4 = 0; q4 < 4; q4++) sAcc[j][q4] *= 0.125f;
            if (diag) {
                int key0 = kt*64 + j*8 + gc*2;
                if (key0     > qrow0) sAcc[j][0] = -1e30f;
                if (key0 + 1 > qrow0) sAcc[j][1] = -1e30f;
                if (key0     > qrow1) sAcc[j][2] = -1e30f;
                if (key0 + 1 > qrow1) sAcc[j][3] = -1e30f;
            }
        }

        float rm0 = -1e30f, rm1 = -1e30f;
        #pragma unroll
        for (int j = 0; j < 8; j++) {
            rm0 = fmaxf(rm0, fmaxf(sAcc[j][0], sAcc[j][1]));
            rm1 = fmaxf(rm1, fmaxf(sAcc[j][2], sAcc[j][3]));
        }
        rm0 = fmaxf(rm0, __shfl_xor_sync(0xffffffffu, rm0, 1));
        rm0 = fmaxf(rm0, __shfl_xor_sync(0xffffffffu, rm0, 2));
        rm1 = fmaxf(rm1, __shfl_xor_sync(0xffffffffu, rm1, 1));
        rm1 = fmaxf(rm1, __shfl_xor_sync(0xffffffffu, rm1, 2));

        float mn0 = fmaxf(m0, rm0), mn1 = fmaxf(m1, rm1);
        float al0 = __expf(m0 - mn0), al1 = __expf(m1 - mn1);

        float ps0 = 0.f, ps1 = 0.f;
        #pragma unroll
        for (int j = 0; j < 8; j++) {
            sAcc[j][0] = __expf(sAcc[j][0] - mn0);
            sAcc[j][1] = __expf(sAcc[j][1] - mn0);
            sAcc[j][2] = __expf(sAcc[j][2] - mn1);
            sAcc[j][3] = __expf(sAcc[j][3] - mn1);
            ps0 += sAcc[j][0] + sAcc[j][1];
            ps1 += sAcc[j][2] + sAcc[j][3];
        }
        ps0 += __shfl_xor_sync(0xffffffffu, ps0, 1);
        ps0 += __shfl_xor_sync(0xffffffffu, ps0, 2);
        ps1 += __shfl_xor_sync(0xffffffffu, ps1, 1);
        ps1 += __shfl_xor_sync(0xffffffffu, ps1, 2);

        l0 = l0*al0 + ps0;  l1 = l1*al1 + ps1;
        m0 = mn0;           m1 = mn1;
        #pragma unroll
        for (int j = 0; j < 8; j++) {
            oAcc[j][0] *= al0; oAcc[j][1] *= al0;
            oAcc[j][2] *= al1; oAcc[j][3] *= al1;
        }

        #pragma unroll
        for (int kk2 = 0; kk2 < 4; kk2++) {
            uint32_t ph[4], pl[4];
            pack2(sAcc[2*kk2  ][0], sAcc[2*kk2  ][1], ph[0], pl[0]);
            pack2(sAcc[2*kk2  ][2], sAcc[2*kk2  ][3], ph[1], pl[1]);
            pack2(sAcc[2*kk2+1][0], sAcc[2*kk2+1][1], ph[2], pl[2]);
            pack2(sAcc[2*kk2+1][2], sAcc[2*kk2+1][3], ph[3], pl[3]);
            #pragma unroll
            for (int g = 0; g < 4; g++) {
                uint32_t off = SWZ((uint32_t)(g*16 + lrow)*128 + (uint32_t)(kk2*16 + lkc8)*2);
                uint32_t vh4[4], vl4[4];
                LDSM4(vh4, sK + 16384 + off);
                LDSM4(vl4, sK + 24576 + off);
                MMA16816(oAcc[2*g  ], ph, vh4[0], vh4[2]);
                MMA16816(oAcc[2*g+1], ph, vh4[1], vh4[3]);
                MMA16816(oAcc[2*g  ], ph, vl4[0], vl4[2]);
                MMA16816(oAcc[2*g+1], ph, vl4[1], vl4[3]);
                MMA16816(oAcc[2*g  ], pl, vh4[0], vh4[2]);
                MMA16816(oAcc[2*g+1], pl, vh4[1], vh4[3]);
            }
        }
        __syncthreads();
    }

    float inv0 = 1.0f / l0, inv1 = 1.0f / l1;
    int mtok0 = b*SEQ + qt*64 + w*16 + gr;
    size_t tb = ((size_t)(mtok0 >> 7) * 16 + h) * 8192;
    #pragma unroll
    for (int g = 0; g < 8; g++) {
        int cc = g*8 + gc*2;
        uint32_t uh0, ul0, uh1, ul1;
        pack2(oAcc[g][0]*inv0, oAcc[g][1]*inv0, uh0, ul0);
        pack2(oAcc[g][2]*inv1, oAcc[g][3]*inv1, uh1, ul1);
        uint32_t bo0 = SWZ((uint32_t)(mtok0 & 127)*128 + (uint32_t)cc*2);
        uint32_t bo1 = SWZ((uint32_t)((mtok0 + 8) & 127)*128 + (uint32_t)cc*2);
        *(uint32_t*)((char*)(yhi + tb) + bo0) = uh0;
        *(uint32_t*)((char*)(ylo + tb) + bo0) = ul0;
        *(uint32_t*)((char*)(yhi + tb) + bo1) = uh1;
        *(uint32_t*)((char*)(ylo + tb) + bo1) = ul1;
    }
}

// ---------------------------------------------------------------------------
// launch
// ---------------------------------------------------------------------------
extern "C" void kernel_launch(void* const* d_in, const int* in_sizes, int n_in,
                              void* d_out, int out_size)
{
    const float* states     = (const float*)d_in[0];
    const int*   timesteps  = (const int*)  d_in[1];
    const float* se_w1 = (const float*)d_in[2];
    const float* se_b1 = (const float*)d_in[3];
    const float* se_w2 = (const float*)d_in[4];
    const float* se_b2 = (const float*)d_in[5];
    const float* se_w3 = (const float*)d_in[6];
    const float* se_b3 = (const float*)d_in[7];
    const float* pos_emb = (const float*)d_in[8];
    const float* gpe     = (const float*)d_in[9];
    const float* ln1_g = (const float*)d_in[10];
    const float* ln1_b = (const float*)d_in[11];
    const float* Wq = (const float*)d_in[12];
    const float* Wk = (const float*)d_in[13];
    const float* Wv = (const float*)d_in[14];
    const float* Wp = (const float*)d_in[15];
    const float* bp = (const float*)d_in[16];
    const float* ln2_g = (const float*)d_in[17];
    const float* ln2_b = (const float*)d_in[18];
    const float* W1 = (const float*)d_in[19];
    const float* b1 = (const float*)d_in[20];
    const float* W2 = (const float*)d_in[21];
    const float* b2 = (const float*)d_in[22];
    const float* lnf_g = (const float*)d_in[23];
    const float* lnf_b = (const float*)d_in[24];
    const float* head_w = (const float*)d_in[25];

    float *x;
    __nv_bfloat16 *hnh, *hnl, *yh, *yl, *mh, *ml, *wh, *wl, *qth, *qtl;
    __half *w16, *w16w2;
    cudaGetSymbolAddress((void**)&x,   g_x);
    cudaGetSymbolAddress((void**)&hnh, g_hn_hi);
    cudaGetSymbolAddress((void**)&hnl, g_hn_lo);
    cudaGetSymbolAddress((void**)&yh,  g_y_hi);
    cudaGetSymbolAddress((void**)&yl,  g_y_lo);
    cudaGetSymbolAddress((void**)&mh,  g_mlp_hi);
    cudaGetSymbolAddress((void**)&ml,  g_mlp_lo);
    cudaGetSymbolAddress((void**)&wh,  g_w_hi);
    cudaGetSymbolAddress((void**)&wl,  g_w_lo);
    cudaGetSymbolAddress((void**)&qth, g_qkvt_hi);
    cudaGetSymbolAddress((void**)&qtl, g_qkvt_lo);
    cudaGetSymbolAddress((void**)&w16, g_w16);
    cudaGetSymbolAddress((void**)&w16w2, g_w16w2);

    cudaFuncSetAttribute(gemm_mma, cudaFuncAttributeMaxDynamicSharedMemorySize, GEMM_SMEM);
    cudaFuncSetAttribute(gemm_f16, cudaFuncAttributeMaxDynamicSharedMemorySize, GEMMF16_SMEM);
    cudaFuncSetAttribute(attn_mma, cudaFuncAttributeMaxDynamicSharedMemorySize, ATTN_SMEM);

    convert_all<<<10144, 256>>>(Wq, Wk, Wv, Wp, W1, W2, head_w, wh, wl, w16, w16w2);
    embed_kernel<<<NTOK, 256>>>(states, timesteps, se_w1, se_b1, se_w2, se_b2,
                                se_w3, se_b3, pos_emb, gpe, x);

    const size_t LW = LWq, MDD = MDDq;
    dim3 gQKV(24, 32), gDD(8, 32), gD4(32, 32), gHead(250, 32);
    dim3 gAttn(SEQ/64, NHEAD, BATCH);

    for (int l = 0; l < NLAYER; l++) {
        size_t wb = (size_t)l * LW;
        ln_hilo_kernel<<<NTOK, 256>>>(x, ln1_g + l*DMODEL, ln1_b + l*DMODEL, hnh, hnl, 0);
        gemm_mma<<<gQKV, 512, GEMM_SMEM>>>((uint4*)hnh, (uint4*)hnl,
            (uint4*)(wh + wb), (uint4*)(wl + wb),
            nullptr, nullptr, nullptr, qth, qtl, 3*DMODEL, 1024, 4);
        attn_mma<<<gAttn, 128, ATTN_SMEM>>>(qth, qtl, yh, yl);
        gemm_mma<<<gDD, 512, GEMM_SMEM>>>((uint4*)yh, (uint4*)yl,
            (uint4*)(wh + wb + 3*MDD), (uint4*)(wl + wb + 3*MDD),
            bp + l*DMODEL, x, x, nullptr, nullptr, 1024, 1024, 2);
        ln_hilo_kernel<<<NTOK, 256>>>(x, ln2_g + l*DMODEL, ln2_b + l*DMODEL, hnh, hnl, 0);
        // MLP1: bf16 3-term, GELU epilogue -> fp16 hi/lo tiles
        gemm_mma<<<gD4, 512, GEMM_SMEM>>>((uint4*)hnh, (uint4*)hnl,
            (uint4*)(wh + wb + 4*MDD), (uint4*)(wl + wb + 4*MDD),
            b1 + (size_t)l*4*DMODEL, nullptr, nullptr, mh, ml, 4096, 1024, 3);
        // MLP2: fp16 2-term x 1-term, bias+resid epilogue
        gemm_f16<<<gDD, 512, GEMMF16_SMEM>>>((uint4*)mh, (uint4*)ml,
            (uint4*)(w16w2 + (size_t)l*4194304ull),
            b2 + l*DMODEL, x, x, 1024, 4096, 2, 2);
    }

    // final LN fp16 hi/lo; head GEMM fp16 1-term x 1-term
    ln_hilo_kernel<<<NTOK, 256>>>(x, lnf_g, lnf_b, hnh, hnl, 1);
    gemm_f16<<<gHead, 512, GEMMF16_SMEM>>>((uint4*)hnh, (uint4*)hnl,
        (uint4*)w16, nullptr, nullptr, (float*)d_out, 32000, 1024, 1, 0);
}

// round 17
// speedup vs baseline: 4.5071x; 1.0647x over previous
#include <cuda_runtime.h>
#include <cuda_bf16.h>
#include <cuda_fp16.h>
#include <math.h>
#include <stdint.h>

#define BATCH 4
#define SEQ   1024
#define DMODEL 1024
#define NHEAD 16
#define NLAYER 4
#define VOCAB 32000
#define DHEAD 64
#define NTOK (BATCH*SEQ)   // 4096

// SW128 swizzle (Swizzle<3,4,3>)
#define SWZ(b) ((b) ^ ((((unsigned)(b)) >> 3) & 0x70u))

// ---------------------------------------------------------------------------
// PTX helpers (portable: sm_80+ PTX, runs on sm_103a)
// ---------------------------------------------------------------------------
__device__ __forceinline__ uint32_t smem_u32(const void* p) {
    uint32_t a;
    asm("{ .reg .u64 t; cvta.to.shared.u64 t, %1; cvt.u32.u64 %0, t; }" : "=r"(a) : "l"(p));
    return a;
}
__device__ __forceinline__ void cp16(uint32_t dst, const void* src) {
    asm volatile("cp.async.cg.shared.global [%0], [%1], 16;" :: "r"(dst), "l"(src));
}
#define CP_COMMIT() asm volatile("cp.async.commit_group;" ::: "memory")
#define CP_WAIT(n)  asm volatile("cp.async.wait_group %0;" :: "n"(n) : "memory")

#define LDSM4(r, addr) \
    asm volatile("ldmatrix.sync.aligned.m8n8.x4.shared.b16 {%0,%1,%2,%3}, [%4];" \
        : "=r"((r)[0]), "=r"((r)[1]), "=r"((r)[2]), "=r"((r)[3]) : "r"(addr))

#define MMA16816(d, a, b0, b1) \
    asm volatile("mma.sync.aligned.m16n8k16.row.col.f32.bf16.bf16.f32 " \
        "{%0,%1,%2,%3}, {%4,%5,%6,%7}, {%8,%9}, {%0,%1,%2,%3};" \
        : "+f"((d)[0]), "+f"((d)[1]), "+f"((d)[2]), "+f"((d)[3]) \
        : "r"((a)[0]), "r"((a)[1]), "r"((a)[2]), "r"((a)[3]), "r"(b0), "r"(b1))

#define MMAF16(d, a, b0, b1) \
    asm volatile("mma.sync.aligned.m16n8k16.row.col.f32.f16.f16.f32 " \
        "{%0,%1,%2,%3}, {%4,%5,%6,%7}, {%8,%9}, {%0,%1,%2,%3};" \
        : "+f"((d)[0]), "+f"((d)[1]), "+f"((d)[2]), "+f"((d)[3]) \
        : "r"((a)[0]), "r"((a)[1]), "r"((a)[2]), "r"((a)[3]), "r"(b0), "r"(b1))

__device__ __forceinline__ void pack2(float v0, float v1, uint32_t& hi, uint32_t& lo) {
    __nv_bfloat16 h0 = __float2bfloat16(v0);
    __nv_bfloat16 l0 = __float2bfloat16(v0 - __bfloat162float(h0));
    __nv_bfloat16 h1 = __float2bfloat16(v1);
    __nv_bfloat16 l1 = __float2bfloat16(v1 - __bfloat162float(h1));
    hi = (uint32_t)__bfloat16_as_ushort(h0) | ((uint32_t)__bfloat16_as_ushort(h1) << 16);
    lo = (uint32_t)__bfloat16_as_ushort(l0) | ((uint32_t)__bfloat16_as_ushort(l1) << 16);
}

__device__ __forceinline__ void pack2h(float v0, float v1, uint32_t& hi, uint32_t& lo) {
    __half h0 = __float2half(v0);
    __half l0 = __float2half(v0 - __half2float(h0));
    __half h1 = __float2half(v1);
    __half l1 = __float2half(v1 - __half2float(h1));
    hi = (uint32_t)__half_as_ushort(h0) | ((uint32_t)__half_as_ushort(h1) << 16);
    lo = (uint32_t)__half_as_ushort(l0) | ((uint32_t)__half_as_ushort(l1) << 16);
}

// ---------------------------------------------------------------------------
// scratch (device globals)
// ---------------------------------------------------------------------------
__device__ float g_x  [NTOK*DMODEL];
// hn buffers: bf16 hi/lo for LN1 (QKV), fp16 hi/lo bits for LN2/LNf
__device__ __nv_bfloat16 g_hn_hi[NTOK*DMODEL];
__device__ __nv_bfloat16 g_hn_lo[NTOK*DMODEL];
__device__ __nv_bfloat16 g_y_hi [NTOK*DMODEL];
__device__ __nv_bfloat16 g_y_lo [NTOK*DMODEL];
// mlp buffers hold fp16 bits
__device__ __nv_bfloat16 g_mlp_hi[NTOK*4*DMODEL];
__device__ __nv_bfloat16 g_mlp_lo[NTOK*4*DMODEL];
// attention operand tiles: Q @0, K @QS1, VT @2*QS1
#define QS1 4194304ull
__device__ __nv_bfloat16 g_qkvt_hi[3*QS1];
__device__ __nv_bfloat16 g_qkvt_lo[3*QS1];
// bf16 hi/lo weights (QKV + proj; W1 region now unused but offsets kept)
#define WTOTAL 50331648ull
#define LWq 12582912ull
#define MDDq 1048576ull
__device__ __nv_bfloat16 g_w_hi[WTOTAL];
__device__ __nv_bfloat16 g_w_lo[WTOTAL];
// fp16-single weights: head, W2 (4 layers), W1 (4 layers)
__device__ __half g_w16  [32768000ull];
__device__ __half g_w16w2[16777216ull];
__device__ __half g_w16w1[16777216ull];

// ---------------------------------------------------------------------------
// single-launch weight convert
// ---------------------------------------------------------------------------
__global__ __launch_bounds__(256)
void convert_all(const float* __restrict__ Wq, const float* __restrict__ Wk,
                 const float* __restrict__ Wv, const float* __restrict__ Wp,
                 const float* __restrict__ W1, const float* __restrict__ W2,
                 const float* __restrict__ Whead,
                 __nv_bfloat16* __restrict__ wh, __nv_bfloat16* __restrict__ wl,
                 __half* __restrict__ w16, __half* __restrict__ w16w2,
                 __half* __restrict__ w16w1)
{
    int bid = blockIdx.x;
    int t = threadIdx.x;
    int n_loc = t & 127, grp = t >> 7;

    // ---- fp16-single conversions ----
    const float* Wf = nullptr; __half* dst16 = nullptr;
    int Nf = 0, ntf = 0, kcf = 0; size_t dstBlk16 = 0;
    if (bid >= 6144) {                       // head [1024 -> 32000]
        int i = bid - 6144;
        ntf = i >> 4; kcf = i & 15;
        Wf = Whead; Nf = 32000; dst16 = w16;
        dstBlk16 = ((size_t)ntf*16 + kcf)*8192;
    } else {
        int l = bid / 1536, r = bid % 1536;
        if (r >= 1024) {                     // W2 [4096 -> 1024]
            int i = r - 1024;
            ntf = i >> 6; kcf = i & 63;
            Wf = W2 + (size_t)l*DMODEL*4*DMODEL; Nf = 1024; dst16 = w16w2;
            dstBlk16 = (size_t)l*4194304ull + ((size_t)ntf*64 + kcf)*8192;
        } else if (r >= 512) {               // W1 [1024 -> 4096]
            int i = r - 512;
            ntf = i >> 4; kcf = i & 15;
            Wf = W1 + (size_t)l*DMODEL*4*DMODEL; Nf = 4096; dst16 = w16w1;
            dstBlk16 = (size_t)l*4194304ull + ((size_t)ntf*16 + kcf)*8192;
        }
    }
    if (Wf) {
        uint4* o4 = (uint4*)(dst16 + dstBlk16);
        #pragma unroll
        for (int g = 0; g < 4; g++) {
            int kg = grp + g*2;
            int k0 = kcf*64 + kg*8;
            unsigned hs[8];
            #pragma unroll
            for (int i2 = 0; i2 < 8; i2++) {
                float v = Wf[(size_t)(k0 + i2) * Nf + ntf*128 + n_loc];
                hs[i2] = __half_as_ushort(__float2half(v));
            }
            uint4 uh;
            uh.x = hs[0] | (hs[1] << 16); uh.y = hs[2] | (hs[3] << 16);
            uh.z = hs[4] | (hs[5] << 16); uh.w = hs[6] | (hs[7] << 16);
            uint32_t bo = SWZ((uint32_t)n_loc*128 + (uint32_t)kg*16);
            o4[bo >> 4] = uh;
        }
        return;
    }

    // ---- bf16 hi/lo conversions (QKV fused, proj) ----
    int l = bid / 1536, r = bid % 1536;
    const float* W; int N, kc, nt;
    size_t dstBlk;
    {
        size_t wb = (size_t)l * LWq;
        if (r < 384) {                       // fused QKV
            int nt_f = r >> 4; kc = r & 15;
            int sel = nt_f >> 3; nt = nt_f & 7;
            W = (sel == 0 ? Wq : (sel == 1 ? Wk : Wv)) + (size_t)l*DMODEL*DMODEL;
            N = 1024;
            dstBlk = wb + ((size_t)nt_f*16 + kc)*8192;
        } else {                             // proj
            int i = r - 384; nt = i >> 4; kc = i & 15;
            W = Wp + (size_t)l*DMODEL*DMODEL; N = 1024;
            dstBlk = wb + 3*MDDq + ((size_t)nt*16 + kc)*8192;
        }
    }

    uint4* hi4 = (uint4*)(wh + dstBlk);
    uint4* lo4 = (uint4*)(wl + dstBlk);
    #pragma unroll
    for (int g = 0; g < 4; g++) {
        int kg = grp + g*2;
        int k0 = kc*64 + kg*8;
        unsigned hs[8], ls[8];
        #pragma unroll
        for (int i = 0; i < 8; i++) {
            float v = W[(size_t)(k0 + i) * N + nt*128 + n_loc];
            __nv_bfloat16 h = __float2bfloat16(v);
            __nv_bfloat16 l2 = __float2bfloat16(v - __bfloat162float(h));
            hs[i] = __bfloat16_as_ushort(h);
            ls[i] = __bfloat16_as_ushort(l2);
        }
        uint4 uh, ul;
        uh.x = hs[0] | (hs[1] << 16); uh.y = hs[2] | (hs[3] << 16);
        uh.z = hs[4] | (hs[5] << 16); uh.w = hs[6] | (hs[7] << 16);
        ul.x = ls[0] | (ls[1] << 16); ul.y = ls[2] | (ls[3] << 16);
        ul.z = ls[4] | (ls[5] << 16); ul.w = ls[6] | (ls[7] << 16);
        uint32_t bo = SWZ((uint32_t)n_loc*128 + (uint32_t)kg*16);
        hi4[bo >> 4] = uh;
        lo4[bo >> 4] = ul;
    }
}

// ---------------------------------------------------------------------------
// embed (fp32 residual stream)
// ---------------------------------------------------------------------------
__global__ __launch_bounds__(256)
void embed_kernel(const float* __restrict__ states, const int* __restrict__ timesteps,
                  const float* __restrict__ w1, const float* __restrict__ b1,
                  const float* __restrict__ w2, const float* __restrict__ b2,
                  const float* __restrict__ w3, const float* __restrict__ b3,
                  const float* __restrict__ pos_emb, const float* __restrict__ gpe,
                  float* __restrict__ x)
{
    int token = blockIdx.x;
    int b = token / SEQ, s = token % SEQ;
    __shared__ float st[4], h1[16], h2[16];
    int tid = threadIdx.x;
    if (tid < 4) st[tid] = states[token*4 + tid];
    __syncthreads();
    if (tid < 16) {
        float a = b1[tid];
        #pragma unroll
        for (int i = 0; i < 4; i++) a += st[i] * w1[i*16 + tid];
        h1[tid] = fmaxf(a, 0.0f);
    }
    __syncthreads();
    if (tid < 16) {
        float a = b2[tid];
        #pragma unroll
        for (int i = 0; i < 16; i++) a += h1[i] * w2[i*16 + tid];
        h2[tid] = fmaxf(a, 0.0f);
    }
    __syncthreads();
    int t = timesteps[b];
    for (int d = tid; d < DMODEL; d += blockDim.x) {
        float a = b3[d];
        #pragma unroll
        for (int i = 0; i < 16; i++) a += h2[i] * w3[i*DMODEL + d];
        x[(size_t)token*DMODEL + d] = tanhf(a) + gpe[(size_t)t*DMODEL + d]
                                      + pos_emb[(size_t)s*DMODEL + d];
    }
}

// ---------------------------------------------------------------------------
// layernorm: fp32 in -> hi/lo swizzled A-tiles (K=1024)
// fmt 0: bf16 hi/lo    fmt 1: fp16 hi/lo
// ---------------------------------------------------------------------------
__global__ __launch_bounds__(256)
void ln_hilo_kernel(const float* __restrict__ X,
                    const float* __restrict__ g, const float* __restrict__ b,
                    __nv_bfloat16* __restrict__ ohi, __nv_bfloat16* __restrict__ olo,
                    int fmt)
{
    int row = blockIdx.x;
    const float* xr = X + (size_t)row*DMODEL;
    int tid = threadIdx.x;
    float4 v = *(const float4*)(xr + tid*4);
    float s = v.x+v.y+v.z+v.w;
    float sq = v.x*v.x + v.y*v.y + v.z*v.z + v.w*v.w;
    __shared__ float rs[8], rq[8];
    #pragma unroll
    for (int off = 16; off; off >>= 1) {
        s  += __shfl_xor_sync(0xffffffffu, s,  off);
        sq += __shfl_xor_sync(0xffffffffu, sq, off);
    }
    if ((tid & 31) == 0) { rs[tid>>5] = s; rq[tid>>5] = sq; }
    __syncthreads();
    if (tid < 32) {
        s  = (tid < 8) ? rs[tid] : 0.f;
        sq = (tid < 8) ? rq[tid] : 0.f;
        #pragma unroll
        for (int off = 4; off; off >>= 1) {
            s  += __shfl_xor_sync(0xffffffffu, s,  off);
            sq += __shfl_xor_sync(0xffffffffu, sq, off);
        }
        if (tid == 0) { rs[0] = s; rq[0] = sq; }
    }
    __syncthreads();
    float mu  = rs[0] * (1.0f/DMODEL);
    float var = rq[0] * (1.0f/DMODEL) - mu*mu;
    float r   = rsqrtf(var + 1e-5f);
    int k0 = tid*4;
    float o[4] = {v.x, v.y, v.z, v.w};
    unsigned hs[4], ls[4];
    #pragma unroll
    for (int i = 0; i < 4; i++) {
        int c = k0 + i;
        float val = (o[i] - mu) * r * g[c] + b[c];
        if (fmt == 0) {
            __nv_bfloat16 h = __float2bfloat16(val);
            __nv_bfloat16 l = __float2bfloat16(val - __bfloat162float(h));
            hs[i] = __bfloat16_as_ushort(h);
            ls[i] = __bfloat16_as_ushort(l);
        } else {
            __half h = __float2half(val);
            __half l = __float2half(val - __half2float(h));
            hs[i] = __half_as_ushort(h);
            ls[i] = __half_as_ushort(l);
        }
    }
    int kc = k0 >> 6, c = k0 & 63;
    size_t tb = ((size_t)(row >> 7) * 16 + kc) * 8192;
    uint32_t bo = SWZ((uint32_t)(row & 127)*128 + (uint32_t)c*2);
    uint2 uh = { hs[0] | (hs[1] << 16), hs[2] | (hs[3] << 16) };
    uint2 ul = { ls[0] | (ls[1] << 16), ls[2] | (ls[3] << 16) };
    *(uint2*)((char*)(ohi + tb) + bo) = uh;
    *(uint2*)((char*)(olo + tb) + bo) = ul;
}

// ---------------------------------------------------------------------------
// mma.sync GEMM (bf16 3-term), 3-stage cp.async pipeline.
// mode 0: C fp32   2: C fp32 +bias +resid
// mode 4: QKV -> attention tiles: Q/K [row][d], V transposed [d][key], bf16 hi/lo
// ---------------------------------------------------------------------------
#define GEMM_SMEM 196608

__global__ __launch_bounds__(512, 1)
void gemm_mma(const uint4* __restrict__ Ahi, const uint4* __restrict__ Alo,
              const uint4* __restrict__ Bhi, const uint4* __restrict__ Blo,
              const float* __restrict__ bias, const float* __restrict__ resid,
              float* __restrict__ Cf,
              __nv_bfloat16* __restrict__ Ohi, __nv_bfloat16* __restrict__ Olo,
              int N, int K, int mode)
{
    extern __shared__ char sb[];
    uint32_t sbase = smem_u32(sb);
    int tid = threadIdx.x, wid = tid >> 5, lane = tid & 31;
    int nt = blockIdx.x, mt = blockIdx.y;
    int NC = K >> 6;
    int wm = wid & 3, wn = wid >> 2;

    const uint4* gA0h = Ahi + (size_t)mt * NC * 1024;
    const uint4* gA0l = Alo + (size_t)mt * NC * 1024;
    const uint4* gB0h = Bhi + (size_t)nt * NC * 1024;
    const uint4* gB0l = Blo + (size_t)nt * NC * 1024;

    float acc[2][4][4];
    #pragma unroll
    for (int i = 0; i < 2; i++)
        #pragma unroll
        for (int j = 0; j < 4; j++)
            #pragma unroll
            for (int q = 0; q < 4; q++) acc[i][j][q] = 0.f;

    auto load_chunk = [&](int c, int s) {
        uint32_t sA = sbase + s*65536;
        const uint4* ah = gA0h + (size_t)c*1024;
        const uint4* al = gA0l + (size_t)c*1024;
        const uint4* bh = gB0h + (size_t)c*1024;
        const uint4* bl = gB0l + (size_t)c*1024;
        #pragma unroll
        for (int i = 0; i < 2; i++) {
            int idx = tid + i*512;
            cp16(sA +         idx*16, ah + idx);
            cp16(sA + 16384 + idx*16, al + idx);
            cp16(sA + 32768 + idx*16, bh + idx);
            cp16(sA + 49152 + idx*16, bl + idx);
        }
    };

    load_chunk(0, 0);
    CP_COMMIT();
    if (NC > 1) { load_chunk(1, 1); CP_COMMIT(); }

    int lrow = lane & 15;
    int lkc8 = (lane >> 4) * 8;

    for (int c = 0; c < NC; c++) {
        int s = c % 3;
        if (c + 2 < NC) {
            load_chunk(c + 2, (c + 2) % 3);
            CP_COMMIT();
            CP_WAIT(2);
        } else if (c + 1 < NC) {
            CP_WAIT(1);
        } else {
            CP_WAIT(0);
        }
        __syncthreads();

        uint32_t sAh = sbase + s*65536;
        uint32_t sAl = sAh + 16384;
        uint32_t sBh = sAh + 32768;
        uint32_t sBl = sAh + 49152;

        #pragma unroll
        for (int ks = 0; ks < 4; ks++) {
            int k0 = ks*16;
            uint32_t ah[2][4], al[2][4];
            #pragma unroll
            for (int tm = 0; tm < 2; tm++) {
                uint32_t off = SWZ((uint32_t)(wm*32 + tm*16 + lrow)*128
                                   + (uint32_t)(k0 + lkc8)*2);
                LDSM4(ah[tm], sAh + off);
                LDSM4(al[tm], sAl + off);
            }
            uint32_t bh[2][4], bl[2][4];
            #pragma unroll
            for (int g = 0; g < 2; g++) {
                uint32_t off = SWZ((uint32_t)(wn*32 + g*16 + lrow)*128
                                   + (uint32_t)(k0 + lkc8)*2);
                LDSM4(bh[g], sBh + off);
                LDSM4(bl[g], sBl + off);
            }
            #pragma unroll
            for (int tm = 0; tm < 2; tm++)
                #pragma unroll
                for (int g = 0; g < 2; g++) {
                    MMA16816(acc[tm][2*g  ], ah[tm], bh[g][0], bh[g][2]);
                    MMA16816(acc[tm][2*g+1], ah[tm], bh[g][1], bh[g][3]);
                }
            #pragma unroll
            for (int tm = 0; tm < 2; tm++)
                #pragma unroll
                for (int g = 0; g < 2; g++) {
                    MMA16816(acc[tm][2*g  ], ah[tm], bl[g][0], bl[g][2]);
                    MMA16816(acc[tm][2*g+1], ah[tm], bl[g][1], bl[g][3]);
                }
            #pragma unroll
            for (int tm = 0; tm < 2; tm++)
                #pragma unroll
                for (int g = 0; g < 2; g++) {
                    MMA16816(acc[tm][2*g  ], al[tm], bh[g][0], bh[g][2]);
                    MMA16816(acc[tm][2*g+1], al[tm], bh[g][1], bh[g][3]);
                }
        }
    }

    // ---- epilogue ----
    int gr = lane >> 2, gc = lane & 3;
    #pragma unroll
    for (int tm = 0; tm < 2; tm++) {
        #pragma unroll
        for (int tn = 0; tn < 4; tn++) {
            float* a = acc[tm][tn];
            int rIn0 = wm*32 + tm*16 + gr;
            int col  = nt*128 + wn*32 + tn*8 + gc*2;
            if (mode == 4) {
                int sect = col >> 10;          // 0=Q, 1=K, 2=V
                int df   = col & 1023;
                int hh2  = df >> 6;            // head
                int cc   = df & 63;            // d within head
                #pragma unroll
                for (int hhalf = 0; hhalf < 2; hhalf++) {
                    int row = mt*128 + rIn0 + hhalf*8;     // token
                    int bq = row >> 10;
                    int tt = (row >> 6) & 15;              // tile index
                    int r  = row & 63;                     // row within tile
                    int bh = bq*NHEAD + hh2;
                    size_t tbase = (size_t)sect * QS1 + ((size_t)(bh*16 + tt))*4096;
                    float v0 = a[hhalf*2], v1 = a[hhalf*2 + 1];
                    uint32_t uh, ul;
                    pack2(v0, v1, uh, ul);
                    if (sect < 2) {
                        uint32_t bo = SWZ((uint32_t)r*128 + (uint32_t)cc*2);
                        *(uint32_t*)((char*)(Ohi + tbase) + bo) = uh;
                        *(uint32_t*)((char*)(Olo + tbase) + bo) = ul;
                    } else {
                        uint32_t bo0 = SWZ((uint32_t)cc*128 + (uint32_t)r*2);
                        uint32_t bo1 = SWZ((uint32_t)(cc+1)*128 + (uint32_t)r*2);
                        *(uint16_t*)((char*)(Ohi + tbase) + bo0) = (uint16_t)(uh & 0xffff);
                        *(uint16_t*)((char*)(Ohi + tbase) + bo1) = (uint16_t)(uh >> 16);
                        *(uint16_t*)((char*)(Olo + tbase) + bo0) = (uint16_t)(ul & 0xffff);
                        *(uint16_t*)((char*)(Olo + tbase) + bo1) = (uint16_t)(ul >> 16);
                    }
                }
            } else {
                #pragma unroll
                for (int hhalf = 0; hhalf < 2; hhalf++) {
                    int row = mt*128 + rIn0 + hhalf*8;
                    float v0 = a[hhalf*2], v1 = a[hhalf*2 + 1];
                    if (mode == 2) {
                        v0 += bias[col]     + resid[(size_t)row*N + col];
                        v1 += bias[col + 1] + resid[(size_t)row*N + col + 1];
                    }
                    float2 o = {v0, v1};
                    *(float2*)(Cf + (size_t)row*N + col) = o;
                }
            }
        }
    }
}

// ---------------------------------------------------------------------------
// fp16 GEMM: C = A x W.  A = fp16 (hi [+ lo if terms==2]), B = fp16 single.
// mode 0: plain fp32 C   2: +bias +resid   3: gelu(+bias) -> fp16 hi/lo tiles
// ---------------------------------------------------------------------------
#define GEMMF16_SMEM 147456

__global__ __launch_bounds__(512, 1)
void gemm_f16(const uint4* __restrict__ Ahi, const uint4* __restrict__ Alo,
              const uint4* __restrict__ B16,
              const float* __restrict__ bias, const float* __restrict__ resid,
              float* __restrict__ Cf,
              __nv_bfloat16* __restrict__ Ohi, __nv_bfloat16* __restrict__ Olo,
              int N, int K, int terms, int mode)
{
    extern __shared__ char sb[];
    uint32_t sbase = smem_u32(sb);
    int tid = threadIdx.x, wid = tid >> 5, lane = tid & 31;
    int nt = blockIdx.x, mt = blockIdx.y;
    int NC = K >> 6;
    int wm = wid & 3, wn = wid >> 2;

    const uint4* gAh = Ahi + (size_t)mt * NC * 1024;
    const uint4* gAl = Alo + (size_t)mt * NC * 1024;
    const uint4* gB  = B16 + (size_t)nt * NC * 1024;

    float acc[2][4][4];
    #pragma unroll
    for (int i = 0; i < 2; i++)
        #pragma unroll
        for (int j = 0; j < 4; j++)
            #pragma unroll
            for (int q = 0; q < 4; q++) acc[i][j][q] = 0.f;

    auto load_chunk = [&](int c, int s) {
        uint32_t sA = sbase + s*49152;
        const uint4* ah = gAh + (size_t)c*1024;
        const uint4* al = gAl + (size_t)c*1024;
        const uint4* bb = gB  + (size_t)c*1024;
        #pragma unroll
        for (int i = 0; i < 2; i++) {
            int idx = tid + i*512;
            cp16(sA +         idx*16, ah + idx);
            if (terms == 2) cp16(sA + 16384 + idx*16, al + idx);
            cp16(sA + 32768 + idx*16, bb + idx);
        }
    };

    load_chunk(0, 0);
    CP_COMMIT();
    if (NC > 1) { load_chunk(1, 1); CP_COMMIT(); }

    int lrow = lane & 15;
    int lkc8 = (lane >> 4) * 8;

    for (int c = 0; c < NC; c++) {
        int s = c % 3;
        if (c + 2 < NC) {
            load_chunk(c + 2, (c + 2) % 3);
            CP_COMMIT();
            CP_WAIT(2);
        } else if (c + 1 < NC) {
            CP_WAIT(1);
        } else {
            CP_WAIT(0);
        }
        __syncthreads();

        uint32_t sAh = sbase + s*49152;
        uint32_t sAl = sAh + 16384;
        uint32_t sB  = sAh + 32768;

        #pragma unroll
        for (int ks = 0; ks < 4; ks++) {
            int k0 = ks*16;
            uint32_t ah[2][4], al[2][4];
            #pragma unroll
            for (int tm = 0; tm < 2; tm++) {
                uint32_t off = SWZ((uint32_t)(wm*32 + tm*16 + lrow)*128
                                   + (uint32_t)(k0 + lkc8)*2);
                LDSM4(ah[tm], sAh + off);
                if (terms == 2) LDSM4(al[tm], sAl + off);
            }
            uint32_t bb[2][4];
            #pragma unroll
            for (int g = 0; g < 2; g++) {
                uint32_t off = SWZ((uint32_t)(wn*32 + g*16 + lrow)*128
                                   + (uint32_t)(k0 + lkc8)*2);
                LDSM4(bb[g], sB + off);
            }
            #pragma unroll
            for (int tm = 0; tm < 2; tm++)
                #pragma unroll
                for (int g = 0; g < 2; g++) {
                    MMAF16(acc[tm][2*g  ], ah[tm], bb[g][0], bb[g][2]);
                    MMAF16(acc[tm][2*g+1], ah[tm], bb[g][1], bb[g][3]);
                }
            if (terms == 2) {
                #pragma unroll
                for (int tm = 0; tm < 2; tm++)
                    #pragma unroll
                    for (int g = 0; g < 2; g++) {
                        MMAF16(acc[tm][2*g  ], al[tm], bb[g][0], bb[g][2]);
                        MMAF16(acc[tm][2*g+1], al[tm], bb[g][1], bb[g][3]);
                    }
            }
        }
    }

    int gr = lane >> 2, gc = lane & 3;
    #pragma unroll
    for (int tm = 0; tm < 2; tm++) {
        #pragma unroll
        for (int tn = 0; tn < 4; tn++) {
            float* a = acc[tm][tn];
            int rIn0 = wm*32 + tm*16 + gr;
            int col  = nt*128 + wn*32 + tn*8 + gc*2;
            if (mode == 3) {
                int kc = col >> 6, cc = col & 63;
                size_t tb = ((size_t)mt * (N >> 6) + kc) * 8192;
                #pragma unroll
                for (int hhalf = 0; hhalf < 2; hhalf++) {
                    int rIn = rIn0 + hhalf*8;
                    float v0 = a[hhalf*2]     + bias[col];
                    float v1 = a[hhalf*2 + 1] + bias[col + 1];
                    v0 = 0.5f * v0 * (1.0f + erff(v0 * 0.70710678118654752f));
                    v1 = 0.5f * v1 * (1.0f + erff(v1 * 0.70710678118654752f));
                    uint32_t uh, ul;
                    pack2h(v0, v1, uh, ul);
                    uint32_t bo = SWZ((uint32_t)rIn*128 + (uint32_t)cc*2);
                    *(uint32_t*)((char*)(Ohi + tb) + bo) = uh;
                    *(uint32_t*)((char*)(Olo + tb) + bo) = ul;
                }
            } else {
                #pragma unroll
                for (int hhalf = 0; hhalf < 2; hhalf++) {
                    int row = mt*128 + rIn0 + hhalf*8;
                    float v0 = a[hhalf*2], v1 = a[hhalf*2 + 1];
                    if (mode == 2) {
                        v0 += bias[col]     + resid[(size_t)row*N + col];
                        v1 += bias[col + 1] + resid[(size_t)row*N + col + 1];
                    }
                    float2 o = {v0, v1};
                    *(float2*)(Cf + (size_t)row*N + col) = o;
                }
            }
        }
    }
}

// ---------------------------------------------------------------------------
// mma.sync causal flash attention. 128 thr (4 warps), 64x64 tiles.
// ---------------------------------------------------------------------------
#define ATTN_SMEM 81920

__global__ __launch_bounds__(128)
void attn_mma(const __nv_bfloat16* __restrict__ qkvt_hi,
              const __nv_bfloat16* __restrict__ qkvt_lo,
              __nv_bfloat16* __restrict__ yhi, __nv_bfloat16* __restrict__ ylo)
{
    extern __shared__ char sb[];
    uint32_t sbase = smem_u32(sb);
    int qt = blockIdx.x, h = blockIdx.y, b = blockIdx.z;
    int tid = threadIdx.x, w = tid >> 5, lane = tid & 31;
    int bh = b*NHEAD + h;
    int lrow = lane & 15, lkc8 = (lane >> 4) * 8;
    int gr = lane >> 2, gc = lane & 3;

    {
        const uint4* gQh = (const uint4*)(qkvt_hi + ((size_t)(bh*16 + qt))*4096);
        const uint4* gQl = (const uint4*)(qkvt_lo + ((size_t)(bh*16 + qt))*4096);
        #pragma unroll
        for (int i = 0; i < 4; i++) {
            int idx = tid + i*128;
            cp16(sbase +        idx*16, gQh + idx);
            cp16(sbase + 8192 + idx*16, gQl + idx);
        }
    }
    CP_COMMIT();

    auto load_kv = [&](int kt, int s) {
        uint32_t st = sbase + 16384 + s*32768;
        size_t toff = (size_t)(bh*16 + kt)*4096;
        const uint4* kh = (const uint4*)(qkvt_hi +   QS1 + toff);
        const uint4* kl = (const uint4*)(qkvt_lo +   QS1 + toff);
        const uint4* vh = (const uint4*)(qkvt_hi + 2*QS1 + toff);
        const uint4* vl = (const uint4*)(qkvt_lo + 2*QS1 + toff);
        #pragma unroll
        for (int i = 0; i < 4; i++) {
            int idx = tid + i*128;
            cp16(st +         idx*16, kh + idx);
            cp16(st +  8192 + idx*16, kl + idx);
            cp16(st + 16384 + idx*16, vh + idx);
            cp16(st + 24576 + idx*16, vl + idx);
        }
    };
    load_kv(0, 0);
    CP_COMMIT();
    CP_WAIT(0);
    __syncthreads();

    uint32_t qh[4][4], ql[4][4];
    #pragma unroll
    for (int kk = 0; kk < 4; kk++) {
        uint32_t off = SWZ((uint32_t)(w*16 + lrow)*128 + (uint32_t)(kk*16 + lkc8)*2);
        LDSM4(qh[kk], sbase + off);
        LDSM4(ql[kk], sbase + 8192 + off);
    }

    float oAcc[8][4];
    #pragma unroll
    for (int j = 0; j < 8; j++)
        #pragma unroll
        for (int q4 = 0; q4 < 4; q4++) oAcc[j][q4] = 0.f;
    float m0 = -1e30f, m1 = -1e30f, l0 = 0.f, l1 = 0.f;

    int qrow0 = qt*64 + w*16 + gr, qrow1 = qrow0 + 8;

    for (int kt = 0; kt <= qt; kt++) {
        int s = kt & 1;
        if (kt + 1 <= qt) {
            load_kv(kt + 1, (kt + 1) & 1);
            CP_COMMIT();
            CP_WAIT(1);
        } else {
            CP_WAIT(0);
        }
        __syncthreads();
        uint32_t sK = sbase + 16384 + s*32768;

        float sAcc[8][4];
        #pragma unroll
        for (int j = 0; j < 8; j++)
            #pragma unroll
            for (int q4 = 0; q4 < 4; q4++) sAcc[j][q4] = 0.f;

        #pragma unroll
        for (int kk = 0; kk < 4; kk++) {
            #pragma unroll
            for (int g = 0; g < 4; g++) {
                uint32_t off = SWZ((uint32_t)(g*16 + lrow)*128 + (uint32_t)(kk*16 + lkc8)*2);
                uint32_t kh4[4], kl4[4];
                LDSM4(kh4, sK + off);
                LDSM4(kl4, sK + 8192 + off);
                MMA16816(sAcc[2*g  ], qh[kk], kh4[0], kh4[2]);
                MMA16816(sAcc[2*g+1], qh[kk], kh4[1], kh4[3]);
                MMA16816(sAcc[2*g  ], qh[kk], kl4[0], kl4[2]);
                MMA16816(sAcc[2*g+1], qh[kk], kl4[1], kl4[3]);
                MMA16816(sAcc[2*g  ], ql[kk], kh4[0], kh4[2]);
                MMA16816(sAcc[2*g+1], ql[kk], kh4[1], kh4[3]);
            }
        }

        bool diag = (kt == qt);
        #pragma unroll
        for (int j = 0; j < 8; j++) {
            #pragma unroll
            for (int q4 = 0; q4 < 4; q4++) sAcc[j][q4] *= 0.125f;
            if (diag) {
                int key0 = kt*64 + j*8 + gc*2;
                if (key0     > qrow0) sAcc[j][0] = -1e30f;
                if (key0 + 1 > qrow0) sAcc[j][1] = -1e30f;
                if (key0     > qrow1) sAcc[j][2] = -1e30f;
                if (key0 + 1 > qrow1) sAcc[j][3] = -1e30f;
            }
        }

        float rm0 = -1e30f, rm1 = -1e30f;
        #pragma unroll
        for (int j = 0; j < 8; j++) {
            rm0 = fmaxf(rm0, fmaxf(sAcc[j][0], sAcc[j][1]));
            rm1 = fmaxf(rm1, fmaxf(sAcc[j][2], sAcc[j][3]));
        }
        rm0 = fmaxf(rm0, __shfl_xor_sync(0xffffffffu, rm0, 1));
        rm0 = fmaxf(rm0, __shfl_xor_sync(0xffffffffu, rm0, 2));
        rm1 = fmaxf(rm1, __shfl_xor_sync(0xffffffffu, rm1, 1));
        rm1 = fmaxf(rm1, __shfl_xor_sync(0xffffffffu, rm1, 2));

        float mn0 = fmaxf(m0, rm0), mn1 = fmaxf(m1, rm1);
        float al0 = __expf(m0 - mn0), al1 = __expf(m1 - mn1);

        float ps0 = 0.f, ps1 = 0.f;
        #pragma unroll
        for (int j = 0; j < 8; j++) {
            sAcc[j][0] = __expf(sAcc[j][0] - mn0);
            sAcc[j][1] = __expf(sAcc[j][1] - mn0);
            sAcc[j][2] = __expf(sAcc[j][2] - mn1);
            sAcc[j][3] = __expf(sAcc[j][3] - mn1);
            ps0 += sAcc[j][0] + sAcc[j][1];
            ps1 += sAcc[j][2] + sAcc[j][3];
        }
        ps0 += __shfl_xor_sync(0xffffffffu, ps0, 1);
        ps0 += __shfl_xor_sync(0xffffffffu, ps0, 2);
        ps1 += __shfl_xor_sync(0xffffffffu, ps1, 1);
        ps1 += __shfl_xor_sync(0xffffffffu, ps1, 2);

        l0 = l0*al0 + ps0;  l1 = l1*al1 + ps1;
        m0 = mn0;           m1 = mn1;
        #pragma unroll
        for (int j = 0; j < 8; j++) {
            oAcc[j][0] *= al0; oAcc[j][1] *= al0;
            oAcc[j][2] *= al1; oAcc[j][3] *= al1;
        }

        #pragma unroll
        for (int kk2 = 0; kk2 < 4; kk2++) {
            uint32_t ph[4], pl[4];
            pack2(sAcc[2*kk2  ][0], sAcc[2*kk2  ][1], ph[0], pl[0]);
            pack2(sAcc[2*kk2  ][2], sAcc[2*kk2  ][3], ph[1], pl[1]);
            pack2(sAcc[2*kk2+1][0], sAcc[2*kk2+1][1], ph[2], pl[2]);
            pack2(sAcc[2*kk2+1][2], sAcc[2*kk2+1][3], ph[3], pl[3]);
            #pragma unroll
            for (int g = 0; g < 4; g++) {
                uint32_t off = SWZ((uint32_t)(g*16 + lrow)*128 + (uint32_t)(kk2*16 + lkc8)*2);
                uint32_t vh4[4], vl4[4];
                LDSM4(vh4, sK + 16384 + off);
                LDSM4(vl4, sK + 24576 + off);
                MMA16816(oAcc[2*g  ], ph, vh4[0], vh4[2]);
                MMA16816(oAcc[2*g+1], ph, vh4[1], vh4[3]);
                MMA16816(oAcc[2*g  ], ph, vl4[0], vl4[2]);
                MMA16816(oAcc[2*g+1], ph, vl4[1], vl4[3]);
                MMA16816(oAcc[2*g  ], pl, vh4[0], vh4[2]);
                MMA16816(oAcc[2*g+1], pl, vh4[1], vh4[3]);
            }
        }
        __syncthreads();
    }

    float inv0 = 1.0f / l0, inv1 = 1.0f / l1;
    int mtok0 = b*SEQ + qt*64 + w*16 + gr;
    size_t tb = ((size_t)(mtok0 >> 7) * 16 + h) * 8192;
    #pragma unroll
    for (int g = 0; g < 8; g++) {
        int cc = g*8 + gc*2;
        uint32_t uh0, ul0, uh1, ul1;
        pack2(oAcc[g][0]*inv0, oAcc[g][1]*inv0, uh0, ul0);
        pack2(oAcc[g][2]*inv1, oAcc[g][3]*inv1, uh1, ul1);
        uint32_t bo0 = SWZ((uint32_t)(mtok0 & 127)*128 + (uint32_t)cc*2);
        uint32_t bo1 = SWZ((uint32_t)((mtok0 + 8) & 127)*128 + (uint32_t)cc*2);
        *(uint32_t*)((char*)(yhi + tb) + bo0) = uh0;
        *(uint32_t*)((char*)(ylo + tb) + bo0) = ul0;
        *(uint32_t*)((char*)(yhi + tb) + bo1) = uh1;
        *(uint32_t*)((char*)(ylo + tb) + bo1) = ul1;
    }
}

// ---------------------------------------------------------------------------
// launch
// ---------------------------------------------------------------------------
extern "C" void kernel_launch(void* const* d_in, const int* in_sizes, int n_in,
                              void* d_out, int out_size)
{
    const float* states     = (const float*)d_in[0];
    const int*   timesteps  = (const int*)  d_in[1];
    const float* se_w1 = (const float*)d_in[2];
    const float* se_b1 = (const float*)d_in[3];
    const float* se_w2 = (const float*)d_in[4];
    const float* se_b2 = (const float*)d_in[5];
    const float* se_w3 = (const float*)d_in[6];
    const float* se_b3 = (const float*)d_in[7];
    const float* pos_emb = (const float*)d_in[8];
    const float* gpe     = (const float*)d_in[9];
    const float* ln1_g = (const float*)d_in[10];
    const float* ln1_b = (const float*)d_in[11];
    const float* Wq = (const float*)d_in[12];
    const float* Wk = (const float*)d_in[13];
    const float* Wv = (const float*)d_in[14];
    const float* Wp = (const float*)d_in[15];
    const float* bp = (const float*)d_in[16];
    const float* ln2_g = (const float*)d_in[17];
    const float* ln2_b = (const float*)d_in[18];
    const float* W1 = (const float*)d_in[19];
    const float* b1 = (const float*)d_in[20];
    const float* W2 = (const float*)d_in[21];
    const float* b2 = (const float*)d_in[22];
    const float* lnf_g = (const float*)d_in[23];
    const float* lnf_b = (const float*)d_in[24];
    const float* head_w = (const float*)d_in[25];

    float *x;
    __nv_bfloat16 *hnh, *hnl, *yh, *yl, *mh, *ml, *wh, *wl, *qth, *qtl;
    __half *w16, *w16w2, *w16w1;
    cudaGetSymbolAddress((void**)&x,   g_x);
    cudaGetSymbolAddress((void**)&hnh, g_hn_hi);
    cudaGetSymbolAddress((void**)&hnl, g_hn_lo);
    cudaGetSymbolAddress((void**)&yh,  g_y_hi);
    cudaGetSymbolAddress((void**)&yl,  g_y_lo);
    cudaGetSymbolAddress((void**)&mh,  g_mlp_hi);
    cudaGetSymbolAddress((void**)&ml,  g_mlp_lo);
    cudaGetSymbolAddress((void**)&wh,  g_w_hi);
    cudaGetSymbolAddress((void**)&wl,  g_w_lo);
    cudaGetSymbolAddress((void**)&qth, g_qkvt_hi);
    cudaGetSymbolAddress((void**)&qtl, g_qkvt_lo);
    cudaGetSymbolAddress((void**)&w16, g_w16);
    cudaGetSymbolAddress((void**)&w16w2, g_w16w2);
    cudaGetSymbolAddress((void**)&w16w1, g_w16w1);

    cudaFuncSetAttribute(gemm_mma, cudaFuncAttributeMaxDynamicSharedMemorySize, GEMM_SMEM);
    cudaFuncSetAttribute(gemm_f16, cudaFuncAttributeMaxDynamicSharedMemorySize, GEMMF16_SMEM);
    cudaFuncSetAttribute(attn_mma, cudaFuncAttributeMaxDynamicSharedMemorySize, ATTN_SMEM);

    convert_all<<<10144, 256>>>(Wq, Wk, Wv, Wp, W1, W2, head_w,
                                wh, wl, w16, w16w2, w16w1);
    embed_kernel<<<NTOK, 256>>>(states, timesteps, se_w1, se_b1, se_w2, se_b2,
                                se_w3, se_b3, pos_emb, gpe, x);

    const size_t LW = LWq, MDD = MDDq;
    dim3 gQKV(24, 32), gDD(8, 32), gD4(32, 32), gHead(250, 32);
    dim3 gAttn(SEQ/64, NHEAD, BATCH);

    for (int l = 0; l < NLAYER; l++) {
        size_t wb = (size_t)l * LW;
        ln_hilo_kernel<<<NTOK, 256>>>(x, ln1_g + l*DMODEL, ln1_b + l*DMODEL, hnh, hnl, 0);
        gemm_mma<<<gQKV, 512, GEMM_SMEM>>>((uint4*)hnh, (uint4*)hnl,
            (uint4*)(wh + wb), (uint4*)(wl + wb),
            nullptr, nullptr, nullptr, qth, qtl, 3*DMODEL, 1024, 4);
        attn_mma<<<gAttn, 128, ATTN_SMEM>>>(qth, qtl, yh, yl);
        gemm_mma<<<gDD, 512, GEMM_SMEM>>>((uint4*)yh, (uint4*)yl,
            (uint4*)(wh + wb + 3*MDD), (uint4*)(wl + wb + 3*MDD),
            bp + l*DMODEL, x, x, nullptr, nullptr, 1024, 1024, 2);
        // LN2 -> fp16 hi/lo tiles
        ln_hilo_kernel<<<NTOK, 256>>>(x, ln2_g + l*DMODEL, ln2_b + l*DMODEL, hnh, hnl, 1);
        // MLP1: fp16 2-term x 1-term, GELU -> fp16 hi/lo tiles
        gemm_f16<<<gD4, 512, GEMMF16_SMEM>>>((uint4*)hnh, (uint4*)hnl,
            (uint4*)(w16w1 + (size_t)l*4194304ull),
            b1 + (size_t)l*4*DMODEL, nullptr, nullptr, mh, ml, 4096, 1024, 2, 3);
        // MLP2: fp16 2-term x 1-term, bias+resid
        gemm_f16<<<gDD, 512, GEMMF16_SMEM>>>((uint4*)mh, (uint4*)ml,
            (uint4*)(w16w2 + (size_t)l*4194304ull),
            b2 + l*DMODEL, x, x, nullptr, nullptr, 1024, 4096, 2, 2);
    }

    // final LN fp16 hi/lo; head GEMM fp16 1-term x 1-term
    ln_hilo_kernel<<<NTOK, 256>>>(x, lnf_g, lnf_b, hnh, hnl, 1);
    gemm_f16<<<gHead, 512, GEMMF16_SMEM>>>((uint4*)hnh, (uint4*)hnl,
        (uint4*)w16, nullptr, nullptr, (float*)d_out, nullptr, nullptr,
        32000, 1024, 1, 0);
}